// round 7
// baseline (speedup 1.0000x reference)
#include <cuda_runtime.h>
#include <cuda_bf16.h>
#include <cuda_fp16.h>
#include <math.h>
#include <stdint.h>

#define BATCH 4
#define CH    256
#define NPIX  4096
#define CPG   8
#define SCALE 0.0625f

__device__ float g_h [BATCH * CH * NPIX];
__device__ __nv_bfloat16 g_hh[(size_t)BATCH * NPIX * CH];
__device__ __nv_bfloat16 g_hl[(size_t)BATCH * NPIX * CH];
__device__ __nv_bfloat16 g_wqh[3 * CH * CH], g_wql[3 * CH * CH];
__device__ __nv_bfloat16 g_wph[CH * CH],     g_wpl[CH * CH];
__device__ __nv_bfloat16 g_qh[(size_t)BATCH * NPIX * CH];
__device__ __nv_bfloat16 g_ql[(size_t)BATCH * NPIX * CH];
__device__ __nv_bfloat16 g_kh[(size_t)BATCH * NPIX * CH];
__device__ __nv_bfloat16 g_kl[(size_t)BATCH * NPIX * CH];
__device__ __half g_v16h[(size_t)BATCH * CH * NPIX];
__device__ __half g_v16l[(size_t)BATCH * CH * NPIX];
__device__ float g_S [(size_t)BATCH * NPIX * NPIX];
__device__ __half g_p [(size_t)BATCH * NPIX * NPIX];
__device__ __nv_bfloat16 g_oh[(size_t)BATCH * NPIX * CH];
__device__ __nv_bfloat16 g_ol[(size_t)BATCH * NPIX * CH];

#define SWZ(o) ((o) ^ (((o) >> 3) & 0x70))

__device__ __forceinline__ uint32_t smem_u32(const void* p) {
    uint32_t a;
    asm("{ .reg .u64 t; cvta.to.shared.u64 t, %1; cvt.u32.u64 %0, t; }" : "=r"(a) : "l"(p));
    return a;
}
__device__ __forceinline__ void cp16(uint32_t dst, const void* src) {
    asm volatile("cp.async.cg.shared.global [%0], [%1], 16;" :: "r"(dst), "l"(src) : "memory");
}
__device__ __forceinline__ void ldm4(uint32_t* r, uint32_t addr) {
    asm volatile("ldmatrix.sync.aligned.m8n8.x4.shared.b16 {%0,%1,%2,%3}, [%4];"
                 : "=r"(r[0]), "=r"(r[1]), "=r"(r[2]), "=r"(r[3]) : "r"(addr));
}
__device__ __forceinline__ void mma16816(float* c, const uint32_t* a, const uint32_t* b) {
    asm volatile("mma.sync.aligned.m16n8k16.row.col.f32.bf16.bf16.f32 "
                 "{%0,%1,%2,%3}, {%4,%5,%6,%7}, {%8,%9}, {%0,%1,%2,%3};"
                 : "+f"(c[0]), "+f"(c[1]), "+f"(c[2]), "+f"(c[3])
                 : "r"(a[0]), "r"(a[1]), "r"(a[2]), "r"(a[3]), "r"(b[0]), "r"(b[1]));
}
__device__ __forceinline__ void mma16816h(float* c, const uint32_t* a, const uint32_t* b) {
    asm volatile("mma.sync.aligned.m16n8k16.row.col.f32.f16.f16.f32 "
                 "{%0,%1,%2,%3}, {%4,%5,%6,%7}, {%8,%9}, {%0,%1,%2,%3};"
                 : "+f"(c[0]), "+f"(c[1]), "+f"(c[2]), "+f"(c[3])
                 : "r"(a[0]), "r"(a[1]), "r"(a[2]), "r"(a[3]), "r"(b[0]), "r"(b[1]));
}
__device__ __forceinline__ void split2(float a, float b, __nv_bfloat162* h, __nv_bfloat162* l) {
    h->x = __float2bfloat16(a); h->y = __float2bfloat16(b);
    l->x = __float2bfloat16(a - __bfloat162float(h->x));
    l->y = __float2bfloat16(b - __bfloat162float(h->y));
}
__device__ __forceinline__ void split2h(float a, float b, __half2* h, __half2* l) {
    __half ha = __float2half_rn(a), hb = __float2half_rn(b);
    h->x = ha; h->y = hb;
    l->x = __float2half_rn(a - __half2float(ha));
    l->y = __float2half_rn(b - __half2float(hb));
}

// copy rows x 128B into SW128-swizzled smem tile (byte pitch); strides by blockDim.x
__device__ __forceinline__ void cp_rows(uint32_t dst, const char* src, long pitchB, int rows) {
    for (int idx = threadIdx.x; idx < rows * 8; idx += blockDim.x) {
        const int r = idx >> 3, cg = idx & 7;
        cp16(dst + SWZ(r * 128 + cg * 16), src + (long)r * pitchB + cg * 16);
    }
}

// ========== 32x64-warp core (qkv/proj, 256 threads, bf16 3-term) ==========
__device__ __forceinline__ void cp_chunk(uint32_t stb,
                                         const __nv_bfloat16* Ah, const __nv_bfloat16* Al,
                                         const __nv_bfloat16* Bh, const __nv_bfloat16* Bl,
                                         long pitch, long k0) {
    cp_rows(stb,         (const char*)(Ah + k0), pitch * 2, 128);
    cp_rows(stb + 16384, (const char*)(Al + k0), pitch * 2, 128);
    cp_rows(stb + 32768, (const char*)(Bh + k0), pitch * 2, 128);
    cp_rows(stb + 49152, (const char*)(Bl + k0), pitch * 2, 128);
}
__device__ __forceinline__ void mma_chunk(uint32_t sAh, uint32_t sAl, uint32_t sBh, uint32_t sBl,
                                          float (&acc)[2][8][4], int wm, int wn, int lane) {
    const int lr = lane & 15;
    const int lc = (lane >> 4) * 16;
    #pragma unroll
    for (int kk = 0; kk < 4; kk++) {
        const int kb = kk * 32;
        uint32_t ah[2][4], al[2][4];
        #pragma unroll
        for (int mt = 0; mt < 2; mt++) {
            const uint32_t off = SWZ((wm * 32 + mt * 16 + lr) * 128 + kb + lc);
            ldm4(ah[mt], sAh + off);
            ldm4(al[mt], sAl + off);
        }
        #pragma unroll
        for (int np = 0; np < 4; np++) {
            const uint32_t off = SWZ((wn * 64 + np * 16 + lr) * 128 + kb + lc);
            uint32_t bh[4], bl[4];
            ldm4(bh, sBh + off);
            ldm4(bl, sBl + off);
            uint32_t b0h[2] = {bh[0], bh[2]}, b1h[2] = {bh[1], bh[3]};
            uint32_t b0l[2] = {bl[0], bl[2]}, b1l[2] = {bl[1], bl[3]};
            #pragma unroll
            for (int mt = 0; mt < 2; mt++) {
                mma16816(acc[mt][np * 2],     ah[mt], b0h);
                mma16816(acc[mt][np * 2 + 1], ah[mt], b1h);
                mma16816(acc[mt][np * 2],     ah[mt], b0l);
                mma16816(acc[mt][np * 2 + 1], ah[mt], b1l);
                mma16816(acc[mt][np * 2],     al[mt], b0h);
                mma16816(acc[mt][np * 2 + 1], al[mt], b1h);
            }
        }
    }
}
__device__ __forceinline__ void hmma_pipeline(uint32_t sb,
        const __nv_bfloat16* Ah, const __nv_bfloat16* Al,
        const __nv_bfloat16* Bh, const __nv_bfloat16* Bl,
        long pitch, int nch, float (&acc)[2][8][4], int wm, int wn, int lane) {
    cp_chunk(sb, Ah, Al, Bh, Bl, pitch, 0);
    asm volatile("cp.async.commit_group;" ::: "memory");
    for (int ch = 0; ch < nch; ch++) {
        const uint32_t stb = sb + (ch & 1) * 65536;
        if (ch + 1 < nch) {
            cp_chunk(sb + ((ch + 1) & 1) * 65536, Ah, Al, Bh, Bl, pitch, (long)(ch + 1) * 64);
            asm volatile("cp.async.commit_group;" ::: "memory");
            asm volatile("cp.async.wait_group 1;" ::: "memory");
        } else {
            asm volatile("cp.async.wait_group 0;" ::: "memory");
        }
        __syncthreads();
        mma_chunk(stb, stb + 16384, stb + 32768, stb + 49152, acc, wm, wn, lane);
        __syncthreads();
    }
}

// ---------- GroupNorm ----------
__global__ void __launch_bounds__(256) gn_kernel(const float* __restrict__ x,
                                                 const float* __restrict__ w,
                                                 const float* __restrict__ bias) {
    const int b = blockIdx.x >> 5, g = blockIdx.x & 31;
    const float* xp = x   + (b * CH + g * CPG) * NPIX;
    float*       hp = g_h + (b * CH + g * CPG) * NPIX;
    const int NE = CPG * NPIX;
    float s = 0.f, ss = 0.f;
    const float4* x4 = (const float4*)xp;
    for (int i = threadIdx.x; i < NE / 4; i += 256) {
        float4 v = x4[i];
        s  += v.x + v.y + v.z + v.w;
        ss += v.x * v.x + v.y * v.y + v.z * v.z + v.w * v.w;
    }
    __shared__ float rs[32], rss[32];
    #pragma unroll
    for (int o = 16; o; o >>= 1) {
        s  += __shfl_xor_sync(~0u, s,  o);
        ss += __shfl_xor_sync(~0u, ss, o);
    }
    const int lane = threadIdx.x & 31, wid = threadIdx.x >> 5;
    if (lane == 0) { rs[wid] = s; rss[wid] = ss; }
    __syncthreads();
    if (wid == 0) {
        s  = (lane < 8) ? rs[lane]  : 0.f;
        ss = (lane < 8) ? rss[lane] : 0.f;
        #pragma unroll
        for (int o = 16; o; o >>= 1) {
            s  += __shfl_xor_sync(~0u, s,  o);
            ss += __shfl_xor_sync(~0u, ss, o);
        }
        if (lane == 0) { rs[0] = s; rss[0] = ss; }
    }
    __syncthreads();
    const float mu   = rs[0] / (float)NE;
    const float rstd = rsqrtf(rss[0] / (float)NE - mu * mu + 1e-5f);
    float4* h4 = (float4*)hp;
    for (int i = threadIdx.x; i < NE / 4; i += 256) {
        const int c = g * CPG + (i >> 10);
        const float wc = w[c] * rstd, bc = bias[c] - mu * wc;
        float4 v = x4[i];
        v.x = v.x * wc + bc; v.y = v.y * wc + bc; v.z = v.z * wc + bc; v.w = v.w * wc + bc;
        h4[i] = v;
    }
}

// ---------- h: [c][n] fp32 -> [n][c] hi/lo bf16 ----------
__global__ void __launch_bounds__(256) h_convert() {
    __shared__ float t[32][33];
    const int n0 = blockIdx.x * 32, c0 = blockIdx.y * 32, b = blockIdx.z;
    const float* src = g_h + ((size_t)b * CH + c0) * NPIX + n0;
    const int tx = threadIdx.x & 31, ty = threadIdx.x >> 5;
    #pragma unroll
    for (int j = 0; j < 4; j++)
        t[ty + 8 * j][tx] = src[(size_t)(ty + 8 * j) * NPIX + tx];
    __syncthreads();
    const size_t dbase = ((size_t)b * NPIX + n0) * CH + c0;
    #pragma unroll
    for (int j = 0; j < 4; j++) {
        float v = t[tx][ty + 8 * j];
        __nv_bfloat16 h = __float2bfloat16(v);
        g_hh[dbase + (size_t)(ty + 8 * j) * CH + tx] = h;
        g_hl[dbase + (size_t)(ty + 8 * j) * CH + tx] = __float2bfloat16(v - __bfloat162float(h));
    }
}

// ---------- weight split ----------
__global__ void __launch_bounds__(256) w_convert(const float* __restrict__ qkv_w,
                                                 const float* __restrict__ proj_w) {
    const int f4 = blockIdx.x * 256 + threadIdx.x;
    const float* src;
    __nv_bfloat16 *dh, *dl;
    size_t e;
    if (f4 < 49152) { src = qkv_w;  dh = g_wqh; dl = g_wql; e = (size_t)f4 * 4; }
    else            { src = proj_w; dh = g_wph; dl = g_wpl; e = (size_t)(f4 - 49152) * 4; }
    float4 v = *(const float4*)(src + e);
    __nv_bfloat162 h0, h1, l0, l1;
    split2(v.x, v.y, &h0, &l0);
    split2(v.z, v.w, &h1, &l1);
    *(__nv_bfloat162*)(dh + e)     = h0; *(__nv_bfloat162*)(dh + e + 2) = h1;
    *(__nv_bfloat162*)(dl + e)     = l0; *(__nv_bfloat162*)(dl + e + 2) = l1;
}

// ---------- QKV (q,k -> [n][c] bf16 hi/lo, v -> [c][n] fp16 hi/lo) ----------
__global__ void __launch_bounds__(256, 1) qkv_hmma(const float* __restrict__ qkv_b) {
    extern __shared__ char smem[];
    const uint32_t sb = smem_u32(smem);
    const int tid = threadIdx.x, lane = tid & 31, wid = tid >> 5;
    const int wm = wid & 3, wn = wid >> 2;
    const int b = blockIdx.z, n0 = blockIdx.x * 128, o0 = blockIdx.y * 128;

    const __nv_bfloat16* Ah = g_wqh + (size_t)o0 * CH;
    const __nv_bfloat16* Al = g_wql + (size_t)o0 * CH;
    const __nv_bfloat16* Bh = g_hh + ((size_t)b * NPIX + n0) * CH;
    const __nv_bfloat16* Bl = g_hl + ((size_t)b * NPIX + n0) * CH;

    float acc[2][8][4] = {};
    hmma_pipeline(sb, Ah, Al, Bh, Bl, CH, 4, acc, wm, wn, lane);

    const int r0 = wm * 32 + (lane >> 2), c0 = wn * 64 + (lane & 3) * 2;
    #pragma unroll
    for (int mt = 0; mt < 2; mt++) {
        const float b0 = qkv_b[o0 + r0 + mt * 16];
        const float b1 = qkv_b[o0 + r0 + mt * 16 + 8];
        #pragma unroll
        for (int nt = 0; nt < 8; nt++) {
            acc[mt][nt][0] += b0; acc[mt][nt][1] += b0;
            acc[mt][nt][2] += b1; acc[mt][nt][3] += b1;
        }
    }

    const int sel = blockIdx.y >> 1;   // 0=q, 1=k, 2=v
    if (sel == 2) {
        __half* vh = g_v16h + ((size_t)b * CH + (o0 - 512)) * NPIX + n0;
        __half* vl = g_v16l + ((size_t)b * CH + (o0 - 512)) * NPIX + n0;
        #pragma unroll
        for (int mt = 0; mt < 2; mt++)
            #pragma unroll
            for (int nt = 0; nt < 8; nt++) {
                const int rr = r0 + mt * 16, cc = c0 + nt * 8;
                __half2 h, l;
                split2h(acc[mt][nt][0], acc[mt][nt][1], &h, &l);
                *(__half2*)(vh + (size_t)rr * NPIX + cc) = h;
                *(__half2*)(vl + (size_t)rr * NPIX + cc) = l;
                split2h(acc[mt][nt][2], acc[mt][nt][3], &h, &l);
                *(__half2*)(vh + (size_t)(rr + 8) * NPIX + cc) = h;
                *(__half2*)(vl + (size_t)(rr + 8) * NPIX + cc) = l;
            }
    } else {
        float* st = (float*)smem;   // [c 128][n 132]
        #pragma unroll
        for (int mt = 0; mt < 2; mt++)
            #pragma unroll
            for (int nt = 0; nt < 8; nt++) {
                const int rr = r0 + mt * 16, cc = c0 + nt * 8;
                st[(cc)     * 132 + rr]     = acc[mt][nt][0];
                st[(cc + 1) * 132 + rr]     = acc[mt][nt][1];
                st[(cc)     * 132 + rr + 8] = acc[mt][nt][2];
                st[(cc + 1) * 132 + rr + 8] = acc[mt][nt][3];
            }
        __syncthreads();
        __nv_bfloat16* dh = (sel ? g_kh : g_qh) + ((size_t)b * NPIX + n0) * CH + (o0 - sel * 256);
        __nv_bfloat16* dl = (sel ? g_kl : g_ql) + ((size_t)b * NPIX + n0) * CH + (o0 - sel * 256);
        const int o4 = lane * 4, nb = tid >> 5;
        #pragma unroll
        for (int j = 0; j < 16; j++) {
            const int n = nb + 8 * j;
            float4 v = *(float4*)(st + n * 132 + o4);
            __nv_bfloat162 h0, h1, l0, l1;
            split2(v.x, v.y, &h0, &l0);
            split2(v.z, v.w, &h1, &l1);
            *(__nv_bfloat162*)(dh + (size_t)n * CH + o4)     = h0;
            *(__nv_bfloat162*)(dh + (size_t)n * CH + o4 + 2) = h1;
            *(__nv_bfloat162*)(dl + (size_t)n * CH + o4)     = l0;
            *(__nv_bfloat162*)(dl + (size_t)n * CH + o4 + 2) = l1;
        }
    }
}

// ---------- S = Q K^T (512 threads, CTA 256x128, warp 64x32, bf16 3-term) ----------
// stage: Ah 32K @0 | Al @32768 | Bh 16K @65536 | Bl @81920 = 96K; x2 = 192K
__global__ void __launch_bounds__(512, 1) s_gemm_kernel() {
    extern __shared__ char smem[];
    const uint32_t sb = smem_u32(smem);
    const int tid = threadIdx.x, lane = tid & 31, wid = tid >> 5;
    const int wm = wid & 3, wn = wid >> 2;   // 4 x 4 warps
    const int b = blockIdx.z, i0 = blockIdx.y * 256, j0 = blockIdx.x * 128;

    const char* Ah = (const char*)(g_qh + ((size_t)b * NPIX + i0) * CH);
    const char* Al = (const char*)(g_ql + ((size_t)b * NPIX + i0) * CH);
    const char* Bh = (const char*)(g_kh + ((size_t)b * NPIX + j0) * CH);
    const char* Bl = (const char*)(g_kl + ((size_t)b * NPIX + j0) * CH);
    const long pB = CH * 2;

    float acc[4][4][4] = {};
    const int lr = lane & 15, lc = (lane >> 4) * 16;

    cp_rows(sb,         Ah, pB, 256);
    cp_rows(sb + 32768, Al, pB, 256);
    cp_rows(sb + 65536, Bh, pB, 128);
    cp_rows(sb + 81920, Bl, pB, 128);
    asm volatile("cp.async.commit_group;" ::: "memory");

    for (int ch = 0; ch < 4; ch++) {
        const uint32_t stb = sb + (ch & 1) * 98304;
        if (ch + 1 < 4) {
            const uint32_t nstb = sb + ((ch + 1) & 1) * 98304;
            const long k0 = (long)(ch + 1) * 128;
            cp_rows(nstb,         Ah + k0, pB, 256);
            cp_rows(nstb + 32768, Al + k0, pB, 256);
            cp_rows(nstb + 65536, Bh + k0, pB, 128);
            cp_rows(nstb + 81920, Bl + k0, pB, 128);
            asm volatile("cp.async.commit_group;" ::: "memory");
            asm volatile("cp.async.wait_group 1;" ::: "memory");
        } else {
            asm volatile("cp.async.wait_group 0;" ::: "memory");
        }
        __syncthreads();
        #pragma unroll
        for (int kk = 0; kk < 4; kk++) {
            const int kb = kk * 32;
            uint32_t ah[4][4], al[4][4];
            #pragma unroll
            for (int mt = 0; mt < 4; mt++) {
                const uint32_t off = SWZ((wm * 64 + mt * 16 + lr) * 128 + kb + lc);
                ldm4(ah[mt], stb + off);
                ldm4(al[mt], stb + 32768 + off);
            }
            #pragma unroll
            for (int np = 0; np < 2; np++) {
                const uint32_t off = SWZ((wn * 32 + np * 16 + lr) * 128 + kb + lc);
                uint32_t bh[4], bl[4];
                ldm4(bh, stb + 65536 + off);
                ldm4(bl, stb + 81920 + off);
                uint32_t b0h[2] = {bh[0], bh[2]}, b1h[2] = {bh[1], bh[3]};
                uint32_t b0l[2] = {bl[0], bl[2]}, b1l[2] = {bl[1], bl[3]};
                #pragma unroll
                for (int mt = 0; mt < 4; mt++) {
                    mma16816(acc[mt][np * 2],     ah[mt], b0h);
                    mma16816(acc[mt][np * 2 + 1], ah[mt], b1h);
                    mma16816(acc[mt][np * 2],     ah[mt], b0l);
                    mma16816(acc[mt][np * 2 + 1], ah[mt], b1l);
                    mma16816(acc[mt][np * 2],     al[mt], b0h);
                    mma16816(acc[mt][np * 2 + 1], al[mt], b1h);
                }
            }
        }
        __syncthreads();
    }

    float* Sb = g_S + ((size_t)b * NPIX + i0) * NPIX + j0;
    const int r0 = wm * 64 + (lane >> 2), c0 = wn * 32 + (lane & 3) * 2;
    #pragma unroll
    for (int mt = 0; mt < 4; mt++)
        #pragma unroll
        for (int nt = 0; nt < 4; nt++) {
            float* p = Sb + (size_t)(r0 + mt * 16) * NPIX + c0 + nt * 8;
            *(float2*)p = make_float2(acc[mt][nt][0], acc[mt][nt][1]);
            *(float2*)(p + (size_t)8 * NPIX) = make_float2(acc[mt][nt][2], acc[mt][nt][3]);
        }
}

// ---------- softmax rows -> P fp16 ----------
__global__ void __launch_bounds__(256) softmax_kernel() {
    const size_t row = blockIdx.x;
    const float4* s4 = (const float4*)(g_S + row * NPIX);
    const int tid = threadIdx.x, lane = tid & 31, wid = tid >> 5;
    __shared__ float rmax[8], rsum[8];
    float4 v[4];
    float mx = -1e30f;
    #pragma unroll
    for (int k = 0; k < 4; k++) {
        float4 t = s4[tid + 256 * k];
        t.x *= SCALE; t.y *= SCALE; t.z *= SCALE; t.w *= SCALE;
        v[k] = t;
        mx = fmaxf(mx, fmaxf(fmaxf(t.x, t.y), fmaxf(t.z, t.w)));
    }
    #pragma unroll
    for (int o = 16; o; o >>= 1) mx = fmaxf(mx, __shfl_xor_sync(~0u, mx, o));
    if (lane == 0) rmax[wid] = mx;
    __syncthreads();
    mx = rmax[0];
    #pragma unroll
    for (int i = 1; i < 8; i++) mx = fmaxf(mx, rmax[i]);
    float sum = 0.f;
    #pragma unroll
    for (int k = 0; k < 4; k++) {
        v[k].x = __expf(v[k].x - mx); v[k].y = __expf(v[k].y - mx);
        v[k].z = __expf(v[k].z - mx); v[k].w = __expf(v[k].w - mx);
        sum += v[k].x + v[k].y + v[k].z + v[k].w;
    }
    #pragma unroll
    for (int o = 16; o; o >>= 1) sum += __shfl_xor_sync(~0u, sum, o);
    if (lane == 0) rsum[wid] = sum;
    __syncthreads();
    sum = rsum[0]+rsum[1]+rsum[2]+rsum[3]+rsum[4]+rsum[5]+rsum[6]+rsum[7];
    const float inv = 1.f / sum;
    __half* ph = g_p + row * NPIX;
    #pragma unroll
    for (int k = 0; k < 4; k++) {
        const int e0 = (tid + 256 * k) * 4;
        __half2 h0, h1;
        h0.x = __float2half_rn(v[k].x * inv); h0.y = __float2half_rn(v[k].y * inv);
        h1.x = __float2half_rn(v[k].z * inv); h1.y = __float2half_rn(v[k].w * inv);
        *(__half2*)(ph + e0)     = h0;
        *(__half2*)(ph + e0 + 2) = h1;
    }
}

// ---------- O = P V (512 threads, CTA 128x256, warp 32x64, fp16 2-term) ----------
// stage: P 16K @0 | Vh 32K @16384 | Vl 32K @49152 = 80K; x2 = 160K
__global__ void __launch_bounds__(512, 1) pv_gemm_kernel() {
    extern __shared__ char smem[];
    const uint32_t sb = smem_u32(smem);
    const int tid = threadIdx.x, lane = tid & 31, wid = tid >> 5;
    const int wm = wid & 3, wn = wid >> 2;   // 4 x 4 warps
    const int b = blockIdx.x & 3, i0 = (blockIdx.x >> 2) * 128;

    const char* Ap = (const char*)(g_p + ((size_t)b * NPIX + i0) * NPIX);
    const char* Bh = (const char*)(g_v16h + (size_t)b * CH * NPIX);
    const char* Bl = (const char*)(g_v16l + (size_t)b * CH * NPIX);
    const long pB = NPIX * 2;

    float acc[2][8][4] = {};
    const int lr = lane & 15, lc = (lane >> 4) * 16;

    cp_rows(sb,         Ap, pB, 128);
    cp_rows(sb + 16384, Bh, pB, 256);
    cp_rows(sb + 49152, Bl, pB, 256);
    asm volatile("cp.async.commit_group;" ::: "memory");

    for (int ch = 0; ch < 64; ch++) {
        const uint32_t stb = sb + (ch & 1) * 81920;
        if (ch + 1 < 64) {
            const uint32_t nstb = sb + ((ch + 1) & 1) * 81920;
            const long k0 = (long)(ch + 1) * 128;
            cp_rows(nstb,         Ap + k0, pB, 128);
            cp_rows(nstb + 16384, Bh + k0, pB, 256);
            cp_rows(nstb + 49152, Bl + k0, pB, 256);
            asm volatile("cp.async.commit_group;" ::: "memory");
            asm volatile("cp.async.wait_group 1;" ::: "memory");
        } else {
            asm volatile("cp.async.wait_group 0;" ::: "memory");
        }
        __syncthreads();
        #pragma unroll
        for (int kk = 0; kk < 4; kk++) {
            const int kb = kk * 32;
            uint32_t a[2][4];
            #pragma unroll
            for (int mt = 0; mt < 2; mt++) {
                const uint32_t off = SWZ((wm * 32 + mt * 16 + lr) * 128 + kb + lc);
                ldm4(a[mt], stb + off);
            }
            #pragma unroll
            for (int np = 0; np < 4; np++) {
                const uint32_t off = SWZ((wn * 64 + np * 16 + lr) * 128 + kb + lc);
                uint32_t bh[4], bl[4];
                ldm4(bh, stb + 16384 + off);
                ldm4(bl, stb + 49152 + off);
                uint32_t b0h[2] = {bh[0], bh[2]}, b1h[2] = {bh[1], bh[3]};
                uint32_t b0l[2] = {bl[0], bl[2]}, b1l[2] = {bl[1], bl[3]};
                #pragma unroll
                for (int mt = 0; mt < 2; mt++) {
                    mma16816h(acc[mt][np * 2],     a[mt], b0h);
                    mma16816h(acc[mt][np * 2 + 1], a[mt], b1h);
                    mma16816h(acc[mt][np * 2],     a[mt], b0l);
                    mma16816h(acc[mt][np * 2 + 1], a[mt], b1l);
                }
            }
        }
        __syncthreads();
    }

    __nv_bfloat16* oh = g_oh + ((size_t)b * NPIX + i0) * CH;
    __nv_bfloat16* ol = g_ol + ((size_t)b * NPIX + i0) * CH;
    const int r0 = wm * 32 + (lane >> 2), c0 = wn * 64 + (lane & 3) * 2;
    #pragma unroll
    for (int mt = 0; mt < 2; mt++)
        #pragma unroll
        for (int nt = 0; nt < 8; nt++) {
            const int rr = r0 + mt * 16, cc = c0 + nt * 8;
            __nv_bfloat162 h, l;
            split2(acc[mt][nt][0], acc[mt][nt][1], &h, &l);
            *(__nv_bfloat162*)(oh + (size_t)rr * CH + cc) = h;
            *(__nv_bfloat162*)(ol + (size_t)rr * CH + cc) = l;
            split2(acc[mt][nt][2], acc[mt][nt][3], &h, &l);
            *(__nv_bfloat162*)(oh + (size_t)(rr + 8) * CH + cc) = h;
            *(__nv_bfloat162*)(ol + (size_t)(rr + 8) * CH + cc) = l;
        }
}

// ---------- out = proj_w * O + proj_b + x ----------
__global__ void __launch_bounds__(256, 1) proj_hmma(const float* __restrict__ proj_b,
                                                    const float* __restrict__ x,
                                                    float* __restrict__ out) {
    extern __shared__ char smem[];
    const uint32_t sb = smem_u32(smem);
    const int tid = threadIdx.x, lane = tid & 31, wid = tid >> 5;
    const int wm = wid & 3, wn = wid >> 2;
    const int b = blockIdx.z, n0 = blockIdx.x * 128, o0 = blockIdx.y * 128;

    const __nv_bfloat16* Ah = g_wph + (size_t)o0 * CH;
    const __nv_bfloat16* Al = g_wpl + (size_t)o0 * CH;
    const __nv_bfloat16* Bh = g_oh + ((size_t)b * NPIX + n0) * CH;
    const __nv_bfloat16* Bl = g_ol + ((size_t)b * NPIX + n0) * CH;

    float acc[2][8][4] = {};
    hmma_pipeline(sb, Ah, Al, Bh, Bl, CH, 4, acc, wm, wn, lane);

    const int r0 = wm * 32 + (lane >> 2), c0 = wn * 64 + (lane & 3) * 2;
    #pragma unroll
    for (int mt = 0; mt < 2; mt++) {
        const int r  = o0 + r0 + mt * 16;
        const float b0 = proj_b[r], b1 = proj_b[r + 8];
        #pragma unroll
        for (int nt = 0; nt < 8; nt++) {
            const size_t idx0 = ((size_t)b * CH + r) * NPIX + n0 + c0 + nt * 8;
            const size_t idx1 = idx0 + (size_t)8 * NPIX;
            float2 x0 = *(const float2*)(x + idx0);
            float2 x1 = *(const float2*)(x + idx1);
            *(float2*)(out + idx0) = make_float2(acc[mt][nt][0] + b0 + x0.x,
                                                 acc[mt][nt][1] + b0 + x0.y);
            *(float2*)(out + idx1) = make_float2(acc[mt][nt][2] + b1 + x1.x,
                                                 acc[mt][nt][3] + b1 + x1.y);
        }
    }
}

// ---------- launch ----------
extern "C" void kernel_launch(void* const* d_in, const int* in_sizes, int n_in,
                              void* d_out, int out_size) {
    const float* x      = (const float*)d_in[0];
    const float* gn_w   = (const float*)d_in[1];
    const float* gn_b   = (const float*)d_in[2];
    const float* qkv_w  = (const float*)d_in[3];
    const float* qkv_b  = (const float*)d_in[4];
    const float* proj_w = (const float*)d_in[5];
    const float* proj_b = (const float*)d_in[6];
    float* out = (float*)d_out;

    cudaFuncSetAttribute(qkv_hmma,      cudaFuncAttributeMaxDynamicSharedMemorySize, 131072);
    cudaFuncSetAttribute(proj_hmma,     cudaFuncAttributeMaxDynamicSharedMemorySize, 131072);
    cudaFuncSetAttribute(s_gemm_kernel, cudaFuncAttributeMaxDynamicSharedMemorySize, 196608);
    cudaFuncSetAttribute(pv_gemm_kernel,cudaFuncAttributeMaxDynamicSharedMemorySize, 163840);

    w_convert<<<256, 256>>>(qkv_w, proj_w);
    gn_kernel<<<BATCH * 32, 256>>>(x, gn_w, gn_b);
    {
        dim3 g(NPIX / 32, CH / 32, BATCH);
        h_convert<<<g, 256>>>();
    }
    {
        dim3 g(NPIX / 128, 6, BATCH);
        qkv_hmma<<<g, 256, 131072>>>(qkv_b);
    }
    {
        dim3 g(NPIX / 128, NPIX / 256, BATCH);
        s_gemm_kernel<<<g, 512, 196608>>>();
    }
    softmax_kernel<<<BATCH * NPIX, 256>>>();
    pv_gemm_kernel<<<(NPIX / 128) * BATCH, 512, 163840>>>();
    {
        dim3 g(NPIX / 128, 2, BATCH);
        proj_hmma<<<g, 256, 131072>>>(proj_b, x, out);
    }
}

// round 8
// speedup vs baseline: 1.0164x; 1.0164x over previous
#include <cuda_runtime.h>
#include <cuda_bf16.h>
#include <cuda_fp16.h>
#include <math.h>
#include <stdint.h>

#define BATCH 4
#define CH    256
#define NPIX  4096
#define CPG   8
#define SCALE 0.0625f

__device__ float g_h [BATCH * CH * NPIX];
__device__ __nv_bfloat16 g_hh[(size_t)BATCH * NPIX * CH];
__device__ __nv_bfloat16 g_hl[(size_t)BATCH * NPIX * CH];
__device__ __nv_bfloat16 g_wqh[3 * CH * CH], g_wql[3 * CH * CH];
__device__ __nv_bfloat16 g_wph[CH * CH],     g_wpl[CH * CH];
__device__ __nv_bfloat16 g_qh[(size_t)BATCH * NPIX * CH];
__device__ __nv_bfloat16 g_ql[(size_t)BATCH * NPIX * CH];
__device__ __nv_bfloat16 g_kh[(size_t)BATCH * NPIX * CH];
__device__ __nv_bfloat16 g_kl[(size_t)BATCH * NPIX * CH];
__device__ __half g_v16h[(size_t)BATCH * CH * NPIX];
__device__ __half g_v16l[(size_t)BATCH * CH * NPIX];
__device__ float g_S [(size_t)BATCH * NPIX * NPIX];
__device__ __half g_p [(size_t)BATCH * NPIX * NPIX];
__device__ __nv_bfloat16 g_oh[(size_t)BATCH * NPIX * CH];
__device__ __nv_bfloat16 g_ol[(size_t)BATCH * NPIX * CH];

#define SWZ(o) ((o) ^ (((o) >> 3) & 0x70))

__device__ __forceinline__ uint32_t smem_u32(const void* p) {
    uint32_t a;
    asm("{ .reg .u64 t; cvta.to.shared.u64 t, %1; cvt.u32.u64 %0, t; }" : "=r"(a) : "l"(p));
    return a;
}
__device__ __forceinline__ void cp16(uint32_t dst, const void* src) {
    asm volatile("cp.async.cg.shared.global [%0], [%1], 16;" :: "r"(dst), "l"(src) : "memory");
}
__device__ __forceinline__ void ldm4(uint32_t* r, uint32_t addr) {
    asm volatile("ldmatrix.sync.aligned.m8n8.x4.shared.b16 {%0,%1,%2,%3}, [%4];"
                 : "=r"(r[0]), "=r"(r[1]), "=r"(r[2]), "=r"(r[3]) : "r"(addr));
}
__device__ __forceinline__ void mma16816(float* c, const uint32_t* a, const uint32_t* b) {
    asm volatile("mma.sync.aligned.m16n8k16.row.col.f32.bf16.bf16.f32 "
                 "{%0,%1,%2,%3}, {%4,%5,%6,%7}, {%8,%9}, {%0,%1,%2,%3};"
                 : "+f"(c[0]), "+f"(c[1]), "+f"(c[2]), "+f"(c[3])
                 : "r"(a[0]), "r"(a[1]), "r"(a[2]), "r"(a[3]), "r"(b[0]), "r"(b[1]));
}
__device__ __forceinline__ void mma16816h(float* c, const uint32_t* a, const uint32_t* b) {
    asm volatile("mma.sync.aligned.m16n8k16.row.col.f32.f16.f16.f32 "
                 "{%0,%1,%2,%3}, {%4,%5,%6,%7}, {%8,%9}, {%0,%1,%2,%3};"
                 : "+f"(c[0]), "+f"(c[1]), "+f"(c[2]), "+f"(c[3])
                 : "r"(a[0]), "r"(a[1]), "r"(a[2]), "r"(a[3]), "r"(b[0]), "r"(b[1]));
}
__device__ __forceinline__ void split2(float a, float b, __nv_bfloat162* h, __nv_bfloat162* l) {
    h->x = __float2bfloat16(a); h->y = __float2bfloat16(b);
    l->x = __float2bfloat16(a - __bfloat162float(h->x));
    l->y = __float2bfloat16(b - __bfloat162float(h->y));
}
__device__ __forceinline__ void split2h(float a, float b, __half2* h, __half2* l) {
    __half ha = __float2half_rn(a), hb = __float2half_rn(b);
    h->x = ha; h->y = hb;
    l->x = __float2half_rn(a - __half2float(ha));
    l->y = __float2half_rn(b - __half2float(hb));
}

// copy rows x 128B into SW128-swizzled smem tile (byte pitch)
__device__ __forceinline__ void cp_rows(uint32_t dst, const char* src, long pitchB, int rows) {
    for (int idx = threadIdx.x; idx < rows * 8; idx += blockDim.x) {
        const int r = idx >> 3, cg = idx & 7;
        cp16(dst + SWZ(r * 128 + cg * 16), src + (long)r * pitchB + cg * 16);
    }
}

// ========== 32x64-warp core (qkv/proj, 256 threads, bf16 3-term) ==========
__device__ __forceinline__ void cp_chunk(uint32_t stb,
                                         const __nv_bfloat16* Ah, const __nv_bfloat16* Al,
                                         const __nv_bfloat16* Bh, const __nv_bfloat16* Bl,
                                         long pitch, long k0) {
    cp_rows(stb,         (const char*)(Ah + k0), pitch * 2, 128);
    cp_rows(stb + 16384, (const char*)(Al + k0), pitch * 2, 128);
    cp_rows(stb + 32768, (const char*)(Bh + k0), pitch * 2, 128);
    cp_rows(stb + 49152, (const char*)(Bl + k0), pitch * 2, 128);
}
__device__ __forceinline__ void mma_chunk(uint32_t sAh, uint32_t sAl, uint32_t sBh, uint32_t sBl,
                                          float (&acc)[2][8][4], int wm, int wn, int lane) {
    const int lr = lane & 15;
    const int lc = (lane >> 4) * 16;
    #pragma unroll
    for (int kk = 0; kk < 4; kk++) {
        const int kb = kk * 32;
        uint32_t ah[2][4], al[2][4];
        #pragma unroll
        for (int mt = 0; mt < 2; mt++) {
            const uint32_t off = SWZ((wm * 32 + mt * 16 + lr) * 128 + kb + lc);
            ldm4(ah[mt], sAh + off);
            ldm4(al[mt], sAl + off);
        }
        #pragma unroll
        for (int np = 0; np < 4; np++) {
            const uint32_t off = SWZ((wn * 64 + np * 16 + lr) * 128 + kb + lc);
            uint32_t bh[4], bl[4];
            ldm4(bh, sBh + off);
            ldm4(bl, sBl + off);
            uint32_t b0h[2] = {bh[0], bh[2]}, b1h[2] = {bh[1], bh[3]};
            uint32_t b0l[2] = {bl[0], bl[2]}, b1l[2] = {bl[1], bl[3]};
            // term-major: max accumulator reuse distance
            #pragma unroll
            for (int mt = 0; mt < 2; mt++) {
                mma16816(acc[mt][np * 2],     ah[mt], b0h);
                mma16816(acc[mt][np * 2 + 1], ah[mt], b1h);
            }
            #pragma unroll
            for (int mt = 0; mt < 2; mt++) {
                mma16816(acc[mt][np * 2],     ah[mt], b0l);
                mma16816(acc[mt][np * 2 + 1], ah[mt], b1l);
            }
            #pragma unroll
            for (int mt = 0; mt < 2; mt++) {
                mma16816(acc[mt][np * 2],     al[mt], b0h);
                mma16816(acc[mt][np * 2 + 1], al[mt], b1h);
            }
        }
    }
}
__device__ __forceinline__ void hmma_pipeline(uint32_t sb,
        const __nv_bfloat16* Ah, const __nv_bfloat16* Al,
        const __nv_bfloat16* Bh, const __nv_bfloat16* Bl,
        long pitch, int nch, float (&acc)[2][8][4], int wm, int wn, int lane) {
    cp_chunk(sb, Ah, Al, Bh, Bl, pitch, 0);
    asm volatile("cp.async.commit_group;" ::: "memory");
    for (int ch = 0; ch < nch; ch++) {
        const uint32_t stb = sb + (ch & 1) * 65536;
        if (ch + 1 < nch) {
            cp_chunk(sb + ((ch + 1) & 1) * 65536, Ah, Al, Bh, Bl, pitch, (long)(ch + 1) * 64);
            asm volatile("cp.async.commit_group;" ::: "memory");
            asm volatile("cp.async.wait_group 1;" ::: "memory");
        } else {
            asm volatile("cp.async.wait_group 0;" ::: "memory");
        }
        __syncthreads();
        mma_chunk(stb, stb + 16384, stb + 32768, stb + 49152, acc, wm, wn, lane);
        __syncthreads();
    }
}

// ---------- GroupNorm ----------
__global__ void __launch_bounds__(256) gn_kernel(const float* __restrict__ x,
                                                 const float* __restrict__ w,
                                                 const float* __restrict__ bias) {
    const int b = blockIdx.x >> 5, g = blockIdx.x & 31;
    const float* xp = x   + (b * CH + g * CPG) * NPIX;
    float*       hp = g_h + (b * CH + g * CPG) * NPIX;
    const int NE = CPG * NPIX;
    float s = 0.f, ss = 0.f;
    const float4* x4 = (const float4*)xp;
    for (int i = threadIdx.x; i < NE / 4; i += 256) {
        float4 v = x4[i];
        s  += v.x + v.y + v.z + v.w;
        ss += v.x * v.x + v.y * v.y + v.z * v.z + v.w * v.w;
    }
    __shared__ float rs[32], rss[32];
    #pragma unroll
    for (int o = 16; o; o >>= 1) {
        s  += __shfl_xor_sync(~0u, s,  o);
        ss += __shfl_xor_sync(~0u, ss, o);
    }
    const int lane = threadIdx.x & 31, wid = threadIdx.x >> 5;
    if (lane == 0) { rs[wid] = s; rss[wid] = ss; }
    __syncthreads();
    if (wid == 0) {
        s  = (lane < 8) ? rs[lane]  : 0.f;
        ss = (lane < 8) ? rss[lane] : 0.f;
        #pragma unroll
        for (int o = 16; o; o >>= 1) {
            s  += __shfl_xor_sync(~0u, s,  o);
            ss += __shfl_xor_sync(~0u, ss, o);
        }
        if (lane == 0) { rs[0] = s; rss[0] = ss; }
    }
    __syncthreads();
    const float mu   = rs[0] / (float)NE;
    const float rstd = rsqrtf(rss[0] / (float)NE - mu * mu + 1e-5f);
    float4* h4 = (float4*)hp;
    for (int i = threadIdx.x; i < NE / 4; i += 256) {
        const int c = g * CPG + (i >> 10);
        const float wc = w[c] * rstd, bc = bias[c] - mu * wc;
        float4 v = x4[i];
        v.x = v.x * wc + bc; v.y = v.y * wc + bc; v.z = v.z * wc + bc; v.w = v.w * wc + bc;
        h4[i] = v;
    }
}

// ---------- h: [c][n] fp32 -> [n][c] hi/lo bf16 ----------
__global__ void __launch_bounds__(256) h_convert() {
    __shared__ float t[32][33];
    const int n0 = blockIdx.x * 32, c0 = blockIdx.y * 32, b = blockIdx.z;
    const float* src = g_h + ((size_t)b * CH + c0) * NPIX + n0;
    const int tx = threadIdx.x & 31, ty = threadIdx.x >> 5;
    #pragma unroll
    for (int j = 0; j < 4; j++)
        t[ty + 8 * j][tx] = src[(size_t)(ty + 8 * j) * NPIX + tx];
    __syncthreads();
    const size_t dbase = ((size_t)b * NPIX + n0) * CH + c0;
    #pragma unroll
    for (int j = 0; j < 4; j++) {
        float v = t[tx][ty + 8 * j];
        __nv_bfloat16 h = __float2bfloat16(v);
        g_hh[dbase + (size_t)(ty + 8 * j) * CH + tx] = h;
        g_hl[dbase + (size_t)(ty + 8 * j) * CH + tx] = __float2bfloat16(v - __bfloat162float(h));
    }
}

// ---------- weight split ----------
__global__ void __launch_bounds__(256) w_convert(const float* __restrict__ qkv_w,
                                                 const float* __restrict__ proj_w) {
    const int f4 = blockIdx.x * 256 + threadIdx.x;
    const float* src;
    __nv_bfloat16 *dh, *dl;
    size_t e;
    if (f4 < 49152) { src = qkv_w;  dh = g_wqh; dl = g_wql; e = (size_t)f4 * 4; }
    else            { src = proj_w; dh = g_wph; dl = g_wpl; e = (size_t)(f4 - 49152) * 4; }
    float4 v = *(const float4*)(src + e);
    __nv_bfloat162 h0, h1, l0, l1;
    split2(v.x, v.y, &h0, &l0);
    split2(v.z, v.w, &h1, &l1);
    *(__nv_bfloat162*)(dh + e)     = h0; *(__nv_bfloat162*)(dh + e + 2) = h1;
    *(__nv_bfloat162*)(dl + e)     = l0; *(__nv_bfloat162*)(dl + e + 2) = l1;
}

// ---------- QKV (q,k -> [n][c] bf16 hi/lo, v -> [c][n] fp16 hi/lo) ----------
__global__ void __launch_bounds__(256, 1) qkv_hmma(const float* __restrict__ qkv_b) {
    extern __shared__ char smem[];
    const uint32_t sb = smem_u32(smem);
    const int tid = threadIdx.x, lane = tid & 31, wid = tid >> 5;
    const int wm = wid & 3, wn = wid >> 2;
    const int b = blockIdx.z, n0 = blockIdx.x * 128, o0 = blockIdx.y * 128;

    const __nv_bfloat16* Ah = g_wqh + (size_t)o0 * CH;
    const __nv_bfloat16* Al = g_wql + (size_t)o0 * CH;
    const __nv_bfloat16* Bh = g_hh + ((size_t)b * NPIX + n0) * CH;
    const __nv_bfloat16* Bl = g_hl + ((size_t)b * NPIX + n0) * CH;

    float acc[2][8][4] = {};
    hmma_pipeline(sb, Ah, Al, Bh, Bl, CH, 4, acc, wm, wn, lane);

    const int r0 = wm * 32 + (lane >> 2), c0 = wn * 64 + (lane & 3) * 2;
    #pragma unroll
    for (int mt = 0; mt < 2; mt++) {
        const float b0 = qkv_b[o0 + r0 + mt * 16];
        const float b1 = qkv_b[o0 + r0 + mt * 16 + 8];
        #pragma unroll
        for (int nt = 0; nt < 8; nt++) {
            acc[mt][nt][0] += b0; acc[mt][nt][1] += b0;
            acc[mt][nt][2] += b1; acc[mt][nt][3] += b1;
        }
    }

    const int sel = blockIdx.y >> 1;   // 0=q, 1=k, 2=v
    if (sel == 2) {
        __half* vh = g_v16h + ((size_t)b * CH + (o0 - 512)) * NPIX + n0;
        __half* vl = g_v16l + ((size_t)b * CH + (o0 - 512)) * NPIX + n0;
        #pragma unroll
        for (int mt = 0; mt < 2; mt++)
            #pragma unroll
            for (int nt = 0; nt < 8; nt++) {
                const int rr = r0 + mt * 16, cc = c0 + nt * 8;
                __half2 h, l;
                split2h(acc[mt][nt][0], acc[mt][nt][1], &h, &l);
                *(__half2*)(vh + (size_t)rr * NPIX + cc) = h;
                *(__half2*)(vl + (size_t)rr * NPIX + cc) = l;
                split2h(acc[mt][nt][2], acc[mt][nt][3], &h, &l);
                *(__half2*)(vh + (size_t)(rr + 8) * NPIX + cc) = h;
                *(__half2*)(vl + (size_t)(rr + 8) * NPIX + cc) = l;
            }
    } else {
        float* st = (float*)smem;   // [c 128][n 132]
        #pragma unroll
        for (int mt = 0; mt < 2; mt++)
            #pragma unroll
            for (int nt = 0; nt < 8; nt++) {
                const int rr = r0 + mt * 16, cc = c0 + nt * 8;
                st[(cc)     * 132 + rr]     = acc[mt][nt][0];
                st[(cc + 1) * 132 + rr]     = acc[mt][nt][1];
                st[(cc)     * 132 + rr + 8] = acc[mt][nt][2];
                st[(cc + 1) * 132 + rr + 8] = acc[mt][nt][3];
            }
        __syncthreads();
        __nv_bfloat16* dh = (sel ? g_kh : g_qh) + ((size_t)b * NPIX + n0) * CH + (o0 - sel * 256);
        __nv_bfloat16* dl = (sel ? g_kl : g_ql) + ((size_t)b * NPIX + n0) * CH + (o0 - sel * 256);
        const int o4 = lane * 4, nb = tid >> 5;
        #pragma unroll
        for (int j = 0; j < 16; j++) {
            const int n = nb + 8 * j;
            float4 v = *(float4*)(st + n * 132 + o4);
            __nv_bfloat162 h0, h1, l0, l1;
            split2(v.x, v.y, &h0, &l0);
            split2(v.z, v.w, &h1, &l1);
            *(__nv_bfloat162*)(dh + (size_t)n * CH + o4)     = h0;
            *(__nv_bfloat162*)(dh + (size_t)n * CH + o4 + 2) = h1;
            *(__nv_bfloat162*)(dl + (size_t)n * CH + o4)     = l0;
            *(__nv_bfloat162*)(dl + (size_t)n * CH + o4 + 2) = l1;
        }
    }
}

// ---------- S = Q K^T (256 threads, CTA 256x128, warp 64x64, bf16 3-term) ----------
// stage: Ah 32K @0 | Al @32768 | Bh 16K @65536 | Bl @81920 = 96K; x2 = 192K
__global__ void __launch_bounds__(256, 1) s_gemm_kernel() {
    extern __shared__ char smem[];
    const uint32_t sb = smem_u32(smem);
    const int tid = threadIdx.x, lane = tid & 31, wid = tid >> 5;
    const int wm = wid & 3, wn = wid >> 2;   // 4 x 2 warps
    const int b = blockIdx.z, i0 = blockIdx.y * 256, j0 = blockIdx.x * 128;

    const char* Ah = (const char*)(g_qh + ((size_t)b * NPIX + i0) * CH);
    const char* Al = (const char*)(g_ql + ((size_t)b * NPIX + i0) * CH);
    const char* Bh = (const char*)(g_kh + ((size_t)b * NPIX + j0) * CH);
    const char* Bl = (const char*)(g_kl + ((size_t)b * NPIX + j0) * CH);
    const long pB = CH * 2;

    float acc[4][8][4] = {};
    const int lr = lane & 15, lc = (lane >> 4) * 16;

    cp_rows(sb,         Ah, pB, 256);
    cp_rows(sb + 32768, Al, pB, 256);
    cp_rows(sb + 65536, Bh, pB, 128);
    cp_rows(sb + 81920, Bl, pB, 128);
    asm volatile("cp.async.commit_group;" ::: "memory");

    for (int ch = 0; ch < 4; ch++) {
        const uint32_t stb = sb + (ch & 1) * 98304;
        if (ch + 1 < 4) {
            const uint32_t nstb = sb + ((ch + 1) & 1) * 98304;
            const long k0 = (long)(ch + 1) * 128;
            cp_rows(nstb,         Ah + k0, pB, 256);
            cp_rows(nstb + 32768, Al + k0, pB, 256);
            cp_rows(nstb + 65536, Bh + k0, pB, 128);
            cp_rows(nstb + 81920, Bl + k0, pB, 128);
            asm volatile("cp.async.commit_group;" ::: "memory");
            asm volatile("cp.async.wait_group 1;" ::: "memory");
        } else {
            asm volatile("cp.async.wait_group 0;" ::: "memory");
        }
        __syncthreads();
        #pragma unroll
        for (int kk = 0; kk < 4; kk++) {
            const int kb = kk * 32;
            uint32_t ah[4][4], al[4][4];
            #pragma unroll
            for (int mt = 0; mt < 4; mt++) {
                const uint32_t off = SWZ((wm * 64 + mt * 16 + lr) * 128 + kb + lc);
                ldm4(ah[mt], stb + off);
                ldm4(al[mt], stb + 32768 + off);
            }
            #pragma unroll
            for (int np = 0; np < 4; np++) {
                const uint32_t off = SWZ((wn * 64 + np * 16 + lr) * 128 + kb + lc);
                uint32_t bh[4], bl[4];
                ldm4(bh, stb + 65536 + off);
                ldm4(bl, stb + 81920 + off);
                uint32_t b0h[2] = {bh[0], bh[2]}, b1h[2] = {bh[1], bh[3]};
                uint32_t b0l[2] = {bl[0], bl[2]}, b1l[2] = {bl[1], bl[3]};
                // term-major: reuse distance 8 mmas
                #pragma unroll
                for (int mt = 0; mt < 4; mt++) {
                    mma16816(acc[mt][np * 2],     ah[mt], b0h);
                    mma16816(acc[mt][np * 2 + 1], ah[mt], b1h);
                }
                #pragma unroll
                for (int mt = 0; mt < 4; mt++) {
                    mma16816(acc[mt][np * 2],     ah[mt], b0l);
                    mma16816(acc[mt][np * 2 + 1], ah[mt], b1l);
                }
                #pragma unroll
                for (int mt = 0; mt < 4; mt++) {
                    mma16816(acc[mt][np * 2],     al[mt], b0h);
                    mma16816(acc[mt][np * 2 + 1], al[mt], b1h);
                }
            }
        }
        __syncthreads();
    }

    float* Sb = g_S + ((size_t)b * NPIX + i0) * NPIX + j0;
    const int r0 = wm * 64 + (lane >> 2), c0 = wn * 64 + (lane & 3) * 2;
    #pragma unroll
    for (int mt = 0; mt < 4; mt++)
        #pragma unroll
        for (int nt = 0; nt < 8; nt++) {
            float* p = Sb + (size_t)(r0 + mt * 16) * NPIX + c0 + nt * 8;
            *(float2*)p = make_float2(acc[mt][nt][0], acc[mt][nt][1]);
            *(float2*)(p + (size_t)8 * NPIX) = make_float2(acc[mt][nt][2], acc[mt][nt][3]);
        }
}

// ---------- softmax rows -> P fp16 ----------
__global__ void __launch_bounds__(256) softmax_kernel() {
    const size_t row = blockIdx.x;
    const float4* s4 = (const float4*)(g_S + row * NPIX);
    const int tid = threadIdx.x, lane = tid & 31, wid = tid >> 5;
    __shared__ float rmax[8], rsum[8];
    float4 v[4];
    float mx = -1e30f;
    #pragma unroll
    for (int k = 0; k < 4; k++) {
        float4 t = s4[tid + 256 * k];
        t.x *= SCALE; t.y *= SCALE; t.z *= SCALE; t.w *= SCALE;
        v[k] = t;
        mx = fmaxf(mx, fmaxf(fmaxf(t.x, t.y), fmaxf(t.z, t.w)));
    }
    #pragma unroll
    for (int o = 16; o; o >>= 1) mx = fmaxf(mx, __shfl_xor_sync(~0u, mx, o));
    if (lane == 0) rmax[wid] = mx;
    __syncthreads();
    mx = rmax[0];
    #pragma unroll
    for (int i = 1; i < 8; i++) mx = fmaxf(mx, rmax[i]);
    float sum = 0.f;
    #pragma unroll
    for (int k = 0; k < 4; k++) {
        v[k].x = __expf(v[k].x - mx); v[k].y = __expf(v[k].y - mx);
        v[k].z = __expf(v[k].z - mx); v[k].w = __expf(v[k].w - mx);
        sum += v[k].x + v[k].y + v[k].z + v[k].w;
    }
    #pragma unroll
    for (int o = 16; o; o >>= 1) sum += __shfl_xor_sync(~0u, sum, o);
    if (lane == 0) rsum[wid] = sum;
    __syncthreads();
    sum = rsum[0]+rsum[1]+rsum[2]+rsum[3]+rsum[4]+rsum[5]+rsum[6]+rsum[7];
    const float inv = 1.f / sum;
    __half* ph = g_p + row * NPIX;
    #pragma unroll
    for (int k = 0; k < 4; k++) {
        const int e0 = (tid + 256 * k) * 4;
        __half2 h0, h1;
        h0.x = __float2half_rn(v[k].x * inv); h0.y = __float2half_rn(v[k].y * inv);
        h1.x = __float2half_rn(v[k].z * inv); h1.y = __float2half_rn(v[k].w * inv);
        *(__half2*)(ph + e0)     = h0;
        *(__half2*)(ph + e0 + 2) = h1;
    }
}

// ---------- O = P V (256 threads, CTA 128x256, warp 64x64, fp16 2-term) ----------
// stage: P 16K @0 | Vh 32K @16384 | Vl 32K @49152 = 80K; x2 = 160K
__global__ void __launch_bounds__(256, 1) pv_gemm_kernel() {
    extern __shared__ char smem[];
    const uint32_t sb = smem_u32(smem);
    const int tid = threadIdx.x, lane = tid & 31, wid = tid >> 5;
    const int wm = wid & 1, wn = wid >> 1;   // 2 x 4 warps
    const int b = blockIdx.x & 3, i0 = (blockIdx.x >> 2) * 128;

    const char* Ap = (const char*)(g_p + ((size_t)b * NPIX + i0) * NPIX);
    const char* Bh = (const char*)(g_v16h + (size_t)b * CH * NPIX);
    const char* Bl = (const char*)(g_v16l + (size_t)b * CH * NPIX);
    const long pB = NPIX * 2;

    float acc[4][8][4] = {};
    const int lr = lane & 15, lc = (lane >> 4) * 16;

    cp_rows(sb,         Ap, pB, 128);
    cp_rows(sb + 16384, Bh, pB, 256);
    cp_rows(sb + 49152, Bl, pB, 256);
    asm volatile("cp.async.commit_group;" ::: "memory");

    for (int ch = 0; ch < 64; ch++) {
        const uint32_t stb = sb + (ch & 1) * 81920;
        if (ch + 1 < 64) {
            const uint32_t nstb = sb + ((ch + 1) & 1) * 81920;
            const long k0 = (long)(ch + 1) * 128;
            cp_rows(nstb,         Ap + k0, pB, 128);
            cp_rows(nstb + 16384, Bh + k0, pB, 256);
            cp_rows(nstb + 49152, Bl + k0, pB, 256);
            asm volatile("cp.async.commit_group;" ::: "memory");
            asm volatile("cp.async.wait_group 1;" ::: "memory");
        } else {
            asm volatile("cp.async.wait_group 0;" ::: "memory");
        }
        __syncthreads();
        #pragma unroll
        for (int kk = 0; kk < 4; kk++) {
            const int kb = kk * 32;
            uint32_t a[4][4];
            #pragma unroll
            for (int mt = 0; mt < 4; mt++) {
                const uint32_t off = SWZ((wm * 64 + mt * 16 + lr) * 128 + kb + lc);
                ldm4(a[mt], stb + off);
            }
            #pragma unroll
            for (int np = 0; np < 4; np++) {
                const uint32_t off = SWZ((wn * 64 + np * 16 + lr) * 128 + kb + lc);
                uint32_t bh[4], bl[4];
                ldm4(bh, stb + 16384 + off);
                ldm4(bl, stb + 49152 + off);
                uint32_t b0h[2] = {bh[0], bh[2]}, b1h[2] = {bh[1], bh[3]};
                uint32_t b0l[2] = {bl[0], bl[2]}, b1l[2] = {bl[1], bl[3]};
                // term-major: reuse distance 8 mmas
                #pragma unroll
                for (int mt = 0; mt < 4; mt++) {
                    mma16816h(acc[mt][np * 2],     a[mt], b0h);
                    mma16816h(acc[mt][np * 2 + 1], a[mt], b1h);
                }
                #pragma unroll
                for (int mt = 0; mt < 4; mt++) {
                    mma16816h(acc[mt][np * 2],     a[mt], b0l);
                    mma16816h(acc[mt][np * 2 + 1], a[mt], b1l);
                }
            }
        }
        __syncthreads();
    }

    __nv_bfloat16* oh = g_oh + ((size_t)b * NPIX + i0) * CH;
    __nv_bfloat16* ol = g_ol + ((size_t)b * NPIX + i0) * CH;
    const int r0 = wm * 64 + (lane >> 2), c0 = wn * 64 + (lane & 3) * 2;
    #pragma unroll
    for (int mt = 0; mt < 4; mt++)
        #pragma unroll
        for (int nt = 0; nt < 8; nt++) {
            const int rr = r0 + mt * 16, cc = c0 + nt * 8;
            __nv_bfloat162 h, l;
            split2(acc[mt][nt][0], acc[mt][nt][1], &h, &l);
            *(__nv_bfloat162*)(oh + (size_t)rr * CH + cc) = h;
            *(__nv_bfloat162*)(ol + (size_t)rr * CH + cc) = l;
            split2(acc[mt][nt][2], acc[mt][nt][3], &h, &l);
            *(__nv_bfloat162*)(oh + (size_t)(rr + 8) * CH + cc) = h;
            *(__nv_bfloat162*)(ol + (size_t)(rr + 8) * CH + cc) = l;
        }
}

// ---------- out = proj_w * O + proj_b + x ----------
__global__ void __launch_bounds__(256, 1) proj_hmma(const float* __restrict__ proj_b,
                                                    const float* __restrict__ x,
                                                    float* __restrict__ out) {
    extern __shared__ char smem[];
    const uint32_t sb = smem_u32(smem);
    const int tid = threadIdx.x, lane = tid & 31, wid = tid >> 5;
    const int wm = wid & 3, wn = wid >> 2;
    const int b = blockIdx.z, n0 = blockIdx.x * 128, o0 = blockIdx.y * 128;

    const __nv_bfloat16* Ah = g_wph + (size_t)o0 * CH;
    const __nv_bfloat16* Al = g_wpl + (size_t)o0 * CH;
    const __nv_bfloat16* Bh = g_oh + ((size_t)b * NPIX + n0) * CH;
    const __nv_bfloat16* Bl = g_ol + ((size_t)b * NPIX + n0) * CH;

    float acc[2][8][4] = {};
    hmma_pipeline(sb, Ah, Al, Bh, Bl, CH, 4, acc, wm, wn, lane);

    const int r0 = wm * 32 + (lane >> 2), c0 = wn * 64 + (lane & 3) * 2;
    #pragma unroll
    for (int mt = 0; mt < 2; mt++) {
        const int r  = o0 + r0 + mt * 16;
        const float b0 = proj_b[r], b1 = proj_b[r + 8];
        #pragma unroll
        for (int nt = 0; nt < 8; nt++) {
            const size_t idx0 = ((size_t)b * CH + r) * NPIX + n0 + c0 + nt * 8;
            const size_t idx1 = idx0 + (size_t)8 * NPIX;
            float2 x0 = *(const float2*)(x + idx0);
            float2 x1 = *(const float2*)(x + idx1);
            *(float2*)(out + idx0) = make_float2(acc[mt][nt][0] + b0 + x0.x,
                                                 acc[mt][nt][1] + b0 + x0.y);
            *(float2*)(out + idx1) = make_float2(acc[mt][nt][2] + b1 + x1.x,
                                                 acc[mt][nt][3] + b1 + x1.y);
        }
    }
}

// ---------- launch ----------
extern "C" void kernel_launch(void* const* d_in, const int* in_sizes, int n_in,
                              void* d_out, int out_size) {
    const float* x      = (const float*)d_in[0];
    const float* gn_w   = (const float*)d_in[1];
    const float* gn_b   = (const float*)d_in[2];
    const float* qkv_w  = (const float*)d_in[3];
    const float* qkv_b  = (const float*)d_in[4];
    const float* proj_w = (const float*)d_in[5];
    const float* proj_b = (const float*)d_in[6];
    float* out = (float*)d_out;

    cudaFuncSetAttribute(qkv_hmma,      cudaFuncAttributeMaxDynamicSharedMemorySize, 131072);
    cudaFuncSetAttribute(proj_hmma,     cudaFuncAttributeMaxDynamicSharedMemorySize, 131072);
    cudaFuncSetAttribute(s_gemm_kernel, cudaFuncAttributeMaxDynamicSharedMemorySize, 196608);
    cudaFuncSetAttribute(pv_gemm_kernel,cudaFuncAttributeMaxDynamicSharedMemorySize, 163840);

    w_convert<<<256, 256>>>(qkv_w, proj_w);
    gn_kernel<<<BATCH * 32, 256>>>(x, gn_w, gn_b);
    {
        dim3 g(NPIX / 32, CH / 32, BATCH);
        h_convert<<<g, 256>>>();
    }
    {
        dim3 g(NPIX / 128, 6, BATCH);
        qkv_hmma<<<g, 256, 131072>>>(qkv_b);
    }
    {
        dim3 g(NPIX / 128, NPIX / 256, BATCH);
        s_gemm_kernel<<<g, 256, 196608>>>();
    }
    softmax_kernel<<<BATCH * NPIX, 256>>>();
    pv_gemm_kernel<<<(NPIX / 128) * BATCH, 256, 163840>>>();
    {
        dim3 g(NPIX / 128, 2, BATCH);
        proj_hmma<<<g, 256, 131072>>>(proj_b, x, out);
    }
}

// round 9
// speedup vs baseline: 1.1621x; 1.1434x over previous
#include <cuda_runtime.h>
#include <cuda_bf16.h>
#include <cuda_fp16.h>
#include <math.h>
#include <stdint.h>

#define BATCH 4
#define CH    256
#define NPIX  4096
#define CPG   8
#define SCALE 0.0625f

__device__ float g_h [BATCH * CH * NPIX];
__device__ __nv_bfloat16 g_hh[(size_t)BATCH * NPIX * CH];
__device__ __nv_bfloat16 g_hl[(size_t)BATCH * NPIX * CH];
__device__ __nv_bfloat16 g_wqh[3 * CH * CH], g_wql[3 * CH * CH];
__device__ __nv_bfloat16 g_wph[CH * CH],     g_wpl[CH * CH];
__device__ __nv_bfloat16 g_qh[(size_t)BATCH * NPIX * CH];
__device__ __nv_bfloat16 g_ql[(size_t)BATCH * NPIX * CH];
__device__ __nv_bfloat16 g_kh[(size_t)BATCH * NPIX * CH];
__device__ __nv_bfloat16 g_kl[(size_t)BATCH * NPIX * CH];
__device__ __half g_v16h[(size_t)BATCH * CH * NPIX];
__device__ float g_S [(size_t)BATCH * NPIX * NPIX];
__device__ __half g_p [(size_t)BATCH * NPIX * NPIX];
__device__ __nv_bfloat16 g_oh[(size_t)BATCH * NPIX * CH];
__device__ __nv_bfloat16 g_ol[(size_t)BATCH * NPIX * CH];

#define SWZ(o) ((o) ^ (((o) >> 3) & 0x70))

__device__ __forceinline__ uint32_t smem_u32(const void* p) {
    uint32_t a;
    asm("{ .reg .u64 t; cvta.to.shared.u64 t, %1; cvt.u32.u64 %0, t; }" : "=r"(a) : "l"(p));
    return a;
}
__device__ __forceinline__ void cp16(uint32_t dst, const void* src) {
    asm volatile("cp.async.cg.shared.global [%0], [%1], 16;" :: "r"(dst), "l"(src) : "memory");
}
__device__ __forceinline__ void ldm4(uint32_t* r, uint32_t addr) {
    asm volatile("ldmatrix.sync.aligned.m8n8.x4.shared.b16 {%0,%1,%2,%3}, [%4];"
                 : "=r"(r[0]), "=r"(r[1]), "=r"(r[2]), "=r"(r[3]) : "r"(addr));
}
__device__ __forceinline__ void mma16816(float* c, const uint32_t* a, const uint32_t* b) {
    asm volatile("mma.sync.aligned.m16n8k16.row.col.f32.bf16.bf16.f32 "
                 "{%0,%1,%2,%3}, {%4,%5,%6,%7}, {%8,%9}, {%0,%1,%2,%3};"
                 : "+f"(c[0]), "+f"(c[1]), "+f"(c[2]), "+f"(c[3])
                 : "r"(a[0]), "r"(a[1]), "r"(a[2]), "r"(a[3]), "r"(b[0]), "r"(b[1]));
}
__device__ __forceinline__ void mma16816h(float* c, const uint32_t* a, const uint32_t* b) {
    asm volatile("mma.sync.aligned.m16n8k16.row.col.f32.f16.f16.f32 "
                 "{%0,%1,%2,%3}, {%4,%5,%6,%7}, {%8,%9}, {%0,%1,%2,%3};"
                 : "+f"(c[0]), "+f"(c[1]), "+f"(c[2]), "+f"(c[3])
                 : "r"(a[0]), "r"(a[1]), "r"(a[2]), "r"(a[3]), "r"(b[0]), "r"(b[1]));
}
__device__ __forceinline__ void split2(float a, float b, __nv_bfloat162* h, __nv_bfloat162* l) {
    h->x = __float2bfloat16(a); h->y = __float2bfloat16(b);
    l->x = __float2bfloat16(a - __bfloat162float(h->x));
    l->y = __float2bfloat16(b - __bfloat162float(h->y));
}

// copy rows x 128B into SW128-swizzled smem tile (byte pitch)
__device__ __forceinline__ void cp_rows(uint32_t dst, const char* src, long pitchB, int rows) {
    for (int idx = threadIdx.x; idx < rows * 8; idx += blockDim.x) {
        const int r = idx >> 3, cg = idx & 7;
        cp16(dst + SWZ(r * 128 + cg * 16), src + (long)r * pitchB + cg * 16);
    }
}

// ========== 32x64-warp core (qkv/proj, 256 threads, bf16 3-term) ==========
__device__ __forceinline__ void cp_chunk(uint32_t stb,
                                         const __nv_bfloat16* Ah, const __nv_bfloat16* Al,
                                         const __nv_bfloat16* Bh, const __nv_bfloat16* Bl,
                                         long pitch, long k0) {
    cp_rows(stb,         (const char*)(Ah + k0), pitch * 2, 128);
    cp_rows(stb + 16384, (const char*)(Al + k0), pitch * 2, 128);
    cp_rows(stb + 32768, (const char*)(Bh + k0), pitch * 2, 128);
    cp_rows(stb + 49152, (const char*)(Bl + k0), pitch * 2, 128);
}
__device__ __forceinline__ void mma_chunk(uint32_t sAh, uint32_t sAl, uint32_t sBh, uint32_t sBl,
                                          float (&acc)[2][8][4], int wm, int wn, int lane) {
    const int lr = lane & 15;
    const int lc = (lane >> 4) * 16;
    #pragma unroll
    for (int kk = 0; kk < 4; kk++) {
        const int kb = kk * 32;
        uint32_t ah[2][4], al[2][4];
        #pragma unroll
        for (int mt = 0; mt < 2; mt++) {
            const uint32_t off = SWZ((wm * 32 + mt * 16 + lr) * 128 + kb + lc);
            ldm4(ah[mt], sAh + off);
            ldm4(al[mt], sAl + off);
        }
        #pragma unroll
        for (int np = 0; np < 4; np++) {
            const uint32_t off = SWZ((wn * 64 + np * 16 + lr) * 128 + kb + lc);
            uint32_t bh[4], bl[4];
            ldm4(bh, sBh + off);
            ldm4(bl, sBl + off);
            uint32_t b0h[2] = {bh[0], bh[2]}, b1h[2] = {bh[1], bh[3]};
            uint32_t b0l[2] = {bl[0], bl[2]}, b1l[2] = {bl[1], bl[3]};
            #pragma unroll
            for (int mt = 0; mt < 2; mt++) {
                mma16816(acc[mt][np * 2],     ah[mt], b0h);
                mma16816(acc[mt][np * 2 + 1], ah[mt], b1h);
            }
            #pragma unroll
            for (int mt = 0; mt < 2; mt++) {
                mma16816(acc[mt][np * 2],     ah[mt], b0l);
                mma16816(acc[mt][np * 2 + 1], ah[mt], b1l);
            }
            #pragma unroll
            for (int mt = 0; mt < 2; mt++) {
                mma16816(acc[mt][np * 2],     al[mt], b0h);
                mma16816(acc[mt][np * 2 + 1], al[mt], b1h);
            }
        }
    }
}
__device__ __forceinline__ void hmma_pipeline(uint32_t sb,
        const __nv_bfloat16* Ah, const __nv_bfloat16* Al,
        const __nv_bfloat16* Bh, const __nv_bfloat16* Bl,
        long pitch, int nch, float (&acc)[2][8][4], int wm, int wn, int lane) {
    cp_chunk(sb, Ah, Al, Bh, Bl, pitch, 0);
    asm volatile("cp.async.commit_group;" ::: "memory");
    for (int ch = 0; ch < nch; ch++) {
        const uint32_t stb = sb + (ch & 1) * 65536;
        if (ch + 1 < nch) {
            cp_chunk(sb + ((ch + 1) & 1) * 65536, Ah, Al, Bh, Bl, pitch, (long)(ch + 1) * 64);
            asm volatile("cp.async.commit_group;" ::: "memory");
            asm volatile("cp.async.wait_group 1;" ::: "memory");
        } else {
            asm volatile("cp.async.wait_group 0;" ::: "memory");
        }
        __syncthreads();
        mma_chunk(stb, stb + 16384, stb + 32768, stb + 49152, acc, wm, wn, lane);
        __syncthreads();
    }
}

// ---------- GroupNorm ----------
__global__ void __launch_bounds__(256) gn_kernel(const float* __restrict__ x,
                                                 const float* __restrict__ w,
                                                 const float* __restrict__ bias) {
    const int b = blockIdx.x >> 5, g = blockIdx.x & 31;
    const float* xp = x   + (b * CH + g * CPG) * NPIX;
    float*       hp = g_h + (b * CH + g * CPG) * NPIX;
    const int NE = CPG * NPIX;
    float s = 0.f, ss = 0.f;
    const float4* x4 = (const float4*)xp;
    for (int i = threadIdx.x; i < NE / 4; i += 256) {
        float4 v = x4[i];
        s  += v.x + v.y + v.z + v.w;
        ss += v.x * v.x + v.y * v.y + v.z * v.z + v.w * v.w;
    }
    __shared__ float rs[32], rss[32];
    #pragma unroll
    for (int o = 16; o; o >>= 1) {
        s  += __shfl_xor_sync(~0u, s,  o);
        ss += __shfl_xor_sync(~0u, ss, o);
    }
    const int lane = threadIdx.x & 31, wid = threadIdx.x >> 5;
    if (lane == 0) { rs[wid] = s; rss[wid] = ss; }
    __syncthreads();
    if (wid == 0) {
        s  = (lane < 8) ? rs[lane]  : 0.f;
        ss = (lane < 8) ? rss[lane] : 0.f;
        #pragma unroll
        for (int o = 16; o; o >>= 1) {
            s  += __shfl_xor_sync(~0u, s,  o);
            ss += __shfl_xor_sync(~0u, ss, o);
        }
        if (lane == 0) { rs[0] = s; rss[0] = ss; }
    }
    __syncthreads();
    const float mu   = rs[0] / (float)NE;
    const float rstd = rsqrtf(rss[0] / (float)NE - mu * mu + 1e-5f);
    float4* h4 = (float4*)hp;
    for (int i = threadIdx.x; i < NE / 4; i += 256) {
        const int c = g * CPG + (i >> 10);
        const float wc = w[c] * rstd, bc = bias[c] - mu * wc;
        float4 v = x4[i];
        v.x = v.x * wc + bc; v.y = v.y * wc + bc; v.z = v.z * wc + bc; v.w = v.w * wc + bc;
        h4[i] = v;
    }
}

// ---------- h: [c][n] fp32 -> [n][c] hi/lo bf16 ----------
__global__ void __launch_bounds__(256) h_convert() {
    __shared__ float t[32][33];
    const int n0 = blockIdx.x * 32, c0 = blockIdx.y * 32, b = blockIdx.z;
    const float* src = g_h + ((size_t)b * CH + c0) * NPIX + n0;
    const int tx = threadIdx.x & 31, ty = threadIdx.x >> 5;
    #pragma unroll
    for (int j = 0; j < 4; j++)
        t[ty + 8 * j][tx] = src[(size_t)(ty + 8 * j) * NPIX + tx];
    __syncthreads();
    const size_t dbase = ((size_t)b * NPIX + n0) * CH + c0;
    #pragma unroll
    for (int j = 0; j < 4; j++) {
        float v = t[tx][ty + 8 * j];
        __nv_bfloat16 h = __float2bfloat16(v);
        g_hh[dbase + (size_t)(ty + 8 * j) * CH + tx] = h;
        g_hl[dbase + (size_t)(ty + 8 * j) * CH + tx] = __float2bfloat16(v - __bfloat162float(h));
    }
}

// ---------- weight split ----------
__global__ void __launch_bounds__(256) w_convert(const float* __restrict__ qkv_w,
                                                 const float* __restrict__ proj_w) {
    const int f4 = blockIdx.x * 256 + threadIdx.x;
    const float* src;
    __nv_bfloat16 *dh, *dl;
    size_t e;
    if (f4 < 49152) { src = qkv_w;  dh = g_wqh; dl = g_wql; e = (size_t)f4 * 4; }
    else            { src = proj_w; dh = g_wph; dl = g_wpl; e = (size_t)(f4 - 49152) * 4; }
    float4 v = *(const float4*)(src + e);
    __nv_bfloat162 h0, h1, l0, l1;
    split2(v.x, v.y, &h0, &l0);
    split2(v.z, v.w, &h1, &l1);
    *(__nv_bfloat162*)(dh + e)     = h0; *(__nv_bfloat162*)(dh + e + 2) = h1;
    *(__nv_bfloat162*)(dl + e)     = l0; *(__nv_bfloat162*)(dl + e + 2) = l1;
}

// ---------- QKV (q,k -> [n][c] bf16 hi/lo, v -> [c][n] fp16) ----------
__global__ void __launch_bounds__(256, 1) qkv_hmma(const float* __restrict__ qkv_b) {
    extern __shared__ char smem[];
    const uint32_t sb = smem_u32(smem);
    const int tid = threadIdx.x, lane = tid & 31, wid = tid >> 5;
    const int wm = wid & 3, wn = wid >> 2;
    const int b = blockIdx.z, n0 = blockIdx.x * 128, o0 = blockIdx.y * 128;

    const __nv_bfloat16* Ah = g_wqh + (size_t)o0 * CH;
    const __nv_bfloat16* Al = g_wql + (size_t)o0 * CH;
    const __nv_bfloat16* Bh = g_hh + ((size_t)b * NPIX + n0) * CH;
    const __nv_bfloat16* Bl = g_hl + ((size_t)b * NPIX + n0) * CH;

    float acc[2][8][4] = {};
    hmma_pipeline(sb, Ah, Al, Bh, Bl, CH, 4, acc, wm, wn, lane);

    const int r0 = wm * 32 + (lane >> 2), c0 = wn * 64 + (lane & 3) * 2;
    #pragma unroll
    for (int mt = 0; mt < 2; mt++) {
        const float b0 = qkv_b[o0 + r0 + mt * 16];
        const float b1 = qkv_b[o0 + r0 + mt * 16 + 8];
        #pragma unroll
        for (int nt = 0; nt < 8; nt++) {
            acc[mt][nt][0] += b0; acc[mt][nt][1] += b0;
            acc[mt][nt][2] += b1; acc[mt][nt][3] += b1;
        }
    }

    const int sel = blockIdx.y >> 1;   // 0=q, 1=k, 2=v
    if (sel == 2) {
        __half* vh = g_v16h + ((size_t)b * CH + (o0 - 512)) * NPIX + n0;
        #pragma unroll
        for (int mt = 0; mt < 2; mt++)
            #pragma unroll
            for (int nt = 0; nt < 8; nt++) {
                const int rr = r0 + mt * 16, cc = c0 + nt * 8;
                __half2 h0, h1;
                h0.x = __float2half_rn(acc[mt][nt][0]); h0.y = __float2half_rn(acc[mt][nt][1]);
                h1.x = __float2half_rn(acc[mt][nt][2]); h1.y = __float2half_rn(acc[mt][nt][3]);
                *(__half2*)(vh + (size_t)rr * NPIX + cc)       = h0;
                *(__half2*)(vh + (size_t)(rr + 8) * NPIX + cc) = h1;
            }
    } else {
        float* st = (float*)smem;   // [c 128][n 132]
        #pragma unroll
        for (int mt = 0; mt < 2; mt++)
            #pragma unroll
            for (int nt = 0; nt < 8; nt++) {
                const int rr = r0 + mt * 16, cc = c0 + nt * 8;
                st[(cc)     * 132 + rr]     = acc[mt][nt][0];
                st[(cc + 1) * 132 + rr]     = acc[mt][nt][1];
                st[(cc)     * 132 + rr + 8] = acc[mt][nt][2];
                st[(cc + 1) * 132 + rr + 8] = acc[mt][nt][3];
            }
        __syncthreads();
        __nv_bfloat16* dh = (sel ? g_kh : g_qh) + ((size_t)b * NPIX + n0) * CH + (o0 - sel * 256);
        __nv_bfloat16* dl = (sel ? g_kl : g_ql) + ((size_t)b * NPIX + n0) * CH + (o0 - sel * 256);
        const int o4 = lane * 4, nb = tid >> 5;
        #pragma unroll
        for (int j = 0; j < 16; j++) {
            const int n = nb + 8 * j;
            float4 v = *(float4*)(st + n * 132 + o4);
            __nv_bfloat162 h0, h1, l0, l1;
            split2(v.x, v.y, &h0, &l0);
            split2(v.z, v.w, &h1, &l1);
            *(__nv_bfloat162*)(dh + (size_t)n * CH + o4)     = h0;
            *(__nv_bfloat162*)(dh + (size_t)n * CH + o4 + 2) = h1;
            *(__nv_bfloat162*)(dl + (size_t)n * CH + o4)     = l0;
            *(__nv_bfloat162*)(dl + (size_t)n * CH + o4 + 2) = l1;
        }
    }
}

// ---------- S = Q K^T (256 threads, CTA 256x128, warp 64x64, bf16 3-term) ----------
// stage: Ah 32K @0 | Al @32768 | Bh 16K @65536 | Bl @81920 = 96K; x2 = 192K
__global__ void __launch_bounds__(256, 1) s_gemm_kernel() {
    extern __shared__ char smem[];
    const uint32_t sb = smem_u32(smem);
    const int tid = threadIdx.x, lane = tid & 31, wid = tid >> 5;
    const int wm = wid & 3, wn = wid >> 2;   // 4 x 2 warps
    const int b = blockIdx.z, i0 = blockIdx.y * 256, j0 = blockIdx.x * 128;

    const char* Ah = (const char*)(g_qh + ((size_t)b * NPIX + i0) * CH);
    const char* Al = (const char*)(g_ql + ((size_t)b * NPIX + i0) * CH);
    const char* Bh = (const char*)(g_kh + ((size_t)b * NPIX + j0) * CH);
    const char* Bl = (const char*)(g_kl + ((size_t)b * NPIX + j0) * CH);
    const long pB = CH * 2;

    float acc[4][8][4] = {};
    const int lr = lane & 15, lc = (lane >> 4) * 16;

    cp_rows(sb,         Ah, pB, 256);
    cp_rows(sb + 32768, Al, pB, 256);
    cp_rows(sb + 65536, Bh, pB, 128);
    cp_rows(sb + 81920, Bl, pB, 128);
    asm volatile("cp.async.commit_group;" ::: "memory");

    for (int ch = 0; ch < 4; ch++) {
        const uint32_t stb = sb + (ch & 1) * 98304;
        if (ch + 1 < 4) {
            const uint32_t nstb = sb + ((ch + 1) & 1) * 98304;
            const long k0 = (long)(ch + 1) * 128;
            cp_rows(nstb,         Ah + k0, pB, 256);
            cp_rows(nstb + 32768, Al + k0, pB, 256);
            cp_rows(nstb + 65536, Bh + k0, pB, 128);
            cp_rows(nstb + 81920, Bl + k0, pB, 128);
            asm volatile("cp.async.commit_group;" ::: "memory");
            asm volatile("cp.async.wait_group 1;" ::: "memory");
        } else {
            asm volatile("cp.async.wait_group 0;" ::: "memory");
        }
        __syncthreads();
        #pragma unroll
        for (int kk = 0; kk < 4; kk++) {
            const int kb = kk * 32;
            uint32_t ah[4][4], al[4][4];
            #pragma unroll
            for (int mt = 0; mt < 4; mt++) {
                const uint32_t off = SWZ((wm * 64 + mt * 16 + lr) * 128 + kb + lc);
                ldm4(ah[mt], stb + off);
                ldm4(al[mt], stb + 32768 + off);
            }
            #pragma unroll
            for (int np = 0; np < 4; np++) {
                const uint32_t off = SWZ((wn * 64 + np * 16 + lr) * 128 + kb + lc);
                uint32_t bh[4], bl[4];
                ldm4(bh, stb + 65536 + off);
                ldm4(bl, stb + 81920 + off);
                uint32_t b0h[2] = {bh[0], bh[2]}, b1h[2] = {bh[1], bh[3]};
                uint32_t b0l[2] = {bl[0], bl[2]}, b1l[2] = {bl[1], bl[3]};
                #pragma unroll
                for (int mt = 0; mt < 4; mt++) {
                    mma16816(acc[mt][np * 2],     ah[mt], b0h);
                    mma16816(acc[mt][np * 2 + 1], ah[mt], b1h);
                }
                #pragma unroll
                for (int mt = 0; mt < 4; mt++) {
                    mma16816(acc[mt][np * 2],     ah[mt], b0l);
                    mma16816(acc[mt][np * 2 + 1], ah[mt], b1l);
                }
                #pragma unroll
                for (int mt = 0; mt < 4; mt++) {
                    mma16816(acc[mt][np * 2],     al[mt], b0h);
                    mma16816(acc[mt][np * 2 + 1], al[mt], b1h);
                }
            }
        }
        __syncthreads();
    }

    float* Sb = g_S + ((size_t)b * NPIX + i0) * NPIX + j0;
    const int r0 = wm * 64 + (lane >> 2), c0 = wn * 64 + (lane & 3) * 2;
    #pragma unroll
    for (int mt = 0; mt < 4; mt++)
        #pragma unroll
        for (int nt = 0; nt < 8; nt++) {
            float* p = Sb + (size_t)(r0 + mt * 16) * NPIX + c0 + nt * 8;
            *(float2*)p = make_float2(acc[mt][nt][0], acc[mt][nt][1]);
            *(float2*)(p + (size_t)8 * NPIX) = make_float2(acc[mt][nt][2], acc[mt][nt][3]);
        }
}

// ---------- softmax rows -> P fp16 ----------
__global__ void __launch_bounds__(256) softmax_kernel() {
    const size_t row = blockIdx.x;
    const float4* s4 = (const float4*)(g_S + row * NPIX);
    const int tid = threadIdx.x, lane = tid & 31, wid = tid >> 5;
    __shared__ float rmax[8], rsum[8];
    float4 v[4];
    float mx = -1e30f;
    #pragma unroll
    for (int k = 0; k < 4; k++) {
        float4 t = s4[tid + 256 * k];
        t.x *= SCALE; t.y *= SCALE; t.z *= SCALE; t.w *= SCALE;
        v[k] = t;
        mx = fmaxf(mx, fmaxf(fmaxf(t.x, t.y), fmaxf(t.z, t.w)));
    }
    #pragma unroll
    for (int o = 16; o; o >>= 1) mx = fmaxf(mx, __shfl_xor_sync(~0u, mx, o));
    if (lane == 0) rmax[wid] = mx;
    __syncthreads();
    mx = rmax[0];
    #pragma unroll
    for (int i = 1; i < 8; i++) mx = fmaxf(mx, rmax[i]);
    float sum = 0.f;
    #pragma unroll
    for (int k = 0; k < 4; k++) {
        v[k].x = __expf(v[k].x - mx); v[k].y = __expf(v[k].y - mx);
        v[k].z = __expf(v[k].z - mx); v[k].w = __expf(v[k].w - mx);
        sum += v[k].x + v[k].y + v[k].z + v[k].w;
    }
    #pragma unroll
    for (int o = 16; o; o >>= 1) sum += __shfl_xor_sync(~0u, sum, o);
    if (lane == 0) rsum[wid] = sum;
    __syncthreads();
    sum = rsum[0]+rsum[1]+rsum[2]+rsum[3]+rsum[4]+rsum[5]+rsum[6]+rsum[7];
    const float inv = 1.f / sum;
    __half* ph = g_p + row * NPIX;
    #pragma unroll
    for (int k = 0; k < 4; k++) {
        const int e0 = (tid + 256 * k) * 4;
        __half2 h0, h1;
        h0.x = __float2half_rn(v[k].x * inv); h0.y = __float2half_rn(v[k].y * inv);
        h1.x = __float2half_rn(v[k].z * inv); h1.y = __float2half_rn(v[k].w * inv);
        *(__half2*)(ph + e0)     = h0;
        *(__half2*)(ph + e0 + 2) = h1;
    }
}

// ---------- O = P V (256 threads, CTA 128x256, warp 64x64, fp16 single-term) ----------
// stage: P 16K @0 | Vh 32K @16384 = 48K; x2 = 96K
__global__ void __launch_bounds__(256, 1) pv_gemm_kernel() {
    extern __shared__ char smem[];
    const uint32_t sb = smem_u32(smem);
    const int tid = threadIdx.x, lane = tid & 31, wid = tid >> 5;
    const int wm = wid & 1, wn = wid >> 1;   // 2 x 4 warps
    const int b = blockIdx.x & 3, i0 = (blockIdx.x >> 2) * 128;

    const char* Ap = (const char*)(g_p + ((size_t)b * NPIX + i0) * NPIX);
    const char* Bh = (const char*)(g_v16h + (size_t)b * CH * NPIX);
    const long pB = NPIX * 2;

    float acc[4][8][4] = {};
    const int lr = lane & 15, lc = (lane >> 4) * 16;

    cp_rows(sb,         Ap, pB, 128);
    cp_rows(sb + 16384, Bh, pB, 256);
    asm volatile("cp.async.commit_group;" ::: "memory");

    for (int ch = 0; ch < 64; ch++) {
        const uint32_t stb = sb + (ch & 1) * 49152;
        if (ch + 1 < 64) {
            const uint32_t nstb = sb + ((ch + 1) & 1) * 49152;
            const long k0 = (long)(ch + 1) * 128;
            cp_rows(nstb,         Ap + k0, pB, 128);
            cp_rows(nstb + 16384, Bh + k0, pB, 256);
            asm volatile("cp.async.commit_group;" ::: "memory");
            asm volatile("cp.async.wait_group 1;" ::: "memory");
        } else {
            asm volatile("cp.async.wait_group 0;" ::: "memory");
        }
        __syncthreads();
        #pragma unroll
        for (int kk = 0; kk < 4; kk++) {
            const int kb = kk * 32;
            uint32_t a[4][4];
            #pragma unroll
            for (int mt = 0; mt < 4; mt++) {
                const uint32_t off = SWZ((wm * 64 + mt * 16 + lr) * 128 + kb + lc);
                ldm4(a[mt], stb + off);
            }
            #pragma unroll
            for (int np = 0; np < 4; np++) {
                const uint32_t off = SWZ((wn * 64 + np * 16 + lr) * 128 + kb + lc);
                uint32_t bh[4];
                ldm4(bh, stb + 16384 + off);
                uint32_t b0h[2] = {bh[0], bh[2]}, b1h[2] = {bh[1], bh[3]};
                #pragma unroll
                for (int mt = 0; mt < 4; mt++) {
                    mma16816h(acc[mt][np * 2],     a[mt], b0h);
                    mma16816h(acc[mt][np * 2 + 1], a[mt], b1h);
                }
            }
        }
        __syncthreads();
    }

    __nv_bfloat16* oh = g_oh + ((size_t)b * NPIX + i0) * CH;
    __nv_bfloat16* ol = g_ol + ((size_t)b * NPIX + i0) * CH;
    const int r0 = wm * 64 + (lane >> 2), c0 = wn * 64 + (lane & 3) * 2;
    #pragma unroll
    for (int mt = 0; mt < 4; mt++)
        #pragma unroll
        for (int nt = 0; nt < 8; nt++) {
            const int rr = r0 + mt * 16, cc = c0 + nt * 8;
            __nv_bfloat162 h, l;
            split2(acc[mt][nt][0], acc[mt][nt][1], &h, &l);
            *(__nv_bfloat162*)(oh + (size_t)rr * CH + cc) = h;
            *(__nv_bfloat162*)(ol + (size_t)rr * CH + cc) = l;
            split2(acc[mt][nt][2], acc[mt][nt][3], &h, &l);
            *(__nv_bfloat162*)(oh + (size_t)(rr + 8) * CH + cc) = h;
            *(__nv_bfloat162*)(ol + (size_t)(rr + 8) * CH + cc) = l;
        }
}

// ---------- out = proj_w * O + proj_b + x ----------
__global__ void __launch_bounds__(256, 1) proj_hmma(const float* __restrict__ proj_b,
                                                    const float* __restrict__ x,
                                                    float* __restrict__ out) {
    extern __shared__ char smem[];
    const uint32_t sb = smem_u32(smem);
    const int tid = threadIdx.x, lane = tid & 31, wid = tid >> 5;
    const int wm = wid & 3, wn = wid >> 2;
    const int b = blockIdx.z, n0 = blockIdx.x * 128, o0 = blockIdx.y * 128;

    const __nv_bfloat16* Ah = g_wph + (size_t)o0 * CH;
    const __nv_bfloat16* Al = g_wpl + (size_t)o0 * CH;
    const __nv_bfloat16* Bh = g_oh + ((size_t)b * NPIX + n0) * CH;
    const __nv_bfloat16* Bl = g_ol + ((size_t)b * NPIX + n0) * CH;

    float acc[2][8][4] = {};
    hmma_pipeline(sb, Ah, Al, Bh, Bl, CH, 4, acc, wm, wn, lane);

    const int r0 = wm * 32 + (lane >> 2), c0 = wn * 64 + (lane & 3) * 2;
    #pragma unroll
    for (int mt = 0; mt < 2; mt++) {
        const int r  = o0 + r0 + mt * 16;
        const float b0 = proj_b[r], b1 = proj_b[r + 8];
        #pragma unroll
        for (int nt = 0; nt < 8; nt++) {
            const size_t idx0 = ((size_t)b * CH + r) * NPIX + n0 + c0 + nt * 8;
            const size_t idx1 = idx0 + (size_t)8 * NPIX;
            float2 x0 = *(const float2*)(x + idx0);
            float2 x1 = *(const float2*)(x + idx1);
            *(float2*)(out + idx0) = make_float2(acc[mt][nt][0] + b0 + x0.x,
                                                 acc[mt][nt][1] + b0 + x0.y);
            *(float2*)(out + idx1) = make_float2(acc[mt][nt][2] + b1 + x1.x,
                                                 acc[mt][nt][3] + b1 + x1.y);
        }
    }
}

// ---------- launch ----------
extern "C" void kernel_launch(void* const* d_in, const int* in_sizes, int n_in,
                              void* d_out, int out_size) {
    const float* x      = (const float*)d_in[0];
    const float* gn_w   = (const float*)d_in[1];
    const float* gn_b   = (const float*)d_in[2];
    const float* qkv_w  = (const float*)d_in[3];
    const float* qkv_b  = (const float*)d_in[4];
    const float* proj_w = (const float*)d_in[5];
    const float* proj_b = (const float*)d_in[6];
    float* out = (float*)d_out;

    cudaFuncSetAttribute(qkv_hmma,      cudaFuncAttributeMaxDynamicSharedMemorySize, 131072);
    cudaFuncSetAttribute(proj_hmma,     cudaFuncAttributeMaxDynamicSharedMemorySize, 131072);
    cudaFuncSetAttribute(s_gemm_kernel, cudaFuncAttributeMaxDynamicSharedMemorySize, 196608);
    cudaFuncSetAttribute(pv_gemm_kernel,cudaFuncAttributeMaxDynamicSharedMemorySize, 98304);

    w_convert<<<256, 256>>>(qkv_w, proj_w);
    gn_kernel<<<BATCH * 32, 256>>>(x, gn_w, gn_b);
    {
        dim3 g(NPIX / 32, CH / 32, BATCH);
        h_convert<<<g, 256>>>();
    }
    {
        dim3 g(NPIX / 128, 6, BATCH);
        qkv_hmma<<<g, 256, 131072>>>(qkv_b);
    }
    {
        dim3 g(NPIX / 128, NPIX / 256, BATCH);
        s_gemm_kernel<<<g, 256, 196608>>>();
    }
    softmax_kernel<<<BATCH * NPIX, 256>>>();
    pv_gemm_kernel<<<(NPIX / 128) * BATCH, 256, 98304>>>();
    {
        dim3 g(NPIX / 128, 2, BATCH);
        proj_hmma<<<g, 256, 131072>>>(proj_b, x, out);
    }
}

// round 10
// speedup vs baseline: 1.6841x; 1.4491x over previous
#include <cuda_runtime.h>
#include <cuda_bf16.h>
#include <cuda_fp16.h>
#include <math.h>
#include <stdint.h>

#define BATCH 4
#define CH    256
#define NPIX  4096
#define CPG   8
#define SCALE 0.0625f

__device__ float g_h [BATCH * CH * NPIX];
__device__ __nv_bfloat16 g_hh[(size_t)BATCH * NPIX * CH];
__device__ __nv_bfloat16 g_hl[(size_t)BATCH * NPIX * CH];
__device__ __nv_bfloat16 g_wqh[3 * CH * CH], g_wql[3 * CH * CH];
__device__ __nv_bfloat16 g_wph[CH * CH],     g_wpl[CH * CH];
__device__ __half g_q16[(size_t)BATCH * NPIX * CH];
__device__ __half g_k16[(size_t)BATCH * NPIX * CH];
__device__ __half g_v16h[(size_t)BATCH * CH * NPIX];
__device__ __half g_S [(size_t)BATCH * NPIX * NPIX];
__device__ __half g_p [(size_t)BATCH * NPIX * NPIX];
__device__ __nv_bfloat16 g_oh[(size_t)BATCH * NPIX * CH];
__device__ __nv_bfloat16 g_ol[(size_t)BATCH * NPIX * CH];

#define SWZ(o) ((o) ^ (((o) >> 3) & 0x70))

__device__ __forceinline__ uint32_t smem_u32(const void* p) {
    uint32_t a;
    asm("{ .reg .u64 t; cvta.to.shared.u64 t, %1; cvt.u32.u64 %0, t; }" : "=r"(a) : "l"(p));
    return a;
}
__device__ __forceinline__ void cp16(uint32_t dst, const void* src) {
    asm volatile("cp.async.cg.shared.global [%0], [%1], 16;" :: "r"(dst), "l"(src) : "memory");
}
__device__ __forceinline__ void ldm4(uint32_t* r, uint32_t addr) {
    asm volatile("ldmatrix.sync.aligned.m8n8.x4.shared.b16 {%0,%1,%2,%3}, [%4];"
                 : "=r"(r[0]), "=r"(r[1]), "=r"(r[2]), "=r"(r[3]) : "r"(addr));
}
__device__ __forceinline__ void mma16816(float* c, const uint32_t* a, const uint32_t* b) {
    asm volatile("mma.sync.aligned.m16n8k16.row.col.f32.bf16.bf16.f32 "
                 "{%0,%1,%2,%3}, {%4,%5,%6,%7}, {%8,%9}, {%0,%1,%2,%3};"
                 : "+f"(c[0]), "+f"(c[1]), "+f"(c[2]), "+f"(c[3])
                 : "r"(a[0]), "r"(a[1]), "r"(a[2]), "r"(a[3]), "r"(b[0]), "r"(b[1]));
}
__device__ __forceinline__ void mma16816h(float* c, const uint32_t* a, const uint32_t* b) {
    asm volatile("mma.sync.aligned.m16n8k16.row.col.f32.f16.f16.f32 "
                 "{%0,%1,%2,%3}, {%4,%5,%6,%7}, {%8,%9}, {%0,%1,%2,%3};"
                 : "+f"(c[0]), "+f"(c[1]), "+f"(c[2]), "+f"(c[3])
                 : "r"(a[0]), "r"(a[1]), "r"(a[2]), "r"(a[3]), "r"(b[0]), "r"(b[1]));
}
__device__ __forceinline__ void split2(float a, float b, __nv_bfloat162* h, __nv_bfloat162* l) {
    h->x = __float2bfloat16(a); h->y = __float2bfloat16(b);
    l->x = __float2bfloat16(a - __bfloat162float(h->x));
    l->y = __float2bfloat16(b - __bfloat162float(h->y));
}

// copy rows x 128B into SW128-swizzled smem tile (byte pitch)
__device__ __forceinline__ void cp_rows(uint32_t dst, const char* src, long pitchB, int rows) {
    for (int idx = threadIdx.x; idx < rows * 8; idx += blockDim.x) {
        const int r = idx >> 3, cg = idx & 7;
        cp16(dst + SWZ(r * 128 + cg * 16), src + (long)r * pitchB + cg * 16);
    }
}

// ========== 32x64-warp core (qkv/proj, 256 threads, bf16 3-term) ==========
__device__ __forceinline__ void cp_chunk(uint32_t stb,
                                         const __nv_bfloat16* Ah, const __nv_bfloat16* Al,
                                         const __nv_bfloat16* Bh, const __nv_bfloat16* Bl,
                                         long pitch, long k0) {
    cp_rows(stb,         (const char*)(Ah + k0), pitch * 2, 128);
    cp_rows(stb + 16384, (const char*)(Al + k0), pitch * 2, 128);
    cp_rows(stb + 32768, (const char*)(Bh + k0), pitch * 2, 128);
    cp_rows(stb + 49152, (const char*)(Bl + k0), pitch * 2, 128);
}
__device__ __forceinline__ void mma_chunk(uint32_t sAh, uint32_t sAl, uint32_t sBh, uint32_t sBl,
                                          float (&acc)[2][8][4], int wm, int wn, int lane) {
    const int lr = lane & 15;
    const int lc = (lane >> 4) * 16;
    #pragma unroll
    for (int kk = 0; kk < 4; kk++) {
        const int kb = kk * 32;
        uint32_t ah[2][4], al[2][4];
        #pragma unroll
        for (int mt = 0; mt < 2; mt++) {
            const uint32_t off = SWZ((wm * 32 + mt * 16 + lr) * 128 + kb + lc);
            ldm4(ah[mt], sAh + off);
            ldm4(al[mt], sAl + off);
        }
        #pragma unroll
        for (int np = 0; np < 4; np++) {
            const uint32_t off = SWZ((wn * 64 + np * 16 + lr) * 128 + kb + lc);
            uint32_t bh[4], bl[4];
            ldm4(bh, sBh + off);
            ldm4(bl, sBl + off);
            uint32_t b0h[2] = {bh[0], bh[2]}, b1h[2] = {bh[1], bh[3]};
            uint32_t b0l[2] = {bl[0], bl[2]}, b1l[2] = {bl[1], bl[3]};
            #pragma unroll
            for (int mt = 0; mt < 2; mt++) {
                mma16816(acc[mt][np * 2],     ah[mt], b0h);
                mma16816(acc[mt][np * 2 + 1], ah[mt], b1h);
            }
            #pragma unroll
            for (int mt = 0; mt < 2; mt++) {
                mma16816(acc[mt][np * 2],     ah[mt], b0l);
                mma16816(acc[mt][np * 2 + 1], ah[mt], b1l);
            }
            #pragma unroll
            for (int mt = 0; mt < 2; mt++) {
                mma16816(acc[mt][np * 2],     al[mt], b0h);
                mma16816(acc[mt][np * 2 + 1], al[mt], b1h);
            }
        }
    }
}
__device__ __forceinline__ void hmma_pipeline(uint32_t sb,
        const __nv_bfloat16* Ah, const __nv_bfloat16* Al,
        const __nv_bfloat16* Bh, const __nv_bfloat16* Bl,
        long pitch, int nch, float (&acc)[2][8][4], int wm, int wn, int lane) {
    cp_chunk(sb, Ah, Al, Bh, Bl, pitch, 0);
    asm volatile("cp.async.commit_group;" ::: "memory");
    for (int ch = 0; ch < nch; ch++) {
        const uint32_t stb = sb + (ch & 1) * 65536;
        if (ch + 1 < nch) {
            cp_chunk(sb + ((ch + 1) & 1) * 65536, Ah, Al, Bh, Bl, pitch, (long)(ch + 1) * 64);
            asm volatile("cp.async.commit_group;" ::: "memory");
            asm volatile("cp.async.wait_group 1;" ::: "memory");
        } else {
            asm volatile("cp.async.wait_group 0;" ::: "memory");
        }
        __syncthreads();
        mma_chunk(stb, stb + 16384, stb + 32768, stb + 49152, acc, wm, wn, lane);
        __syncthreads();
    }
}

// ---------- GroupNorm ----------
__global__ void __launch_bounds__(256) gn_kernel(const float* __restrict__ x,
                                                 const float* __restrict__ w,
                                                 const float* __restrict__ bias) {
    const int b = blockIdx.x >> 5, g = blockIdx.x & 31;
    const float* xp = x   + (b * CH + g * CPG) * NPIX;
    float*       hp = g_h + (b * CH + g * CPG) * NPIX;
    const int NE = CPG * NPIX;
    float s = 0.f, ss = 0.f;
    const float4* x4 = (const float4*)xp;
    for (int i = threadIdx.x; i < NE / 4; i += 256) {
        float4 v = x4[i];
        s  += v.x + v.y + v.z + v.w;
        ss += v.x * v.x + v.y * v.y + v.z * v.z + v.w * v.w;
    }
    __shared__ float rs[32], rss[32];
    #pragma unroll
    for (int o = 16; o; o >>= 1) {
        s  += __shfl_xor_sync(~0u, s,  o);
        ss += __shfl_xor_sync(~0u, ss, o);
    }
    const int lane = threadIdx.x & 31, wid = threadIdx.x >> 5;
    if (lane == 0) { rs[wid] = s; rss[wid] = ss; }
    __syncthreads();
    if (wid == 0) {
        s  = (lane < 8) ? rs[lane]  : 0.f;
        ss = (lane < 8) ? rss[lane] : 0.f;
        #pragma unroll
        for (int o = 16; o; o >>= 1) {
            s  += __shfl_xor_sync(~0u, s,  o);
            ss += __shfl_xor_sync(~0u, ss, o);
        }
        if (lane == 0) { rs[0] = s; rss[0] = ss; }
    }
    __syncthreads();
    const float mu   = rs[0] / (float)NE;
    const float rstd = rsqrtf(rss[0] / (float)NE - mu * mu + 1e-5f);
    float4* h4 = (float4*)hp;
    for (int i = threadIdx.x; i < NE / 4; i += 256) {
        const int c = g * CPG + (i >> 10);
        const float wc = w[c] * rstd, bc = bias[c] - mu * wc;
        float4 v = x4[i];
        v.x = v.x * wc + bc; v.y = v.y * wc + bc; v.z = v.z * wc + bc; v.w = v.w * wc + bc;
        h4[i] = v;
    }
}

// ---------- h: [c][n] fp32 -> [n][c] hi/lo bf16 ----------
__global__ void __launch_bounds__(256) h_convert() {
    __shared__ float t[32][33];
    const int n0 = blockIdx.x * 32, c0 = blockIdx.y * 32, b = blockIdx.z;
    const float* src = g_h + ((size_t)b * CH + c0) * NPIX + n0;
    const int tx = threadIdx.x & 31, ty = threadIdx.x >> 5;
    #pragma unroll
    for (int j = 0; j < 4; j++)
        t[ty + 8 * j][tx] = src[(size_t)(ty + 8 * j) * NPIX + tx];
    __syncthreads();
    const size_t dbase = ((size_t)b * NPIX + n0) * CH + c0;
    #pragma unroll
    for (int j = 0; j < 4; j++) {
        float v = t[tx][ty + 8 * j];
        __nv_bfloat16 h = __float2bfloat16(v);
        g_hh[dbase + (size_t)(ty + 8 * j) * CH + tx] = h;
        g_hl[dbase + (size_t)(ty + 8 * j) * CH + tx] = __float2bfloat16(v - __bfloat162float(h));
    }
}

// ---------- weight split ----------
__global__ void __launch_bounds__(256) w_convert(const float* __restrict__ qkv_w,
                                                 const float* __restrict__ proj_w) {
    const int f4 = blockIdx.x * 256 + threadIdx.x;
    const float* src;
    __nv_bfloat16 *dh, *dl;
    size_t e;
    if (f4 < 49152) { src = qkv_w;  dh = g_wqh; dl = g_wql; e = (size_t)f4 * 4; }
    else            { src = proj_w; dh = g_wph; dl = g_wpl; e = (size_t)(f4 - 49152) * 4; }
    float4 v = *(const float4*)(src + e);
    __nv_bfloat162 h0, h1, l0, l1;
    split2(v.x, v.y, &h0, &l0);
    split2(v.z, v.w, &h1, &l1);
    *(__nv_bfloat162*)(dh + e)     = h0; *(__nv_bfloat162*)(dh + e + 2) = h1;
    *(__nv_bfloat162*)(dl + e)     = l0; *(__nv_bfloat162*)(dl + e + 2) = l1;
}

// ---------- QKV (q,k -> [n][c] fp16, v -> [c][n] fp16) ----------
__global__ void __launch_bounds__(256, 1) qkv_hmma(const float* __restrict__ qkv_b) {
    extern __shared__ char smem[];
    const uint32_t sb = smem_u32(smem);
    const int tid = threadIdx.x, lane = tid & 31, wid = tid >> 5;
    const int wm = wid & 3, wn = wid >> 2;
    const int b = blockIdx.z, n0 = blockIdx.x * 128, o0 = blockIdx.y * 128;

    const __nv_bfloat16* Ah = g_wqh + (size_t)o0 * CH;
    const __nv_bfloat16* Al = g_wql + (size_t)o0 * CH;
    const __nv_bfloat16* Bh = g_hh + ((size_t)b * NPIX + n0) * CH;
    const __nv_bfloat16* Bl = g_hl + ((size_t)b * NPIX + n0) * CH;

    float acc[2][8][4] = {};
    hmma_pipeline(sb, Ah, Al, Bh, Bl, CH, 4, acc, wm, wn, lane);

    const int r0 = wm * 32 + (lane >> 2), c0 = wn * 64 + (lane & 3) * 2;
    #pragma unroll
    for (int mt = 0; mt < 2; mt++) {
        const float b0 = qkv_b[o0 + r0 + mt * 16];
        const float b1 = qkv_b[o0 + r0 + mt * 16 + 8];
        #pragma unroll
        for (int nt = 0; nt < 8; nt++) {
            acc[mt][nt][0] += b0; acc[mt][nt][1] += b0;
            acc[mt][nt][2] += b1; acc[mt][nt][3] += b1;
        }
    }

    const int sel = blockIdx.y >> 1;   // 0=q, 1=k, 2=v
    if (sel == 2) {
        __half* vh = g_v16h + ((size_t)b * CH + (o0 - 512)) * NPIX + n0;
        #pragma unroll
        for (int mt = 0; mt < 2; mt++)
            #pragma unroll
            for (int nt = 0; nt < 8; nt++) {
                const int rr = r0 + mt * 16, cc = c0 + nt * 8;
                __half2 h0, h1;
                h0.x = __float2half_rn(acc[mt][nt][0]); h0.y = __float2half_rn(acc[mt][nt][1]);
                h1.x = __float2half_rn(acc[mt][nt][2]); h1.y = __float2half_rn(acc[mt][nt][3]);
                *(__half2*)(vh + (size_t)rr * NPIX + cc)       = h0;
                *(__half2*)(vh + (size_t)(rr + 8) * NPIX + cc) = h1;
            }
    } else {
        float* st = (float*)smem;   // [c 128][n 132]
        #pragma unroll
        for (int mt = 0; mt < 2; mt++)
            #pragma unroll
            for (int nt = 0; nt < 8; nt++) {
                const int rr = r0 + mt * 16, cc = c0 + nt * 8;
                st[(cc)     * 132 + rr]     = acc[mt][nt][0];
                st[(cc + 1) * 132 + rr]     = acc[mt][nt][1];
                st[(cc)     * 132 + rr + 8] = acc[mt][nt][2];
                st[(cc + 1) * 132 + rr + 8] = acc[mt][nt][3];
            }
        __syncthreads();
        __half* dq = (sel ? g_k16 : g_q16) + ((size_t)b * NPIX + n0) * CH + (o0 - sel * 256);
        const int o4 = lane * 4, nb = tid >> 5;
        #pragma unroll
        for (int j = 0; j < 16; j++) {
            const int n = nb + 8 * j;
            float4 v = *(float4*)(st + n * 132 + o4);
            __half2 h0, h1;
            h0.x = __float2half_rn(v.x); h0.y = __float2half_rn(v.y);
            h1.x = __float2half_rn(v.z); h1.y = __float2half_rn(v.w);
            *(__half2*)(dq + (size_t)n * CH + o4)     = h0;
            *(__half2*)(dq + (size_t)n * CH + o4 + 2) = h1;
        }
    }
}

// ---------- S = Q K^T (256 threads, CTA 256x128, warp 64x64, fp16 single-term) ----------
// stage: A 32K @0 | B 16K @32768 = 48K; x2 = 96K
__global__ void __launch_bounds__(256, 1) s_gemm_kernel() {
    extern __shared__ char smem[];
    const uint32_t sb = smem_u32(smem);
    const int tid = threadIdx.x, lane = tid & 31, wid = tid >> 5;
    const int wm = wid & 3, wn = wid >> 2;   // 4 x 2 warps
    const int b = blockIdx.z, i0 = blockIdx.y * 256, j0 = blockIdx.x * 128;

    const char* Aq = (const char*)(g_q16 + ((size_t)b * NPIX + i0) * CH);
    const char* Bk = (const char*)(g_k16 + ((size_t)b * NPIX + j0) * CH);
    const long pB = CH * 2;

    float acc[4][8][4] = {};
    const int lr = lane & 15, lc = (lane >> 4) * 16;

    cp_rows(sb,         Aq, pB, 256);
    cp_rows(sb + 32768, Bk, pB, 128);
    asm volatile("cp.async.commit_group;" ::: "memory");

    for (int ch = 0; ch < 4; ch++) {
        const uint32_t stb = sb + (ch & 1) * 49152;
        if (ch + 1 < 4) {
            const uint32_t nstb = sb + ((ch + 1) & 1) * 49152;
            const long k0 = (long)(ch + 1) * 128;
            cp_rows(nstb,         Aq + k0, pB, 256);
            cp_rows(nstb + 32768, Bk + k0, pB, 128);
            asm volatile("cp.async.commit_group;" ::: "memory");
            asm volatile("cp.async.wait_group 1;" ::: "memory");
        } else {
            asm volatile("cp.async.wait_group 0;" ::: "memory");
        }
        __syncthreads();
        #pragma unroll
        for (int kk = 0; kk < 4; kk++) {
            const int kb = kk * 32;
            uint32_t a[4][4];
            #pragma unroll
            for (int mt = 0; mt < 4; mt++) {
                const uint32_t off = SWZ((wm * 64 + mt * 16 + lr) * 128 + kb + lc);
                ldm4(a[mt], stb + off);
            }
            #pragma unroll
            for (int np = 0; np < 4; np++) {
                const uint32_t off = SWZ((wn * 64 + np * 16 + lr) * 128 + kb + lc);
                uint32_t bh[4];
                ldm4(bh, stb + 32768 + off);
                uint32_t b0h[2] = {bh[0], bh[2]}, b1h[2] = {bh[1], bh[3]};
                #pragma unroll
                for (int mt = 0; mt < 4; mt++) {
                    mma16816h(acc[mt][np * 2],     a[mt], b0h);
                    mma16816h(acc[mt][np * 2 + 1], a[mt], b1h);
                }
            }
        }
        __syncthreads();
    }

    __half* Sb = g_S + ((size_t)b * NPIX + i0) * NPIX + j0;
    const int r0 = wm * 64 + (lane >> 2), c0 = wn * 64 + (lane & 3) * 2;
    #pragma unroll
    for (int mt = 0; mt < 4; mt++)
        #pragma unroll
        for (int nt = 0; nt < 8; nt++) {
            __half* p = Sb + (size_t)(r0 + mt * 16) * NPIX + c0 + nt * 8;
            __half2 h0, h1;
            h0.x = __float2half_rn(acc[mt][nt][0]); h0.y = __float2half_rn(acc[mt][nt][1]);
            h1.x = __float2half_rn(acc[mt][nt][2]); h1.y = __float2half_rn(acc[mt][nt][3]);
            *(__half2*)p = h0;
            *(__half2*)(p + (size_t)8 * NPIX) = h1;
        }
}

// ---------- softmax rows (fp16 S) -> P fp16 ----------
__global__ void __launch_bounds__(256) softmax_kernel() {
    const size_t row = blockIdx.x;
    const uint4* s8 = (const uint4*)(g_S + row * NPIX);   // 8 halfs per uint4
    const int tid = threadIdx.x, lane = tid & 31, wid = tid >> 5;
    __shared__ float rmax[8], rsum[8];

    uint4 raw[2];
    raw[0] = s8[tid];
    raw[1] = s8[tid + 256];
    float v[16];
    #pragma unroll
    for (int k = 0; k < 2; k++) {
        const __half2* hp = (const __half2*)&raw[k];
        #pragma unroll
        for (int j = 0; j < 4; j++) {
            float2 f = __half22float2(hp[j]);
            v[k * 8 + 2 * j]     = f.x * SCALE;
            v[k * 8 + 2 * j + 1] = f.y * SCALE;
        }
    }
    float mx = v[0];
    #pragma unroll
    for (int i = 1; i < 16; i++) mx = fmaxf(mx, v[i]);
    #pragma unroll
    for (int o = 16; o; o >>= 1) mx = fmaxf(mx, __shfl_xor_sync(~0u, mx, o));
    if (lane == 0) rmax[wid] = mx;
    __syncthreads();
    mx = rmax[0];
    #pragma unroll
    for (int i = 1; i < 8; i++) mx = fmaxf(mx, rmax[i]);
    float sum = 0.f;
    #pragma unroll
    for (int i = 0; i < 16; i++) {
        v[i] = __expf(v[i] - mx);
        sum += v[i];
    }
    #pragma unroll
    for (int o = 16; o; o >>= 1) sum += __shfl_xor_sync(~0u, sum, o);
    if (lane == 0) rsum[wid] = sum;
    __syncthreads();
    sum = rsum[0]+rsum[1]+rsum[2]+rsum[3]+rsum[4]+rsum[5]+rsum[6]+rsum[7];
    const float inv = 1.f / sum;

    uint4* ph = (uint4*)(g_p + row * NPIX);
    #pragma unroll
    for (int k = 0; k < 2; k++) {
        uint4 o;
        __half2* op = (__half2*)&o;
        #pragma unroll
        for (int j = 0; j < 4; j++) {
            op[j].x = __float2half_rn(v[k * 8 + 2 * j]     * inv);
            op[j].y = __float2half_rn(v[k * 8 + 2 * j + 1] * inv);
        }
        ph[tid + 256 * k] = o;
    }
}

// ---------- O = P V (256 threads, CTA 128x256, warp 64x64, fp16 single-term) ----------
// stage: P 16K @0 | Vh 32K @16384 = 48K; x2 = 96K
__global__ void __launch_bounds__(256, 1) pv_gemm_kernel() {
    extern __shared__ char smem[];
    const uint32_t sb = smem_u32(smem);
    const int tid = threadIdx.x, lane = tid & 31, wid = tid >> 5;
    const int wm = wid & 1, wn = wid >> 1;   // 2 x 4 warps
    const int b = blockIdx.x & 3, i0 = (blockIdx.x >> 2) * 128;

    const char* Ap = (const char*)(g_p + ((size_t)b * NPIX + i0) * NPIX);
    const char* Bh = (const char*)(g_v16h + (size_t)b * CH * NPIX);
    const long pB = NPIX * 2;

    float acc[4][8][4] = {};
    const int lr = lane & 15, lc = (lane >> 4) * 16;

    cp_rows(sb,         Ap, pB, 128);
    cp_rows(sb + 16384, Bh, pB, 256);
    asm volatile("cp.async.commit_group;" ::: "memory");

    for (int ch = 0; ch < 64; ch++) {
        const uint32_t stb = sb + (ch & 1) * 49152;
        if (ch + 1 < 64) {
            const uint32_t nstb = sb + ((ch + 1) & 1) * 49152;
            const long k0 = (long)(ch + 1) * 128;
            cp_rows(nstb,         Ap + k0, pB, 128);
            cp_rows(nstb + 16384, Bh + k0, pB, 256);
            asm volatile("cp.async.commit_group;" ::: "memory");
            asm volatile("cp.async.wait_group 1;" ::: "memory");
        } else {
            asm volatile("cp.async.wait_group 0;" ::: "memory");
        }
        __syncthreads();
        #pragma unroll
        for (int kk = 0; kk < 4; kk++) {
            const int kb = kk * 32;
            uint32_t a[4][4];
            #pragma unroll
            for (int mt = 0; mt < 4; mt++) {
                const uint32_t off = SWZ((wm * 64 + mt * 16 + lr) * 128 + kb + lc);
                ldm4(a[mt], stb + off);
            }
            #pragma unroll
            for (int np = 0; np < 4; np++) {
                const uint32_t off = SWZ((wn * 64 + np * 16 + lr) * 128 + kb + lc);
                uint32_t bh[4];
                ldm4(bh, stb + 16384 + off);
                uint32_t b0h[2] = {bh[0], bh[2]}, b1h[2] = {bh[1], bh[3]};
                #pragma unroll
                for (int mt = 0; mt < 4; mt++) {
                    mma16816h(acc[mt][np * 2],     a[mt], b0h);
                    mma16816h(acc[mt][np * 2 + 1], a[mt], b1h);
                }
            }
        }
        __syncthreads();
    }

    __nv_bfloat16* oh = g_oh + ((size_t)b * NPIX + i0) * CH;
    __nv_bfloat16* ol = g_ol + ((size_t)b * NPIX + i0) * CH;
    const int r0 = wm * 64 + (lane >> 2), c0 = wn * 64 + (lane & 3) * 2;
    #pragma unroll
    for (int mt = 0; mt < 4; mt++)
        #pragma unroll
        for (int nt = 0; nt < 8; nt++) {
            const int rr = r0 + mt * 16, cc = c0 + nt * 8;
            __nv_bfloat162 h, l;
            split2(acc[mt][nt][0], acc[mt][nt][1], &h, &l);
            *(__nv_bfloat162*)(oh + (size_t)rr * CH + cc) = h;
            *(__nv_bfloat162*)(ol + (size_t)rr * CH + cc) = l;
            split2(acc[mt][nt][2], acc[mt][nt][3], &h, &l);
            *(__nv_bfloat162*)(oh + (size_t)(rr + 8) * CH + cc) = h;
            *(__nv_bfloat162*)(ol + (size_t)(rr + 8) * CH + cc) = l;
        }
}

// ---------- out = proj_w * O + proj_b + x ----------
__global__ void __launch_bounds__(256, 1) proj_hmma(const float* __restrict__ proj_b,
                                                    const float* __restrict__ x,
                                                    float* __restrict__ out) {
    extern __shared__ char smem[];
    const uint32_t sb = smem_u32(smem);
    const int tid = threadIdx.x, lane = tid & 31, wid = tid >> 5;
    const int wm = wid & 3, wn = wid >> 2;
    const int b = blockIdx.z, n0 = blockIdx.x * 128, o0 = blockIdx.y * 128;

    const __nv_bfloat16* Ah = g_wph + (size_t)o0 * CH;
    const __nv_bfloat16* Al = g_wpl + (size_t)o0 * CH;
    const __nv_bfloat16* Bh = g_oh + ((size_t)b * NPIX + n0) * CH;
    const __nv_bfloat16* Bl = g_ol + ((size_t)b * NPIX + n0) * CH;

    float acc[2][8][4] = {};
    hmma_pipeline(sb, Ah, Al, Bh, Bl, CH, 4, acc, wm, wn, lane);

    const int r0 = wm * 32 + (lane >> 2), c0 = wn * 64 + (lane & 3) * 2;
    #pragma unroll
    for (int mt = 0; mt < 2; mt++) {
        const int r  = o0 + r0 + mt * 16;
        const float b0 = proj_b[r], b1 = proj_b[r + 8];
        #pragma unroll
        for (int nt = 0; nt < 8; nt++) {
            const size_t idx0 = ((size_t)b * CH + r) * NPIX + n0 + c0 + nt * 8;
            const size_t idx1 = idx0 + (size_t)8 * NPIX;
            float2 x0 = *(const float2*)(x + idx0);
            float2 x1 = *(const float2*)(x + idx1);
            *(float2*)(out + idx0) = make_float2(acc[mt][nt][0] + b0 + x0.x,
                                                 acc[mt][nt][1] + b0 + x0.y);
            *(float2*)(out + idx1) = make_float2(acc[mt][nt][2] + b1 + x1.x,
                                                 acc[mt][nt][3] + b1 + x1.y);
        }
    }
}

// ---------- launch ----------
extern "C" void kernel_launch(void* const* d_in, const int* in_sizes, int n_in,
                              void* d_out, int out_size) {
    const float* x      = (const float*)d_in[0];
    const float* gn_w   = (const float*)d_in[1];
    const float* gn_b   = (const float*)d_in[2];
    const float* qkv_w  = (const float*)d_in[3];
    const float* qkv_b  = (const float*)d_in[4];
    const float* proj_w = (const float*)d_in[5];
    const float* proj_b = (const float*)d_in[6];
    float* out = (float*)d_out;

    cudaFuncSetAttribute(qkv_hmma,      cudaFuncAttributeMaxDynamicSharedMemorySize, 131072);
    cudaFuncSetAttribute(proj_hmma,     cudaFuncAttributeMaxDynamicSharedMemorySize, 131072);
    cudaFuncSetAttribute(s_gemm_kernel, cudaFuncAttributeMaxDynamicSharedMemorySize, 98304);
    cudaFuncSetAttribute(pv_gemm_kernel,cudaFuncAttributeMaxDynamicSharedMemorySize, 98304);

    w_convert<<<256, 256>>>(qkv_w, proj_w);
    gn_kernel<<<BATCH * 32, 256>>>(x, gn_w, gn_b);
    {
        dim3 g(NPIX / 32, CH / 32, BATCH);
        h_convert<<<g, 256>>>();
    }
    {
        dim3 g(NPIX / 128, 6, BATCH);
        qkv_hmma<<<g, 256, 131072>>>(qkv_b);
    }
    {
        dim3 g(NPIX / 128, NPIX / 256, BATCH);
        s_gemm_kernel<<<g, 256, 98304>>>();
    }
    softmax_kernel<<<BATCH * NPIX, 256>>>();
    pv_gemm_kernel<<<(NPIX / 128) * BATCH, 256, 98304>>>();
    {
        dim3 g(NPIX / 128, 2, BATCH);
        proj_hmma<<<g, 256, 131072>>>(proj_b, x, out);
    }
}

// round 11
// speedup vs baseline: 1.9486x; 1.1571x over previous
#include <cuda_runtime.h>
#include <cuda_fp16.h>
#include <math.h>
#include <stdint.h>

#define BATCH 4
#define CH    256
#define NPIX  4096
#define CPG   8
#define SCALE 0.0625f

__device__ float g_h [BATCH * CH * NPIX];
__device__ __half g_h16[(size_t)BATCH * NPIX * CH];
__device__ __half g_wq16[3 * CH * CH];
__device__ __half g_wp16[CH * CH];
__device__ __half g_q16[(size_t)BATCH * NPIX * CH];
__device__ __half g_k16[(size_t)BATCH * NPIX * CH];
__device__ __half g_v16h[(size_t)BATCH * CH * NPIX];
__device__ __half g_S [(size_t)BATCH * NPIX * NPIX];
__device__ __half g_p [(size_t)BATCH * NPIX * NPIX];
__device__ __half g_o16[(size_t)BATCH * NPIX * CH];

#define SWZ(o) ((o) ^ (((o) >> 3) & 0x70))

__device__ __forceinline__ uint32_t smem_u32(const void* p) {
    uint32_t a;
    asm("{ .reg .u64 t; cvta.to.shared.u64 t, %1; cvt.u32.u64 %0, t; }" : "=r"(a) : "l"(p));
    return a;
}
__device__ __forceinline__ void cp16(uint32_t dst, const void* src) {
    asm volatile("cp.async.cg.shared.global [%0], [%1], 16;" :: "r"(dst), "l"(src) : "memory");
}
__device__ __forceinline__ void ldm4(uint32_t* r, uint32_t addr) {
    asm volatile("ldmatrix.sync.aligned.m8n8.x4.shared.b16 {%0,%1,%2,%3}, [%4];"
                 : "=r"(r[0]), "=r"(r[1]), "=r"(r[2]), "=r"(r[3]) : "r"(addr));
}
__device__ __forceinline__ void mma16816h(float* c, const uint32_t* a, const uint32_t* b) {
    asm volatile("mma.sync.aligned.m16n8k16.row.col.f32.f16.f16.f32 "
                 "{%0,%1,%2,%3}, {%4,%5,%6,%7}, {%8,%9}, {%0,%1,%2,%3};"
                 : "+f"(c[0]), "+f"(c[1]), "+f"(c[2]), "+f"(c[3])
                 : "r"(a[0]), "r"(a[1]), "r"(a[2]), "r"(a[3]), "r"(b[0]), "r"(b[1]));
}

// copy rows x 128B into SW128-swizzled smem tile (byte pitch)
__device__ __forceinline__ void cp_rows(uint32_t dst, const char* src, long pitchB, int rows) {
    for (int idx = threadIdx.x; idx < rows * 8; idx += blockDim.x) {
        const int r = idx >> 3, cg = idx & 7;
        cp16(dst + SWZ(r * 128 + cg * 16), src + (long)r * pitchB + cg * 16);
    }
}

// ========== single-fp16 core, CTA 128x128, warp 32x64 (8 warps) ==========
__device__ __forceinline__ void mma_chunk1(uint32_t sA, uint32_t sB,
                                           float (&acc)[2][8][4], int wm, int wn, int lane) {
    const int lr = lane & 15, lc = (lane >> 4) * 16;
    #pragma unroll
    for (int kk = 0; kk < 4; kk++) {
        const int kb = kk * 32;
        uint32_t a[2][4];
        #pragma unroll
        for (int mt = 0; mt < 2; mt++)
            ldm4(a[mt], sA + SWZ((wm * 32 + mt * 16 + lr) * 128 + kb + lc));
        #pragma unroll
        for (int np = 0; np < 4; np++) {
            uint32_t b4[4];
            ldm4(b4, sB + SWZ((wn * 64 + np * 16 + lr) * 128 + kb + lc));
            uint32_t b0[2] = {b4[0], b4[2]}, b1[2] = {b4[1], b4[3]};
            #pragma unroll
            for (int mt = 0; mt < 2; mt++) {
                mma16816h(acc[mt][np * 2],     a[mt], b0);
                mma16816h(acc[mt][np * 2 + 1], a[mt], b1);
            }
        }
    }
}
__device__ __forceinline__ void pipeline1(uint32_t sb, const char* A, const char* B,
                                          long pitchB, int nch,
                                          float (&acc)[2][8][4], int wm, int wn, int lane) {
    cp_rows(sb,         A, pitchB, 128);
    cp_rows(sb + 16384, B, pitchB, 128);
    asm volatile("cp.async.commit_group;" ::: "memory");
    for (int ch = 0; ch < nch; ch++) {
        const uint32_t stb = sb + (ch & 1) * 32768;
        if (ch + 1 < nch) {
            const uint32_t nstb = sb + ((ch + 1) & 1) * 32768;
            const long k0 = (long)(ch + 1) * 128;
            cp_rows(nstb,         A + k0, pitchB, 128);
            cp_rows(nstb + 16384, B + k0, pitchB, 128);
            asm volatile("cp.async.commit_group;" ::: "memory");
            asm volatile("cp.async.wait_group 1;" ::: "memory");
        } else {
            asm volatile("cp.async.wait_group 0;" ::: "memory");
        }
        __syncthreads();
        mma_chunk1(stb, stb + 16384, acc, wm, wn, lane);
        __syncthreads();
    }
}

// ---------- GroupNorm ----------
__global__ void __launch_bounds__(256) gn_kernel(const float* __restrict__ x,
                                                 const float* __restrict__ w,
                                                 const float* __restrict__ bias) {
    const int b = blockIdx.x >> 5, g = blockIdx.x & 31;
    const float* xp = x   + (b * CH + g * CPG) * NPIX;
    float*       hp = g_h + (b * CH + g * CPG) * NPIX;
    const int NE = CPG * NPIX;
    float s = 0.f, ss = 0.f;
    const float4* x4 = (const float4*)xp;
    for (int i = threadIdx.x; i < NE / 4; i += 256) {
        float4 v = x4[i];
        s  += v.x + v.y + v.z + v.w;
        ss += v.x * v.x + v.y * v.y + v.z * v.z + v.w * v.w;
    }
    __shared__ float rs[32], rss[32];
    #pragma unroll
    for (int o = 16; o; o >>= 1) {
        s  += __shfl_xor_sync(~0u, s,  o);
        ss += __shfl_xor_sync(~0u, ss, o);
    }
    const int lane = threadIdx.x & 31, wid = threadIdx.x >> 5;
    if (lane == 0) { rs[wid] = s; rss[wid] = ss; }
    __syncthreads();
    if (wid == 0) {
        s  = (lane < 8) ? rs[lane]  : 0.f;
        ss = (lane < 8) ? rss[lane] : 0.f;
        #pragma unroll
        for (int o = 16; o; o >>= 1) {
            s  += __shfl_xor_sync(~0u, s,  o);
            ss += __shfl_xor_sync(~0u, ss, o);
        }
        if (lane == 0) { rs[0] = s; rss[0] = ss; }
    }
    __syncthreads();
    const float mu   = rs[0] / (float)NE;
    const float rstd = rsqrtf(rss[0] / (float)NE - mu * mu + 1e-5f);
    float4* h4 = (float4*)hp;
    for (int i = threadIdx.x; i < NE / 4; i += 256) {
        const int c = g * CPG + (i >> 10);
        const float wc = w[c] * rstd, bc = bias[c] - mu * wc;
        float4 v = x4[i];
        v.x = v.x * wc + bc; v.y = v.y * wc + bc; v.z = v.z * wc + bc; v.w = v.w * wc + bc;
        h4[i] = v;
    }
}

// ---------- h: [c][n] fp32 -> [n][c] fp16 ----------
__global__ void __launch_bounds__(256) h_convert() {
    __shared__ float t[32][33];
    const int n0 = blockIdx.x * 32, c0 = blockIdx.y * 32, b = blockIdx.z;
    const float* src = g_h + ((size_t)b * CH + c0) * NPIX + n0;
    const int tx = threadIdx.x & 31, ty = threadIdx.x >> 5;
    #pragma unroll
    for (int j = 0; j < 4; j++)
        t[ty + 8 * j][tx] = src[(size_t)(ty + 8 * j) * NPIX + tx];
    __syncthreads();
    const size_t dbase = ((size_t)b * NPIX + n0) * CH + c0;
    #pragma unroll
    for (int j = 0; j < 4; j++)
        g_h16[dbase + (size_t)(ty + 8 * j) * CH + tx] = __float2half_rn(t[tx][ty + 8 * j]);
}

// ---------- weight -> fp16 ----------
__global__ void __launch_bounds__(256) w_convert(const float* __restrict__ qkv_w,
                                                 const float* __restrict__ proj_w) {
    const int f4 = blockIdx.x * 256 + threadIdx.x;
    const float* src;
    __half* d;
    size_t e;
    if (f4 < 49152) { src = qkv_w;  d = g_wq16; e = (size_t)f4 * 4; }
    else            { src = proj_w; d = g_wp16; e = (size_t)(f4 - 49152) * 4; }
    float4 v = *(const float4*)(src + e);
    __half2 h0, h1;
    h0.x = __float2half_rn(v.x); h0.y = __float2half_rn(v.y);
    h1.x = __float2half_rn(v.z); h1.y = __float2half_rn(v.w);
    *(__half2*)(d + e)     = h0;
    *(__half2*)(d + e + 2) = h1;
}

// ---------- QKV = W*H (single fp16; q,k -> [n][c], v -> [c][n]) ----------
__global__ void __launch_bounds__(256, 1) qkv_hmma(const float* __restrict__ qkv_b) {
    extern __shared__ char smem[];
    const uint32_t sb = smem_u32(smem);
    const int tid = threadIdx.x, lane = tid & 31, wid = tid >> 5;
    const int wm = wid & 3, wn = wid >> 2;
    const int b = blockIdx.z, n0 = blockIdx.x * 128, o0 = blockIdx.y * 128;

    const char* A = (const char*)(g_wq16 + (size_t)o0 * CH);
    const char* B = (const char*)(g_h16 + ((size_t)b * NPIX + n0) * CH);

    float acc[2][8][4] = {};
    pipeline1(sb, A, B, CH * 2, 4, acc, wm, wn, lane);

    const int r0 = wm * 32 + (lane >> 2), c0 = wn * 64 + (lane & 3) * 2;
    #pragma unroll
    for (int mt = 0; mt < 2; mt++) {
        const float b0 = qkv_b[o0 + r0 + mt * 16];
        const float b1 = qkv_b[o0 + r0 + mt * 16 + 8];
        #pragma unroll
        for (int nt = 0; nt < 8; nt++) {
            acc[mt][nt][0] += b0; acc[mt][nt][1] += b0;
            acc[mt][nt][2] += b1; acc[mt][nt][3] += b1;
        }
    }

    const int sel = blockIdx.y >> 1;   // 0=q, 1=k, 2=v
    if (sel == 2) {
        __half* vh = g_v16h + ((size_t)b * CH + (o0 - 512)) * NPIX + n0;
        #pragma unroll
        for (int mt = 0; mt < 2; mt++)
            #pragma unroll
            for (int nt = 0; nt < 8; nt++) {
                const int rr = r0 + mt * 16, cc = c0 + nt * 8;
                __half2 h0, h1;
                h0.x = __float2half_rn(acc[mt][nt][0]); h0.y = __float2half_rn(acc[mt][nt][1]);
                h1.x = __float2half_rn(acc[mt][nt][2]); h1.y = __float2half_rn(acc[mt][nt][3]);
                *(__half2*)(vh + (size_t)rr * NPIX + cc)       = h0;
                *(__half2*)(vh + (size_t)(rr + 8) * NPIX + cc) = h1;
            }
    } else {
        float* st = (float*)smem;   // [c 128][n 132]
        __syncthreads();
        #pragma unroll
        for (int mt = 0; mt < 2; mt++)
            #pragma unroll
            for (int nt = 0; nt < 8; nt++) {
                const int rr = r0 + mt * 16, cc = c0 + nt * 8;
                st[(cc)     * 132 + rr]     = acc[mt][nt][0];
                st[(cc + 1) * 132 + rr]     = acc[mt][nt][1];
                st[(cc)     * 132 + rr + 8] = acc[mt][nt][2];
                st[(cc + 1) * 132 + rr + 8] = acc[mt][nt][3];
            }
        __syncthreads();
        __half* dq = (sel ? g_k16 : g_q16) + ((size_t)b * NPIX + n0) * CH + (o0 - sel * 256);
        const int o4 = lane * 4, nb = tid >> 5;
        #pragma unroll
        for (int j = 0; j < 16; j++) {
            const int n = nb + 8 * j;
            float4 v = *(float4*)(st + n * 132 + o4);
            __half2 h0, h1;
            h0.x = __float2half_rn(v.x); h0.y = __float2half_rn(v.y);
            h1.x = __float2half_rn(v.z); h1.y = __float2half_rn(v.w);
            *(__half2*)(dq + (size_t)n * CH + o4)     = h0;
            *(__half2*)(dq + (size_t)n * CH + o4 + 2) = h1;
        }
    }
}

// ---------- S = Q K^T (256 threads, CTA 256x128, warp 64x64, fp16) ----------
// stage: A 32K @0 | B 16K @32768 = 48K; x2 = 96K
__global__ void __launch_bounds__(256, 1) s_gemm_kernel() {
    extern __shared__ char smem[];
    const uint32_t sb = smem_u32(smem);
    const int tid = threadIdx.x, lane = tid & 31, wid = tid >> 5;
    const int wm = wid & 3, wn = wid >> 2;   // 4 x 2 warps
    const int b = blockIdx.z, i0 = blockIdx.y * 256, j0 = blockIdx.x * 128;

    const char* Aq = (const char*)(g_q16 + ((size_t)b * NPIX + i0) * CH);
    const char* Bk = (const char*)(g_k16 + ((size_t)b * NPIX + j0) * CH);
    const long pB = CH * 2;

    float acc[4][8][4] = {};
    const int lr = lane & 15, lc = (lane >> 4) * 16;

    cp_rows(sb,         Aq, pB, 256);
    cp_rows(sb + 32768, Bk, pB, 128);
    asm volatile("cp.async.commit_group;" ::: "memory");

    for (int ch = 0; ch < 4; ch++) {
        const uint32_t stb = sb + (ch & 1) * 49152;
        if (ch + 1 < 4) {
            const uint32_t nstb = sb + ((ch + 1) & 1) * 49152;
            const long k0 = (long)(ch + 1) * 128;
            cp_rows(nstb,         Aq + k0, pB, 256);
            cp_rows(nstb + 32768, Bk + k0, pB, 128);
            asm volatile("cp.async.commit_group;" ::: "memory");
            asm volatile("cp.async.wait_group 1;" ::: "memory");
        } else {
            asm volatile("cp.async.wait_group 0;" ::: "memory");
        }
        __syncthreads();
        #pragma unroll
        for (int kk = 0; kk < 4; kk++) {
            const int kb = kk * 32;
            uint32_t a[4][4];
            #pragma unroll
            for (int mt = 0; mt < 4; mt++)
                ldm4(a[mt], stb + SWZ((wm * 64 + mt * 16 + lr) * 128 + kb + lc));
            #pragma unroll
            for (int np = 0; np < 4; np++) {
                uint32_t b4[4];
                ldm4(b4, stb + 32768 + SWZ((wn * 64 + np * 16 + lr) * 128 + kb + lc));
                uint32_t b0[2] = {b4[0], b4[2]}, b1[2] = {b4[1], b4[3]};
                #pragma unroll
                for (int mt = 0; mt < 4; mt++) {
                    mma16816h(acc[mt][np * 2],     a[mt], b0);
                    mma16816h(acc[mt][np * 2 + 1], a[mt], b1);
                }
            }
        }
        __syncthreads();
    }

    __half* Sb = g_S + ((size_t)b * NPIX + i0) * NPIX + j0;
    const int r0 = wm * 64 + (lane >> 2), c0 = wn * 64 + (lane & 3) * 2;
    #pragma unroll
    for (int mt = 0; mt < 4; mt++)
        #pragma unroll
        for (int nt = 0; nt < 8; nt++) {
            __half* p = Sb + (size_t)(r0 + mt * 16) * NPIX + c0 + nt * 8;
            __half2 h0, h1;
            h0.x = __float2half_rn(acc[mt][nt][0]); h0.y = __float2half_rn(acc[mt][nt][1]);
            h1.x = __float2half_rn(acc[mt][nt][2]); h1.y = __float2half_rn(acc[mt][nt][3]);
            *(__half2*)p = h0;
            *(__half2*)(p + (size_t)8 * NPIX) = h1;
        }
}

// ---------- softmax rows (fp16 S) -> P fp16 ----------
__global__ void __launch_bounds__(256) softmax_kernel() {
    const size_t row = blockIdx.x;
    const uint4* s8 = (const uint4*)(g_S + row * NPIX);
    const int tid = threadIdx.x, lane = tid & 31, wid = tid >> 5;
    __shared__ float rmax[8], rsum[8];

    uint4 raw[2];
    raw[0] = s8[tid];
    raw[1] = s8[tid + 256];
    float v[16];
    #pragma unroll
    for (int k = 0; k < 2; k++) {
        const __half2* hp = (const __half2*)&raw[k];
        #pragma unroll
        for (int j = 0; j < 4; j++) {
            float2 f = __half22float2(hp[j]);
            v[k * 8 + 2 * j]     = f.x * SCALE;
            v[k * 8 + 2 * j + 1] = f.y * SCALE;
        }
    }
    float mx = v[0];
    #pragma unroll
    for (int i = 1; i < 16; i++) mx = fmaxf(mx, v[i]);
    #pragma unroll
    for (int o = 16; o; o >>= 1) mx = fmaxf(mx, __shfl_xor_sync(~0u, mx, o));
    if (lane == 0) rmax[wid] = mx;
    __syncthreads();
    mx = rmax[0];
    #pragma unroll
    for (int i = 1; i < 8; i++) mx = fmaxf(mx, rmax[i]);
    float sum = 0.f;
    #pragma unroll
    for (int i = 0; i < 16; i++) {
        v[i] = __expf(v[i] - mx);
        sum += v[i];
    }
    #pragma unroll
    for (int o = 16; o; o >>= 1) sum += __shfl_xor_sync(~0u, sum, o);
    if (lane == 0) rsum[wid] = sum;
    __syncthreads();
    sum = rsum[0]+rsum[1]+rsum[2]+rsum[3]+rsum[4]+rsum[5]+rsum[6]+rsum[7];
    const float inv = 1.f / sum;

    uint4* ph = (uint4*)(g_p + row * NPIX);
    #pragma unroll
    for (int k = 0; k < 2; k++) {
        uint4 o;
        __half2* op = (__half2*)&o;
        #pragma unroll
        for (int j = 0; j < 4; j++) {
            op[j].x = __float2half_rn(v[k * 8 + 2 * j]     * inv);
            op[j].y = __float2half_rn(v[k * 8 + 2 * j + 1] * inv);
        }
        ph[tid + 256 * k] = o;
    }
}

// ---------- O = P V (256 threads, CTA 128x256, warp 64x64, fp16) ----------
// stage: P 16K @0 | Vh 32K @16384 = 48K; x2 = 96K
__global__ void __launch_bounds__(256, 1) pv_gemm_kernel() {
    extern __shared__ char smem[];
    const uint32_t sb = smem_u32(smem);
    const int tid = threadIdx.x, lane = tid & 31, wid = tid >> 5;
    const int wm = wid & 1, wn = wid >> 1;   // 2 x 4 warps
    const int b = blockIdx.x & 3, i0 = (blockIdx.x >> 2) * 128;

    const char* Ap = (const char*)(g_p + ((size_t)b * NPIX + i0) * NPIX);
    const char* Bh = (const char*)(g_v16h + (size_t)b * CH * NPIX);
    const long pB = NPIX * 2;

    float acc[4][8][4] = {};
    const int lr = lane & 15, lc = (lane >> 4) * 16;

    cp_rows(sb,         Ap, pB, 128);
    cp_rows(sb + 16384, Bh, pB, 256);
    asm volatile("cp.async.commit_group;" ::: "memory");

    for (int ch = 0; ch < 64; ch++) {
        const uint32_t stb = sb + (ch & 1) * 49152;
        if (ch + 1 < 64) {
            const uint32_t nstb = sb + ((ch + 1) & 1) * 49152;
            const long k0 = (long)(ch + 1) * 128;
            cp_rows(nstb,         Ap + k0, pB, 128);
            cp_rows(nstb + 16384, Bh + k0, pB, 256);
            asm volatile("cp.async.commit_group;" ::: "memory");
            asm volatile("cp.async.wait_group 1;" ::: "memory");
        } else {
            asm volatile("cp.async.wait_group 0;" ::: "memory");
        }
        __syncthreads();
        #pragma unroll
        for (int kk = 0; kk < 4; kk++) {
            const int kb = kk * 32;
            uint32_t a[4][4];
            #pragma unroll
            for (int mt = 0; mt < 4; mt++)
                ldm4(a[mt], stb + SWZ((wm * 64 + mt * 16 + lr) * 128 + kb + lc));
            #pragma unroll
            for (int np = 0; np < 4; np++) {
                uint32_t b4[4];
                ldm4(b4, stb + 16384 + SWZ((wn * 64 + np * 16 + lr) * 128 + kb + lc));
                uint32_t b0[2] = {b4[0], b4[2]}, b1[2] = {b4[1], b4[3]};
                #pragma unroll
                for (int mt = 0; mt < 4; mt++) {
                    mma16816h(acc[mt][np * 2],     a[mt], b0);
                    mma16816h(acc[mt][np * 2 + 1], a[mt], b1);
                }
            }
        }
        __syncthreads();
    }

    __half* o16 = g_o16 + ((size_t)b * NPIX + i0) * CH;
    const int r0 = wm * 64 + (lane >> 2), c0 = wn * 64 + (lane & 3) * 2;
    #pragma unroll
    for (int mt = 0; mt < 4; mt++)
        #pragma unroll
        for (int nt = 0; nt < 8; nt++) {
            const int rr = r0 + mt * 16, cc = c0 + nt * 8;
            __half2 h0, h1;
            h0.x = __float2half_rn(acc[mt][nt][0]); h0.y = __float2half_rn(acc[mt][nt][1]);
            h1.x = __float2half_rn(acc[mt][nt][2]); h1.y = __float2half_rn(acc[mt][nt][3]);
            *(__half2*)(o16 + (size_t)rr * CH + cc)       = h0;
            *(__half2*)(o16 + (size_t)(rr + 8) * CH + cc) = h1;
        }
}

// ---------- out = proj_w * O + proj_b + x (single fp16) ----------
__global__ void __launch_bounds__(256, 1) proj_hmma(const float* __restrict__ proj_b,
                                                    const float* __restrict__ x,
                                                    float* __restrict__ out) {
    extern __shared__ char smem[];
    const uint32_t sb = smem_u32(smem);
    const int tid = threadIdx.x, lane = tid & 31, wid = tid >> 5;
    const int wm = wid & 3, wn = wid >> 2;
    const int b = blockIdx.z, n0 = blockIdx.x * 128, o0 = blockIdx.y * 128;

    const char* A = (const char*)(g_wp16 + (size_t)o0 * CH);
    const char* B = (const char*)(g_o16 + ((size_t)b * NPIX + n0) * CH);

    float acc[2][8][4] = {};
    pipeline1(sb, A, B, CH * 2, 4, acc, wm, wn, lane);

    const int r0 = wm * 32 + (lane >> 2), c0 = wn * 64 + (lane & 3) * 2;
    #pragma unroll
    for (int mt = 0; mt < 2; mt++) {
        const int r  = o0 + r0 + mt * 16;
        const float b0 = proj_b[r], b1 = proj_b[r + 8];
        #pragma unroll
        for (int nt = 0; nt < 8; nt++) {
            const size_t idx0 = ((size_t)b * CH + r) * NPIX + n0 + c0 + nt * 8;
            const size_t idx1 = idx0 + (size_t)8 * NPIX;
            float2 x0 = *(const float2*)(x + idx0);
            float2 x1 = *(const float2*)(x + idx1);
            *(float2*)(out + idx0) = make_float2(acc[mt][nt][0] + b0 + x0.x,
                                                 acc[mt][nt][1] + b0 + x0.y);
            *(float2*)(out + idx1) = make_float2(acc[mt][nt][2] + b1 + x1.x,
                                                 acc[mt][nt][3] + b1 + x1.y);
        }
    }
}

// ---------- launch ----------
extern "C" void kernel_launch(void* const* d_in, const int* in_sizes, int n_in,
                              void* d_out, int out_size) {
    const float* x      = (const float*)d_in[0];
    const float* gn_w   = (const float*)d_in[1];
    const float* gn_b   = (const float*)d_in[2];
    const float* qkv_w  = (const float*)d_in[3];
    const float* qkv_b  = (const float*)d_in[4];
    const float* proj_w = (const float*)d_in[5];
    const float* proj_b = (const float*)d_in[6];
    float* out = (float*)d_out;

    cudaFuncSetAttribute(qkv_hmma,      cudaFuncAttributeMaxDynamicSharedMemorySize, 69632);
    cudaFuncSetAttribute(proj_hmma,     cudaFuncAttributeMaxDynamicSharedMemorySize, 65536);
    cudaFuncSetAttribute(s_gemm_kernel, cudaFuncAttributeMaxDynamicSharedMemorySize, 98304);
    cudaFuncSetAttribute(pv_gemm_kernel,cudaFuncAttributeMaxDynamicSharedMemorySize, 98304);

    w_convert<<<256, 256>>>(qkv_w, proj_w);
    gn_kernel<<<BATCH * 32, 256>>>(x, gn_w, gn_b);
    {
        dim3 g(NPIX / 32, CH / 32, BATCH);
        h_convert<<<g, 256>>>();
    }
    {
        dim3 g(NPIX / 128, 6, BATCH);
        qkv_hmma<<<g, 256, 69632>>>(qkv_b);
    }
    {
        dim3 g(NPIX / 128, NPIX / 256, BATCH);
        s_gemm_kernel<<<g, 256, 98304>>>();
    }
    softmax_kernel<<<BATCH * NPIX, 256>>>();
    pv_gemm_kernel<<<(NPIX / 128) * BATCH, 256, 98304>>>();
    {
        dim3 g(NPIX / 128, 2, BATCH);
        proj_hmma<<<g, 256, 65536>>>(proj_b, x, out);
    }
}

// round 12
// speedup vs baseline: 2.0687x; 1.0616x over previous
#include <cuda_runtime.h>
#include <cuda_fp16.h>
#include <math.h>
#include <stdint.h>

#define BATCH 4
#define CH    256
#define NPIX  4096
#define CPG   8
#define SCALE 0.0625f

__device__ float g_h [BATCH * CH * NPIX];
__device__ __half g_h16[(size_t)BATCH * NPIX * CH];
__device__ __half g_wq16[3 * CH * CH];
__device__ __half g_wp16[CH * CH];
__device__ __half g_q16[(size_t)BATCH * NPIX * CH];
__device__ __half g_k16[(size_t)BATCH * NPIX * CH];
__device__ __half g_v16h[(size_t)BATCH * CH * NPIX];
__device__ __half g_p [(size_t)BATCH * NPIX * NPIX];
__device__ float g_l [BATCH * NPIX];
__device__ __half g_o16[(size_t)BATCH * NPIX * CH];

#define SWZ(o) ((o) ^ (((o) >> 3) & 0x70))

__device__ __forceinline__ uint32_t smem_u32(const void* p) {
    uint32_t a;
    asm("{ .reg .u64 t; cvta.to.shared.u64 t, %1; cvt.u32.u64 %0, t; }" : "=r"(a) : "l"(p));
    return a;
}
__device__ __forceinline__ void cp16(uint32_t dst, const void* src) {
    asm volatile("cp.async.cg.shared.global [%0], [%1], 16;" :: "r"(dst), "l"(src) : "memory");
}
__device__ __forceinline__ void ldm4(uint32_t* r, uint32_t addr) {
    asm volatile("ldmatrix.sync.aligned.m8n8.x4.shared.b16 {%0,%1,%2,%3}, [%4];"
                 : "=r"(r[0]), "=r"(r[1]), "=r"(r[2]), "=r"(r[3]) : "r"(addr));
}
__device__ __forceinline__ void mma16816h(float* c, const uint32_t* a, const uint32_t* b) {
    asm volatile("mma.sync.aligned.m16n8k16.row.col.f32.f16.f16.f32 "
                 "{%0,%1,%2,%3}, {%4,%5,%6,%7}, {%8,%9}, {%0,%1,%2,%3};"
                 : "+f"(c[0]), "+f"(c[1]), "+f"(c[2]), "+f"(c[3])
                 : "r"(a[0]), "r"(a[1]), "r"(a[2]), "r"(a[3]), "r"(b[0]), "r"(b[1]));
}

// copy rows x 128B into SW128-swizzled smem tile (byte pitch)
__device__ __forceinline__ void cp_rows(uint32_t dst, const char* src, long pitchB, int rows) {
    for (int idx = threadIdx.x; idx < rows * 8; idx += blockDim.x) {
        const int r = idx >> 3, cg = idx & 7;
        cp16(dst + SWZ(r * 128 + cg * 16), src + (long)r * pitchB + cg * 16);
    }
}

// ========== single-fp16 core, CTA 128x128, warp 32x64 (8 warps) ==========
__device__ __forceinline__ void mma_chunk1(uint32_t sA, uint32_t sB,
                                           float (&acc)[2][8][4], int wm, int wn, int lane) {
    const int lr = lane & 15, lc = (lane >> 4) * 16;
    #pragma unroll
    for (int kk = 0; kk < 4; kk++) {
        const int kb = kk * 32;
        uint32_t a[2][4];
        #pragma unroll
        for (int mt = 0; mt < 2; mt++)
            ldm4(a[mt], sA + SWZ((wm * 32 + mt * 16 + lr) * 128 + kb + lc));
        #pragma unroll
        for (int np = 0; np < 4; np++) {
            uint32_t b4[4];
            ldm4(b4, sB + SWZ((wn * 64 + np * 16 + lr) * 128 + kb + lc));
            uint32_t b0[2] = {b4[0], b4[2]}, b1[2] = {b4[1], b4[3]};
            #pragma unroll
            for (int mt = 0; mt < 2; mt++) {
                mma16816h(acc[mt][np * 2],     a[mt], b0);
                mma16816h(acc[mt][np * 2 + 1], a[mt], b1);
            }
        }
    }
}
__device__ __forceinline__ void pipeline1(uint32_t sb, const char* A, const char* B,
                                          long pitchB, int nch,
                                          float (&acc)[2][8][4], int wm, int wn, int lane) {
    cp_rows(sb,         A, pitchB, 128);
    cp_rows(sb + 16384, B, pitchB, 128);
    asm volatile("cp.async.commit_group;" ::: "memory");
    for (int ch = 0; ch < nch; ch++) {
        const uint32_t stb = sb + (ch & 1) * 32768;
        if (ch + 1 < nch) {
            const uint32_t nstb = sb + ((ch + 1) & 1) * 32768;
            const long k0 = (long)(ch + 1) * 128;
            cp_rows(nstb,         A + k0, pitchB, 128);
            cp_rows(nstb + 16384, B + k0, pitchB, 128);
            asm volatile("cp.async.commit_group;" ::: "memory");
            asm volatile("cp.async.wait_group 1;" ::: "memory");
        } else {
            asm volatile("cp.async.wait_group 0;" ::: "memory");
        }
        __syncthreads();
        mma_chunk1(stb, stb + 16384, acc, wm, wn, lane);
        __syncthreads();
    }
}

// ---------- zero row sums ----------
__global__ void __launch_bounds__(256) zero_l() {
    g_l[blockIdx.x * 256 + threadIdx.x] = 0.f;
}

// ---------- GroupNorm ----------
__global__ void __launch_bounds__(256) gn_kernel(const float* __restrict__ x,
                                                 const float* __restrict__ w,
                                                 const float* __restrict__ bias) {
    const int b = blockIdx.x >> 5, g = blockIdx.x & 31;
    const float* xp = x   + (b * CH + g * CPG) * NPIX;
    float*       hp = g_h + (b * CH + g * CPG) * NPIX;
    const int NE = CPG * NPIX;
    float s = 0.f, ss = 0.f;
    const float4* x4 = (const float4*)xp;
    for (int i = threadIdx.x; i < NE / 4; i += 256) {
        float4 v = x4[i];
        s  += v.x + v.y + v.z + v.w;
        ss += v.x * v.x + v.y * v.y + v.z * v.z + v.w * v.w;
    }
    __shared__ float rs[32], rss[32];
    #pragma unroll
    for (int o = 16; o; o >>= 1) {
        s  += __shfl_xor_sync(~0u, s,  o);
        ss += __shfl_xor_sync(~0u, ss, o);
    }
    const int lane = threadIdx.x & 31, wid = threadIdx.x >> 5;
    if (lane == 0) { rs[wid] = s; rss[wid] = ss; }
    __syncthreads();
    if (wid == 0) {
        s  = (lane < 8) ? rs[lane]  : 0.f;
        ss = (lane < 8) ? rss[lane] : 0.f;
        #pragma unroll
        for (int o = 16; o; o >>= 1) {
            s  += __shfl_xor_sync(~0u, s,  o);
            ss += __shfl_xor_sync(~0u, ss, o);
        }
        if (lane == 0) { rs[0] = s; rss[0] = ss; }
    }
    __syncthreads();
    const float mu   = rs[0] / (float)NE;
    const float rstd = rsqrtf(rss[0] / (float)NE - mu * mu + 1e-5f);
    float4* h4 = (float4*)hp;
    for (int i = threadIdx.x; i < NE / 4; i += 256) {
        const int c = g * CPG + (i >> 10);
        const float wc = w[c] * rstd, bc = bias[c] - mu * wc;
        float4 v = x4[i];
        v.x = v.x * wc + bc; v.y = v.y * wc + bc; v.z = v.z * wc + bc; v.w = v.w * wc + bc;
        h4[i] = v;
    }
}

// ---------- h: [c][n] fp32 -> [n][c] fp16 ----------
__global__ void __launch_bounds__(256) h_convert() {
    __shared__ float t[32][33];
    const int n0 = blockIdx.x * 32, c0 = blockIdx.y * 32, b = blockIdx.z;
    const float* src = g_h + ((size_t)b * CH + c0) * NPIX + n0;
    const int tx = threadIdx.x & 31, ty = threadIdx.x >> 5;
    #pragma unroll
    for (int j = 0; j < 4; j++)
        t[ty + 8 * j][tx] = src[(size_t)(ty + 8 * j) * NPIX + tx];
    __syncthreads();
    const size_t dbase = ((size_t)b * NPIX + n0) * CH + c0;
    #pragma unroll
    for (int j = 0; j < 4; j++)
        g_h16[dbase + (size_t)(ty + 8 * j) * CH + tx] = __float2half_rn(t[tx][ty + 8 * j]);
}

// ---------- weight -> fp16 ----------
__global__ void __launch_bounds__(256) w_convert(const float* __restrict__ qkv_w,
                                                 const float* __restrict__ proj_w) {
    const int f4 = blockIdx.x * 256 + threadIdx.x;
    const float* src;
    __half* d;
    size_t e;
    if (f4 < 49152) { src = qkv_w;  d = g_wq16; e = (size_t)f4 * 4; }
    else            { src = proj_w; d = g_wp16; e = (size_t)(f4 - 49152) * 4; }
    float4 v = *(const float4*)(src + e);
    __half2 h0, h1;
    h0.x = __float2half_rn(v.x); h0.y = __float2half_rn(v.y);
    h1.x = __float2half_rn(v.z); h1.y = __float2half_rn(v.w);
    *(__half2*)(d + e)     = h0;
    *(__half2*)(d + e + 2) = h1;
}

// ---------- QKV = W*H (single fp16; q (pre-scaled),k -> [n][c], v -> [c][n]) ----------
__global__ void __launch_bounds__(256, 1) qkv_hmma(const float* __restrict__ qkv_b) {
    extern __shared__ char smem[];
    const uint32_t sb = smem_u32(smem);
    const int tid = threadIdx.x, lane = tid & 31, wid = tid >> 5;
    const int wm = wid & 3, wn = wid >> 2;
    const int b = blockIdx.z, n0 = blockIdx.x * 128, o0 = blockIdx.y * 128;

    const char* A = (const char*)(g_wq16 + (size_t)o0 * CH);
    const char* B = (const char*)(g_h16 + ((size_t)b * NPIX + n0) * CH);

    float acc[2][8][4] = {};
    pipeline1(sb, A, B, CH * 2, 4, acc, wm, wn, lane);

    const int r0 = wm * 32 + (lane >> 2), c0 = wn * 64 + (lane & 3) * 2;
    #pragma unroll
    for (int mt = 0; mt < 2; mt++) {
        const float b0 = qkv_b[o0 + r0 + mt * 16];
        const float b1 = qkv_b[o0 + r0 + mt * 16 + 8];
        #pragma unroll
        for (int nt = 0; nt < 8; nt++) {
            acc[mt][nt][0] += b0; acc[mt][nt][1] += b0;
            acc[mt][nt][2] += b1; acc[mt][nt][3] += b1;
        }
    }

    const int sel = blockIdx.y >> 1;   // 0=q, 1=k, 2=v
    if (sel == 2) {
        __half* vh = g_v16h + ((size_t)b * CH + (o0 - 512)) * NPIX + n0;
        #pragma unroll
        for (int mt = 0; mt < 2; mt++)
            #pragma unroll
            for (int nt = 0; nt < 8; nt++) {
                const int rr = r0 + mt * 16, cc = c0 + nt * 8;
                __half2 h0, h1;
                h0.x = __float2half_rn(acc[mt][nt][0]); h0.y = __float2half_rn(acc[mt][nt][1]);
                h1.x = __float2half_rn(acc[mt][nt][2]); h1.y = __float2half_rn(acc[mt][nt][3]);
                *(__half2*)(vh + (size_t)rr * NPIX + cc)       = h0;
                *(__half2*)(vh + (size_t)(rr + 8) * NPIX + cc) = h1;
            }
    } else {
        const float sc = sel ? 1.f : SCALE;   // fold C^-0.5 into q
        float* st = (float*)smem;   // [c 128][n 132]
        __syncthreads();
        #pragma unroll
        for (int mt = 0; mt < 2; mt++)
            #pragma unroll
            for (int nt = 0; nt < 8; nt++) {
                const int rr = r0 + mt * 16, cc = c0 + nt * 8;
                st[(cc)     * 132 + rr]     = acc[mt][nt][0];
                st[(cc + 1) * 132 + rr]     = acc[mt][nt][1];
                st[(cc)     * 132 + rr + 8] = acc[mt][nt][2];
                st[(cc + 1) * 132 + rr + 8] = acc[mt][nt][3];
            }
        __syncthreads();
        __half* dq = (sel ? g_k16 : g_q16) + ((size_t)b * NPIX + n0) * CH + (o0 - sel * 256);
        const int o4 = lane * 4, nb = tid >> 5;
        #pragma unroll
        for (int j = 0; j < 16; j++) {
            const int n = nb + 8 * j;
            float4 v = *(float4*)(st + n * 132 + o4);
            __half2 h0, h1;
            h0.x = __float2half_rn(v.x * sc); h0.y = __float2half_rn(v.y * sc);
            h1.x = __float2half_rn(v.z * sc); h1.y = __float2half_rn(v.w * sc);
            *(__half2*)(dq + (size_t)n * CH + o4)     = h0;
            *(__half2*)(dq + (size_t)n * CH + o4 + 2) = h1;
        }
    }
}

// ---------- P = exp(Q K^T) unnormalized + row-sum atomics ----------
// (256 threads, CTA 256x128, warp 64x64, fp16)
__global__ void __launch_bounds__(256, 1) s_gemm_kernel() {
    extern __shared__ char smem[];
    const uint32_t sb = smem_u32(smem);
    const int tid = threadIdx.x, lane = tid & 31, wid = tid >> 5;
    const int wm = wid & 3, wn = wid >> 2;   // 4 x 2 warps
    const int b = blockIdx.z, i0 = blockIdx.y * 256, j0 = blockIdx.x * 128;

    const char* Aq = (const char*)(g_q16 + ((size_t)b * NPIX + i0) * CH);
    const char* Bk = (const char*)(g_k16 + ((size_t)b * NPIX + j0) * CH);
    const long pB = CH * 2;

    float acc[4][8][4] = {};
    const int lr = lane & 15, lc = (lane >> 4) * 16;

    cp_rows(sb,         Aq, pB, 256);
    cp_rows(sb + 32768, Bk, pB, 128);
    asm volatile("cp.async.commit_group;" ::: "memory");

    for (int ch = 0; ch < 4; ch++) {
        const uint32_t stb = sb + (ch & 1) * 49152;
        if (ch + 1 < 4) {
            const uint32_t nstb = sb + ((ch + 1) & 1) * 49152;
            const long k0 = (long)(ch + 1) * 128;
            cp_rows(nstb,         Aq + k0, pB, 256);
            cp_rows(nstb + 32768, Bk + k0, pB, 128);
            asm volatile("cp.async.commit_group;" ::: "memory");
            asm volatile("cp.async.wait_group 1;" ::: "memory");
        } else {
            asm volatile("cp.async.wait_group 0;" ::: "memory");
        }
        __syncthreads();
        #pragma unroll
        for (int kk = 0; kk < 4; kk++) {
            const int kb = kk * 32;
            uint32_t a[4][4];
            #pragma unroll
            for (int mt = 0; mt < 4; mt++)
                ldm4(a[mt], stb + SWZ((wm * 64 + mt * 16 + lr) * 128 + kb + lc));
            #pragma unroll
            for (int np = 0; np < 4; np++) {
                uint32_t b4[4];
                ldm4(b4, stb + 32768 + SWZ((wn * 64 + np * 16 + lr) * 128 + kb + lc));
                uint32_t b0[2] = {b4[0], b4[2]}, b1[2] = {b4[1], b4[3]};
                #pragma unroll
                for (int mt = 0; mt < 4; mt++) {
                    mma16816h(acc[mt][np * 2],     a[mt], b0);
                    mma16816h(acc[mt][np * 2 + 1], a[mt], b1);
                }
            }
        }
        __syncthreads();
    }

    // epilogue: exponentiate, store P fp16, accumulate row sums
    __half* Pb = g_p + ((size_t)b * NPIX + i0) * NPIX + j0;
    float* lrow = g_l + (size_t)b * NPIX + i0;
    const int r0 = wm * 64 + (lane >> 2), c0 = wn * 64 + (lane & 3) * 2;
    #pragma unroll
    for (int mt = 0; mt < 4; mt++) {
        float rs0 = 0.f, rs1 = 0.f;
        #pragma unroll
        for (int nt = 0; nt < 8; nt++) {
            float e0 = __expf(acc[mt][nt][0]);
            float e1 = __expf(acc[mt][nt][1]);
            float e2 = __expf(acc[mt][nt][2]);
            float e3 = __expf(acc[mt][nt][3]);
            rs0 += e0 + e1;
            rs1 += e2 + e3;
            __half* p = Pb + (size_t)(r0 + mt * 16) * NPIX + c0 + nt * 8;
            __half2 h0, h1;
            h0.x = __float2half_rn(e0); h0.y = __float2half_rn(e1);
            h1.x = __float2half_rn(e2); h1.y = __float2half_rn(e3);
            *(__half2*)p = h0;
            *(__half2*)(p + (size_t)8 * NPIX) = h1;
        }
        rs0 += __shfl_xor_sync(~0u, rs0, 1);
        rs0 += __shfl_xor_sync(~0u, rs0, 2);
        rs1 += __shfl_xor_sync(~0u, rs1, 1);
        rs1 += __shfl_xor_sync(~0u, rs1, 2);
        if ((lane & 3) == 0) {
            atomicAdd(lrow + r0 + mt * 16,     rs0);
            atomicAdd(lrow + r0 + mt * 16 + 8, rs1);
        }
    }
}

// ---------- O = P V then normalize by row sums (256 threads, CTA 128x256, warp 64x64) ----------
// stage: P 16K @0 | Vh 32K @16384 = 48K; x2 = 96K
__global__ void __launch_bounds__(256, 1) pv_gemm_kernel() {
    extern __shared__ char smem[];
    const uint32_t sb = smem_u32(smem);
    const int tid = threadIdx.x, lane = tid & 31, wid = tid >> 5;
    const int wm = wid & 1, wn = wid >> 1;   // 2 x 4 warps
    const int b = blockIdx.x & 3, i0 = (blockIdx.x >> 2) * 128;

    const char* Ap = (const char*)(g_p + ((size_t)b * NPIX + i0) * NPIX);
    const char* Bh = (const char*)(g_v16h + (size_t)b * CH * NPIX);
    const long pB = NPIX * 2;

    float acc[4][8][4] = {};
    const int lr = lane & 15, lc = (lane >> 4) * 16;

    cp_rows(sb,         Ap, pB, 128);
    cp_rows(sb + 16384, Bh, pB, 256);
    asm volatile("cp.async.commit_group;" ::: "memory");

    for (int ch = 0; ch < 64; ch++) {
        const uint32_t stb = sb + (ch & 1) * 49152;
        if (ch + 1 < 64) {
            const uint32_t nstb = sb + ((ch + 1) & 1) * 49152;
            const long k0 = (long)(ch + 1) * 128;
            cp_rows(nstb,         Ap + k0, pB, 128);
            cp_rows(nstb + 16384, Bh + k0, pB, 256);
            asm volatile("cp.async.commit_group;" ::: "memory");
            asm volatile("cp.async.wait_group 1;" ::: "memory");
        } else {
            asm volatile("cp.async.wait_group 0;" ::: "memory");
        }
        __syncthreads();
        #pragma unroll
        for (int kk = 0; kk < 4; kk++) {
            const int kb = kk * 32;
            uint32_t a[4][4];
            #pragma unroll
            for (int mt = 0; mt < 4; mt++)
                ldm4(a[mt], stb + SWZ((wm * 64 + mt * 16 + lr) * 128 + kb + lc));
            #pragma unroll
            for (int np = 0; np < 4; np++) {
                uint32_t b4[4];
                ldm4(b4, stb + 16384 + SWZ((wn * 64 + np * 16 + lr) * 128 + kb + lc));
                uint32_t b0[2] = {b4[0], b4[2]}, b1[2] = {b4[1], b4[3]};
                #pragma unroll
                for (int mt = 0; mt < 4; mt++) {
                    mma16816h(acc[mt][np * 2],     a[mt], b0);
                    mma16816h(acc[mt][np * 2 + 1], a[mt], b1);
                }
            }
        }
        __syncthreads();
    }

    __half* o16 = g_o16 + ((size_t)b * NPIX + i0) * CH;
    const float* lrow = g_l + (size_t)b * NPIX + i0;
    const int r0 = wm * 64 + (lane >> 2), c0 = wn * 64 + (lane & 3) * 2;
    #pragma unroll
    for (int mt = 0; mt < 4; mt++) {
        const float inv0 = 1.f / lrow[r0 + mt * 16];
        const float inv1 = 1.f / lrow[r0 + mt * 16 + 8];
        #pragma unroll
        for (int nt = 0; nt < 8; nt++) {
            const int rr = r0 + mt * 16, cc = c0 + nt * 8;
            __half2 h0, h1;
            h0.x = __float2half_rn(acc[mt][nt][0] * inv0);
            h0.y = __float2half_rn(acc[mt][nt][1] * inv0);
            h1.x = __float2half_rn(acc[mt][nt][2] * inv1);
            h1.y = __float2half_rn(acc[mt][nt][3] * inv1);
            *(__half2*)(o16 + (size_t)rr * CH + cc)       = h0;
            *(__half2*)(o16 + (size_t)(rr + 8) * CH + cc) = h1;
        }
    }
}

// ---------- out = proj_w * O + proj_b + x (single fp16) ----------
__global__ void __launch_bounds__(256, 1) proj_hmma(const float* __restrict__ proj_b,
                                                    const float* __restrict__ x,
                                                    float* __restrict__ out) {
    extern __shared__ char smem[];
    const uint32_t sb = smem_u32(smem);
    const int tid = threadIdx.x, lane = tid & 31, wid = tid >> 5;
    const int wm = wid & 3, wn = wid >> 2;
    const int b = blockIdx.z, n0 = blockIdx.x * 128, o0 = blockIdx.y * 128;

    const char* A = (const char*)(g_wp16 + (size_t)o0 * CH);
    const char* B = (const char*)(g_o16 + ((size_t)b * NPIX + n0) * CH);

    float acc[2][8][4] = {};
    pipeline1(sb, A, B, CH * 2, 4, acc, wm, wn, lane);

    const int r0 = wm * 32 + (lane >> 2), c0 = wn * 64 + (lane & 3) * 2;
    #pragma unroll
    for (int mt = 0; mt < 2; mt++) {
        const int r  = o0 + r0 + mt * 16;
        const float b0 = proj_b[r], b1 = proj_b[r + 8];
        #pragma unroll
        for (int nt = 0; nt < 8; nt++) {
            const size_t idx0 = ((size_t)b * CH + r) * NPIX + n0 + c0 + nt * 8;
            const size_t idx1 = idx0 + (size_t)8 * NPIX;
            float2 x0 = *(const float2*)(x + idx0);
            float2 x1 = *(const float2*)(x + idx1);
            *(float2*)(out + idx0) = make_float2(acc[mt][nt][0] + b0 + x0.x,
                                                 acc[mt][nt][1] + b0 + x0.y);
            *(float2*)(out + idx1) = make_float2(acc[mt][nt][2] + b1 + x1.x,
                                                 acc[mt][nt][3] + b1 + x1.y);
        }
    }
}

// ---------- launch ----------
extern "C" void kernel_launch(void* const* d_in, const int* in_sizes, int n_in,
                              void* d_out, int out_size) {
    const float* x      = (const float*)d_in[0];
    const float* gn_w   = (const float*)d_in[1];
    const float* gn_b   = (const float*)d_in[2];
    const float* qkv_w  = (const float*)d_in[3];
    const float* qkv_b  = (const float*)d_in[4];
    const float* proj_w = (const float*)d_in[5];
    const float* proj_b = (const float*)d_in[6];
    float* out = (float*)d_out;

    cudaFuncSetAttribute(qkv_hmma,      cudaFuncAttributeMaxDynamicSharedMemorySize, 69632);
    cudaFuncSetAttribute(proj_hmma,     cudaFuncAttributeMaxDynamicSharedMemorySize, 65536);
    cudaFuncSetAttribute(s_gemm_kernel, cudaFuncAttributeMaxDynamicSharedMemorySize, 98304);
    cudaFuncSetAttribute(pv_gemm_kernel,cudaFuncAttributeMaxDynamicSharedMemorySize, 98304);

    zero_l<<<BATCH * NPIX / 256, 256>>>();
    w_convert<<<256, 256>>>(qkv_w, proj_w);
    gn_kernel<<<BATCH * 32, 256>>>(x, gn_w, gn_b);
    {
        dim3 g(NPIX / 32, CH / 32, BATCH);
        h_convert<<<g, 256>>>();
    }
    {
        dim3 g(NPIX / 128, 6, BATCH);
        qkv_hmma<<<g, 256, 69632>>>(qkv_b);
    }
    {
        dim3 g(NPIX / 128, NPIX / 256, BATCH);
        s_gemm_kernel<<<g, 256, 98304>>>();
    }
    pv_gemm_kernel<<<(NPIX / 128) * BATCH, 256, 98304>>>();
    {
        dim3 g(NPIX / 128, 2, BATCH);
        proj_hmma<<<g, 256, 65536>>>(proj_b, x, out);
    }
}

// round 13
// speedup vs baseline: 2.0877x; 1.0092x over previous
#include <cuda_runtime.h>
#include <cuda_fp16.h>
#include <math.h>
#include <stdint.h>

#define BATCH 4
#define CH    256
#define NPIX  4096
#define CPG   8
// q pre-scale: C^-0.5 * log2(e)  -> S emerges in log2 domain, P = 2^S
#define QSC   (0.0625f * 1.44269504f)

__device__ __half g_h16c[(size_t)BATCH * CH * NPIX];   // groupnorm out [c][n] fp16
__device__ __half g_h16 [(size_t)BATCH * NPIX * CH];   // transposed [n][c]
__device__ __half g_wq16[3 * CH * CH];
__device__ __half g_wp16[CH * CH];
__device__ __half g_q16[(size_t)BATCH * NPIX * CH];
__device__ __half g_k16[(size_t)BATCH * NPIX * CH];
__device__ __half g_v16h[(size_t)BATCH * CH * NPIX];
__device__ __half g_p [(size_t)BATCH * NPIX * NPIX];
__device__ float g_l [BATCH * NPIX];
__device__ __half g_o16[(size_t)BATCH * NPIX * CH];

#define SWZ(o) ((o) ^ (((o) >> 3) & 0x70))

__device__ __forceinline__ uint32_t smem_u32(const void* p) {
    uint32_t a;
    asm("{ .reg .u64 t; cvta.to.shared.u64 t, %1; cvt.u32.u64 %0, t; }" : "=r"(a) : "l"(p));
    return a;
}
__device__ __forceinline__ void cp16(uint32_t dst, const void* src) {
    asm volatile("cp.async.cg.shared.global [%0], [%1], 16;" :: "r"(dst), "l"(src) : "memory");
}
__device__ __forceinline__ void ldm4(uint32_t* r, uint32_t addr) {
    asm volatile("ldmatrix.sync.aligned.m8n8.x4.shared.b16 {%0,%1,%2,%3}, [%4];"
                 : "=r"(r[0]), "=r"(r[1]), "=r"(r[2]), "=r"(r[3]) : "r"(addr));
}
__device__ __forceinline__ void mma16816h(float* c, const uint32_t* a, const uint32_t* b) {
    asm volatile("mma.sync.aligned.m16n8k16.row.col.f32.f16.f16.f32 "
                 "{%0,%1,%2,%3}, {%4,%5,%6,%7}, {%8,%9}, {%0,%1,%2,%3};"
                 : "+f"(c[0]), "+f"(c[1]), "+f"(c[2]), "+f"(c[3])
                 : "r"(a[0]), "r"(a[1]), "r"(a[2]), "r"(a[3]), "r"(b[0]), "r"(b[1]));
}
__device__ __forceinline__ uint32_t ex2h2(uint32_t x) {
    uint32_t r;
    asm("ex2.approx.f16x2 %0, %1;" : "=r"(r) : "r"(x));
    return r;
}

// copy rows x 128B into SW128-swizzled smem tile (byte pitch)
__device__ __forceinline__ void cp_rows(uint32_t dst, const char* src, long pitchB, int rows) {
    for (int idx = threadIdx.x; idx < rows * 8; idx += blockDim.x) {
        const int r = idx >> 3, cg = idx & 7;
        cp16(dst + SWZ(r * 128 + cg * 16), src + (long)r * pitchB + cg * 16);
    }
}

// ========== single-fp16 core, CTA 128x128, warp 32x64 (8 warps) ==========
__device__ __forceinline__ void mma_chunk1(uint32_t sA, uint32_t sB,
                                           float (&acc)[2][8][4], int wm, int wn, int lane) {
    const int lr = lane & 15, lc = (lane >> 4) * 16;
    #pragma unroll
    for (int kk = 0; kk < 4; kk++) {
        const int kb = kk * 32;
        uint32_t a[2][4];
        #pragma unroll
        for (int mt = 0; mt < 2; mt++)
            ldm4(a[mt], sA + SWZ((wm * 32 + mt * 16 + lr) * 128 + kb + lc));
        #pragma unroll
        for (int np = 0; np < 4; np++) {
            uint32_t b4[4];
            ldm4(b4, sB + SWZ((wn * 64 + np * 16 + lr) * 128 + kb + lc));
            uint32_t b0[2] = {b4[0], b4[2]}, b1[2] = {b4[1], b4[3]};
            #pragma unroll
            for (int mt = 0; mt < 2; mt++) {
                mma16816h(acc[mt][np * 2],     a[mt], b0);
                mma16816h(acc[mt][np * 2 + 1], a[mt], b1);
            }
        }
    }
}
__device__ __forceinline__ void pipeline1(uint32_t sb, const char* A, const char* B,
                                          long pitchB, int nch,
                                          float (&acc)[2][8][4], int wm, int wn, int lane) {
    cp_rows(sb,         A, pitchB, 128);
    cp_rows(sb + 16384, B, pitchB, 128);
    asm volatile("cp.async.commit_group;" ::: "memory");
    for (int ch = 0; ch < nch; ch++) {
        const uint32_t stb = sb + (ch & 1) * 32768;
        if (ch + 1 < nch) {
            const uint32_t nstb = sb + ((ch + 1) & 1) * 32768;
            const long k0 = (long)(ch + 1) * 128;
            cp_rows(nstb,         A + k0, pitchB, 128);
            cp_rows(nstb + 16384, B + k0, pitchB, 128);
            asm volatile("cp.async.commit_group;" ::: "memory");
            asm volatile("cp.async.wait_group 1;" ::: "memory");
        } else {
            asm volatile("cp.async.wait_group 0;" ::: "memory");
        }
        __syncthreads();
        mma_chunk1(stb, stb + 16384, acc, wm, wn, lane);
        __syncthreads();
    }
}

// ---------- GroupNorm -> fp16 [c][n] ----------
__global__ void __launch_bounds__(256) gn_kernel(const float* __restrict__ x,
                                                 const float* __restrict__ w,
                                                 const float* __restrict__ bias) {
    const int b = blockIdx.x >> 5, g = blockIdx.x & 31;
    const float* xp = x + (b * CH + g * CPG) * NPIX;
    __half*      hp = g_h16c + ((size_t)b * CH + g * CPG) * NPIX;
    const int NE = CPG * NPIX;
    float s = 0.f, ss = 0.f;
    const float4* x4 = (const float4*)xp;
    for (int i = threadIdx.x; i < NE / 4; i += 256) {
        float4 v = x4[i];
        s  += v.x + v.y + v.z + v.w;
        ss += v.x * v.x + v.y * v.y + v.z * v.z + v.w * v.w;
    }
    __shared__ float rs[32], rss[32];
    #pragma unroll
    for (int o = 16; o; o >>= 1) {
        s  += __shfl_xor_sync(~0u, s,  o);
        ss += __shfl_xor_sync(~0u, ss, o);
    }
    const int lane = threadIdx.x & 31, wid = threadIdx.x >> 5;
    if (lane == 0) { rs[wid] = s; rss[wid] = ss; }
    __syncthreads();
    if (wid == 0) {
        s  = (lane < 8) ? rs[lane]  : 0.f;
        ss = (lane < 8) ? rss[lane] : 0.f;
        #pragma unroll
        for (int o = 16; o; o >>= 1) {
            s  += __shfl_xor_sync(~0u, s,  o);
            ss += __shfl_xor_sync(~0u, ss, o);
        }
        if (lane == 0) { rs[0] = s; rss[0] = ss; }
    }
    __syncthreads();
    const float mu   = rs[0] / (float)NE;
    const float rstd = rsqrtf(rss[0] / (float)NE - mu * mu + 1e-5f);
    for (int i = threadIdx.x; i < NE / 4; i += 256) {
        const int c = g * CPG + (i >> 10);
        const float wc = w[c] * rstd, bc = bias[c] - mu * wc;
        float4 v = x4[i];
        __half2 h0, h1;
        h0.x = __float2half_rn(v.x * wc + bc); h0.y = __float2half_rn(v.y * wc + bc);
        h1.x = __float2half_rn(v.z * wc + bc); h1.y = __float2half_rn(v.w * wc + bc);
        *(__half2*)(hp + i * 4)     = h0;
        *(__half2*)(hp + i * 4 + 2) = h1;
    }
}

// ---------- h: [c][n] fp16 -> [n][c] fp16 ----------
__global__ void __launch_bounds__(256) h_convert() {
    __shared__ float t[32][33];
    const int n0 = blockIdx.x * 32, c0 = blockIdx.y * 32, b = blockIdx.z;
    const __half* src = g_h16c + ((size_t)b * CH + c0) * NPIX + n0;
    const int tx = threadIdx.x & 31, ty = threadIdx.x >> 5;
    #pragma unroll
    for (int j = 0; j < 4; j++)
        t[ty + 8 * j][tx] = __half2float(src[(size_t)(ty + 8 * j) * NPIX + tx]);
    __syncthreads();
    const size_t dbase = ((size_t)b * NPIX + n0) * CH + c0;
    #pragma unroll
    for (int j = 0; j < 4; j++)
        g_h16[dbase + (size_t)(ty + 8 * j) * CH + tx] = __float2half_rn(t[tx][ty + 8 * j]);
}

// ---------- weight -> fp16 (also zeroes g_l) ----------
__global__ void __launch_bounds__(256) w_convert(const float* __restrict__ qkv_w,
                                                 const float* __restrict__ proj_w) {
    if (blockIdx.x < 64)
        g_l[blockIdx.x * 256 + threadIdx.x] = 0.f;
    const int f4 = blockIdx.x * 256 + threadIdx.x;
    const float* src;
    __half* d;
    size_t e;
    if (f4 < 49152) { src = qkv_w;  d = g_wq16; e = (size_t)f4 * 4; }
    else            { src = proj_w; d = g_wp16; e = (size_t)(f4 - 49152) * 4; }
    float4 v = *(const float4*)(src + e);
    __half2 h0, h1;
    h0.x = __float2half_rn(v.x); h0.y = __float2half_rn(v.y);
    h1.x = __float2half_rn(v.z); h1.y = __float2half_rn(v.w);
    *(__half2*)(d + e)     = h0;
    *(__half2*)(d + e + 2) = h1;
}

// ---------- QKV = W*H (single fp16; q (scaled by QSC),k -> [n][c], v -> [c][n]) ----------
__global__ void __launch_bounds__(256, 1) qkv_hmma(const float* __restrict__ qkv_b) {
    extern __shared__ char smem[];
    const uint32_t sb = smem_u32(smem);
    const int tid = threadIdx.x, lane = tid & 31, wid = tid >> 5;
    const int wm = wid & 3, wn = wid >> 2;
    const int b = blockIdx.z, n0 = blockIdx.x * 128, o0 = blockIdx.y * 128;

    const char* A = (const char*)(g_wq16 + (size_t)o0 * CH);
    const char* B = (const char*)(g_h16 + ((size_t)b * NPIX + n0) * CH);

    float acc[2][8][4] = {};
    pipeline1(sb, A, B, CH * 2, 4, acc, wm, wn, lane);

    const int r0 = wm * 32 + (lane >> 2), c0 = wn * 64 + (lane & 3) * 2;
    #pragma unroll
    for (int mt = 0; mt < 2; mt++) {
        const float b0 = qkv_b[o0 + r0 + mt * 16];
        const float b1 = qkv_b[o0 + r0 + mt * 16 + 8];
        #pragma unroll
        for (int nt = 0; nt < 8; nt++) {
            acc[mt][nt][0] += b0; acc[mt][nt][1] += b0;
            acc[mt][nt][2] += b1; acc[mt][nt][3] += b1;
        }
    }

    const int sel = blockIdx.y >> 1;   // 0=q, 1=k, 2=v
    if (sel == 2) {
        __half* vh = g_v16h + ((size_t)b * CH + (o0 - 512)) * NPIX + n0;
        #pragma unroll
        for (int mt = 0; mt < 2; mt++)
            #pragma unroll
            for (int nt = 0; nt < 8; nt++) {
                const int rr = r0 + mt * 16, cc = c0 + nt * 8;
                __half2 h0, h1;
                h0.x = __float2half_rn(acc[mt][nt][0]); h0.y = __float2half_rn(acc[mt][nt][1]);
                h1.x = __float2half_rn(acc[mt][nt][2]); h1.y = __float2half_rn(acc[mt][nt][3]);
                *(__half2*)(vh + (size_t)rr * NPIX + cc)       = h0;
                *(__half2*)(vh + (size_t)(rr + 8) * NPIX + cc) = h1;
            }
    } else {
        const float sc = sel ? 1.f : QSC;
        float* st = (float*)smem;   // [c 128][n 132]
        __syncthreads();
        #pragma unroll
        for (int mt = 0; mt < 2; mt++)
            #pragma unroll
            for (int nt = 0; nt < 8; nt++) {
                const int rr = r0 + mt * 16, cc = c0 + nt * 8;
                st[(cc)     * 132 + rr]     = acc[mt][nt][0];
                st[(cc + 1) * 132 + rr]     = acc[mt][nt][1];
                st[(cc)     * 132 + rr + 8] = acc[mt][nt][2];
                st[(cc + 1) * 132 + rr + 8] = acc[mt][nt][3];
            }
        __syncthreads();
        __half* dq = (sel ? g_k16 : g_q16) + ((size_t)b * NPIX + n0) * CH + (o0 - sel * 256);
        const int o4 = lane * 4, nb = tid >> 5;
        #pragma unroll
        for (int j = 0; j < 16; j++) {
            const int n = nb + 8 * j;
            float4 v = *(float4*)(st + n * 132 + o4);
            __half2 h0, h1;
            h0.x = __float2half_rn(v.x * sc); h0.y = __float2half_rn(v.y * sc);
            h1.x = __float2half_rn(v.z * sc); h1.y = __float2half_rn(v.w * sc);
            *(__half2*)(dq + (size_t)n * CH + o4)     = h0;
            *(__half2*)(dq + (size_t)n * CH + o4 + 2) = h1;
        }
    }
}

// ---------- P = 2^(Q K^T) unnormalized (ex2.f16x2) + row-sum atomics ----------
__global__ void __launch_bounds__(256, 1) s_gemm_kernel() {
    extern __shared__ char smem[];
    const uint32_t sb = smem_u32(smem);
    const int tid = threadIdx.x, lane = tid & 31, wid = tid >> 5;
    const int wm = wid & 3, wn = wid >> 2;   // 4 x 2 warps
    const int b = blockIdx.z, i0 = blockIdx.y * 256, j0 = blockIdx.x * 128;

    const char* Aq = (const char*)(g_q16 + ((size_t)b * NPIX + i0) * CH);
    const char* Bk = (const char*)(g_k16 + ((size_t)b * NPIX + j0) * CH);
    const long pB = CH * 2;

    float acc[4][8][4] = {};
    const int lr = lane & 15, lc = (lane >> 4) * 16;

    cp_rows(sb,         Aq, pB, 256);
    cp_rows(sb + 32768, Bk, pB, 128);
    asm volatile("cp.async.commit_group;" ::: "memory");

    for (int ch = 0; ch < 4; ch++) {
        const uint32_t stb = sb + (ch & 1) * 49152;
        if (ch + 1 < 4) {
            const uint32_t nstb = sb + ((ch + 1) & 1) * 49152;
            const long k0 = (long)(ch + 1) * 128;
            cp_rows(nstb,         Aq + k0, pB, 256);
            cp_rows(nstb + 32768, Bk + k0, pB, 128);
            asm volatile("cp.async.commit_group;" ::: "memory");
            asm volatile("cp.async.wait_group 1;" ::: "memory");
        } else {
            asm volatile("cp.async.wait_group 0;" ::: "memory");
        }
        __syncthreads();
        #pragma unroll
        for (int kk = 0; kk < 4; kk++) {
            const int kb = kk * 32;
            uint32_t a[4][4];
            #pragma unroll
            for (int mt = 0; mt < 4; mt++)
                ldm4(a[mt], stb + SWZ((wm * 64 + mt * 16 + lr) * 128 + kb + lc));
            #pragma unroll
            for (int np = 0; np < 4; np++) {
                uint32_t b4[4];
                ldm4(b4, stb + 32768 + SWZ((wn * 64 + np * 16 + lr) * 128 + kb + lc));
                uint32_t b0[2] = {b4[0], b4[2]}, b1[2] = {b4[1], b4[3]};
                #pragma unroll
                for (int mt = 0; mt < 4; mt++) {
                    mma16816h(acc[mt][np * 2],     a[mt], b0);
                    mma16816h(acc[mt][np * 2 + 1], a[mt], b1);
                }
            }
        }
        __syncthreads();
    }

    // epilogue: P = 2^acc via packed f16x2 MUFU, store fp16, row sums fp32
    __half* Pb = g_p + ((size_t)b * NPIX + i0) * NPIX + j0;
    float* lrow = g_l + (size_t)b * NPIX + i0;
    const int r0 = wm * 64 + (lane >> 2), c0 = wn * 64 + (lane & 3) * 2;
    #pragma unroll
    for (int mt = 0; mt < 4; mt++) {
        float rs0 = 0.f, rs1 = 0.f;
        #pragma unroll
        for (int nt = 0; nt < 8; nt++) {
            __half2 x01 = __floats2half2_rn(acc[mt][nt][0], acc[mt][nt][1]);
            __half2 x23 = __floats2half2_rn(acc[mt][nt][2], acc[mt][nt][3]);
            const uint32_t e01 = ex2h2(*(uint32_t*)&x01);
            const uint32_t e23 = ex2h2(*(uint32_t*)&x23);
            float2 f01 = __half22float2(*(const __half2*)&e01);
            float2 f23 = __half22float2(*(const __half2*)&e23);
            rs0 += f01.x + f01.y;
            rs1 += f23.x + f23.y;
            __half* p = Pb + (size_t)(r0 + mt * 16) * NPIX + c0 + nt * 8;
            *(uint32_t*)p = e01;
            *(uint32_t*)(p + (size_t)8 * NPIX) = e23;
        }
        rs0 += __shfl_xor_sync(~0u, rs0, 1);
        rs0 += __shfl_xor_sync(~0u, rs0, 2);
        rs1 += __shfl_xor_sync(~0u, rs1, 1);
        rs1 += __shfl_xor_sync(~0u, rs1, 2);
        if ((lane & 3) == 0) {
            atomicAdd(lrow + r0 + mt * 16,     rs0);
            atomicAdd(lrow + r0 + mt * 16 + 8, rs1);
        }
    }
}

// ---------- O = P V then normalize by row sums ----------
__global__ void __launch_bounds__(256, 1) pv_gemm_kernel() {
    extern __shared__ char smem[];
    const uint32_t sb = smem_u32(smem);
    const int tid = threadIdx.x, lane = tid & 31, wid = tid >> 5;
    const int wm = wid & 1, wn = wid >> 1;   // 2 x 4 warps
    const int b = blockIdx.x & 3, i0 = (blockIdx.x >> 2) * 128;

    const char* Ap = (const char*)(g_p + ((size_t)b * NPIX + i0) * NPIX);
    const char* Bh = (const char*)(g_v16h + (size_t)b * CH * NPIX);
    const long pB = NPIX * 2;

    float acc[4][8][4] = {};
    const int lr = lane & 15, lc = (lane >> 4) * 16;

    cp_rows(sb,         Ap, pB, 128);
    cp_rows(sb + 16384, Bh, pB, 256);
    asm volatile("cp.async.commit_group;" ::: "memory");

    for (int ch = 0; ch < 64; ch++) {
        const uint32_t stb = sb + (ch & 1) * 49152;
        if (ch + 1 < 64) {
            const uint32_t nstb = sb + ((ch + 1) & 1) * 49152;
            const long k0 = (long)(ch + 1) * 128;
            cp_rows(nstb,         Ap + k0, pB, 128);
            cp_rows(nstb + 16384, Bh + k0, pB, 256);
            asm volatile("cp.async.commit_group;" ::: "memory");
            asm volatile("cp.async.wait_group 1;" ::: "memory");
        } else {
            asm volatile("cp.async.wait_group 0;" ::: "memory");
        }
        __syncthreads();
        #pragma unroll
        for (int kk = 0; kk < 4; kk++) {
            const int kb = kk * 32;
            uint32_t a[4][4];
            #pragma unroll
            for (int mt = 0; mt < 4; mt++)
                ldm4(a[mt], stb + SWZ((wm * 64 + mt * 16 + lr) * 128 + kb + lc));
            #pragma unroll
            for (int np = 0; np < 4; np++) {
                uint32_t b4[4];
                ldm4(b4, stb + 16384 + SWZ((wn * 64 + np * 16 + lr) * 128 + kb + lc));
                uint32_t b0[2] = {b4[0], b4[2]}, b1[2] = {b4[1], b4[3]};
                #pragma unroll
                for (int mt = 0; mt < 4; mt++) {
                    mma16816h(acc[mt][np * 2],     a[mt], b0);
                    mma16816h(acc[mt][np * 2 + 1], a[mt], b1);
                }
            }
        }
        __syncthreads();
    }

    __half* o16 = g_o16 + ((size_t)b * NPIX + i0) * CH;
    const float* lrow = g_l + (size_t)b * NPIX + i0;
    const int r0 = wm * 64 + (lane >> 2), c0 = wn * 64 + (lane & 3) * 2;
    #pragma unroll
    for (int mt = 0; mt < 4; mt++) {
        const float inv0 = 1.f / lrow[r0 + mt * 16];
        const float inv1 = 1.f / lrow[r0 + mt * 16 + 8];
        #pragma unroll
        for (int nt = 0; nt < 8; nt++) {
            const int rr = r0 + mt * 16, cc = c0 + nt * 8;
            __half2 h0, h1;
            h0.x = __float2half_rn(acc[mt][nt][0] * inv0);
            h0.y = __float2half_rn(acc[mt][nt][1] * inv0);
            h1.x = __float2half_rn(acc[mt][nt][2] * inv1);
            h1.y = __float2half_rn(acc[mt][nt][3] * inv1);
            *(__half2*)(o16 + (size_t)rr * CH + cc)       = h0;
            *(__half2*)(o16 + (size_t)(rr + 8) * CH + cc) = h1;
        }
    }
}

// ---------- out = proj_w * O + proj_b + x ----------
__global__ void __launch_bounds__(256, 1) proj_hmma(const float* __restrict__ proj_b,
                                                    const float* __restrict__ x,
                                                    float* __restrict__ out) {
    extern __shared__ char smem[];
    const uint32_t sb = smem_u32(smem);
    const int tid = threadIdx.x, lane = tid & 31, wid = tid >> 5;
    const int wm = wid & 3, wn = wid >> 2;
    const int b = blockIdx.z, n0 = blockIdx.x * 128, o0 = blockIdx.y * 128;

    const char* A = (const char*)(g_wp16 + (size_t)o0 * CH);
    const char* B = (const char*)(g_o16 + ((size_t)b * NPIX + n0) * CH);

    float acc[2][8][4] = {};
    pipeline1(sb, A, B, CH * 2, 4, acc, wm, wn, lane);

    const int r0 = wm * 32 + (lane >> 2), c0 = wn * 64 + (lane & 3) * 2;
    #pragma unroll
    for (int mt = 0; mt < 2; mt++) {
        const int r  = o0 + r0 + mt * 16;
        const float b0 = proj_b[r], b1 = proj_b[r + 8];
        #pragma unroll
        for (int nt = 0; nt < 8; nt++) {
            const size_t idx0 = ((size_t)b * CH + r) * NPIX + n0 + c0 + nt * 8;
            const size_t idx1 = idx0 + (size_t)8 * NPIX;
            float2 x0 = *(const float2*)(x + idx0);
            float2 x1 = *(const float2*)(x + idx1);
            *(float2*)(out + idx0) = make_float2(acc[mt][nt][0] + b0 + x0.x,
                                                 acc[mt][nt][1] + b0 + x0.y);
            *(float2*)(out + idx1) = make_float2(acc[mt][nt][2] + b1 + x1.x,
                                                 acc[mt][nt][3] + b1 + x1.y);
        }
    }
}

// ---------- launch ----------
extern "C" void kernel_launch(void* const* d_in, const int* in_sizes, int n_in,
                              void* d_out, int out_size) {
    const float* x      = (const float*)d_in[0];
    const float* gn_w   = (const float*)d_in[1];
    const float* gn_b   = (const float*)d_in[2];
    const float* qkv_w  = (const float*)d_in[3];
    const float* qkv_b  = (const float*)d_in[4];
    const float* proj_w = (const float*)d_in[5];
    const float* proj_b = (const float*)d_in[6];
    float* out = (float*)d_out;

    cudaFuncSetAttribute(qkv_hmma,      cudaFuncAttributeMaxDynamicSharedMemorySize, 69632);
    cudaFuncSetAttribute(proj_hmma,     cudaFuncAttributeMaxDynamicSharedMemorySize, 65536);
    cudaFuncSetAttribute(s_gemm_kernel, cudaFuncAttributeMaxDynamicSharedMemorySize, 98304);
    cudaFuncSetAttribute(pv_gemm_kernel,cudaFuncAttributeMaxDynamicSharedMemorySize, 98304);

    w_convert<<<256, 256>>>(qkv_w, proj_w);
    gn_kernel<<<BATCH * 32, 256>>>(x, gn_w, gn_b);
    {
        dim3 g(NPIX / 32, CH / 32, BATCH);
        h_convert<<<g, 256>>>();
    }
    {
        dim3 g(NPIX / 128, 6, BATCH);
        qkv_hmma<<<g, 256, 69632>>>(qkv_b);
    }
    {
        dim3 g(NPIX / 128, NPIX / 256, BATCH);
        s_gemm_kernel<<<g, 256, 98304>>>();
    }
    pv_gemm_kernel<<<(NPIX / 128) * BATCH, 256, 98304>>>();
    {
        dim3 g(NPIX / 128, 2, BATCH);
        proj_hmma<<<g, 256, 65536>>>(proj_b, x, out);
    }
}

// round 14
// speedup vs baseline: 2.2628x; 1.0839x over previous
#include <cuda_runtime.h>
#include <cuda_fp16.h>
#include <math.h>
#include <stdint.h>

#define BATCH 4
#define CH    256
#define NPIX  4096
#define CPG   8
// q pre-scale: C^-0.5 * log2(e)  -> S emerges in log2 domain, P = 2^S
#define QSC   (0.0625f * 1.44269504f)

__device__ __half g_h16c[(size_t)BATCH * CH * NPIX];
__device__ __half g_h16 [(size_t)BATCH * NPIX * CH];
__device__ __half g_wq16[3 * CH * CH];
__device__ __half g_wp16[CH * CH];
__device__ __half g_q16[(size_t)BATCH * NPIX * CH];
__device__ __half g_k16[(size_t)BATCH * NPIX * CH];
__device__ __half g_v16h[(size_t)BATCH * CH * NPIX];
__device__ __half g_p [(size_t)BATCH * NPIX * NPIX];
__device__ float g_l [BATCH * NPIX];
__device__ __half g_o16[(size_t)BATCH * NPIX * CH];

#define SWZ(o) ((o) ^ (((o) >> 3) & 0x70))

__device__ __forceinline__ uint32_t smem_u32(const void* p) {
    uint32_t a;
    asm("{ .reg .u64 t; cvta.to.shared.u64 t, %1; cvt.u32.u64 %0, t; }" : "=r"(a) : "l"(p));
    return a;
}
__device__ __forceinline__ void cp16(uint32_t dst, const void* src) {
    asm volatile("cp.async.cg.shared.global [%0], [%1], 16;" :: "r"(dst), "l"(src) : "memory");
}
__device__ __forceinline__ void ldm4(uint32_t* r, uint32_t addr) {
    asm volatile("ldmatrix.sync.aligned.m8n8.x4.shared.b16 {%0,%1,%2,%3}, [%4];"
                 : "=r"(r[0]), "=r"(r[1]), "=r"(r[2]), "=r"(r[3]) : "r"(addr));
}
__device__ __forceinline__ void mma16816h(float* c, const uint32_t* a, const uint32_t* b) {
    asm volatile("mma.sync.aligned.m16n8k16.row.col.f32.f16.f16.f32 "
                 "{%0,%1,%2,%3}, {%4,%5,%6,%7}, {%8,%9}, {%0,%1,%2,%3};"
                 : "+f"(c[0]), "+f"(c[1]), "+f"(c[2]), "+f"(c[3])
                 : "r"(a[0]), "r"(a[1]), "r"(a[2]), "r"(a[3]), "r"(b[0]), "r"(b[1]));
}
__device__ __forceinline__ uint32_t ex2h2(uint32_t x) {
    uint32_t r;
    asm("ex2.approx.f16x2 %0, %1;" : "=r"(r) : "r"(x));
    return r;
}

// copy rows x 128B into SW128-swizzled smem tile
__device__ __forceinline__ void cp_rows(uint32_t dst, const char* src, long pitchB, int rows) {
    for (int idx = threadIdx.x; idx < rows * 8; idx += blockDim.x) {
        const int r = idx >> 3, cg = idx & 7;
        cp16(dst + SWZ(r * 128 + cg * 16), src + (long)r * pitchB + cg * 16);
    }
}
// copy rows x 256B as two stacked 128B tiles (second half at +rows*128)
__device__ __forceinline__ void cp_rows2(uint32_t dst, const char* src, long pitchB, int rows) {
    for (int idx = threadIdx.x; idx < rows * 16; idx += blockDim.x) {
        const int r = idx >> 4, cg = idx & 15;
        const uint32_t off = ((cg & 8) ? (uint32_t)rows * 128 : 0u) + SWZ(r * 128 + (cg & 7) * 16);
        cp16(dst + off, src + (long)r * pitchB + cg * 16);
    }
}

// ========== single-fp16 core, CTA 128x128, warp 32x64 (8 warps) ==========
__device__ __forceinline__ void mma_chunk1(uint32_t sA, uint32_t sB,
                                           float (&acc)[2][8][4], int wm, int wn, int lane) {
    const int lr = lane & 15, lc = (lane >> 4) * 16;
    #pragma unroll
    for (int kk = 0; kk < 4; kk++) {
        const int kb = kk * 32;
        uint32_t a[2][4];
        #pragma unroll
        for (int mt = 0; mt < 2; mt++)
            ldm4(a[mt], sA + SWZ((wm * 32 + mt * 16 + lr) * 128 + kb + lc));
        #pragma unroll
        for (int np = 0; np < 4; np++) {
            uint32_t b4[4];
            ldm4(b4, sB + SWZ((wn * 64 + np * 16 + lr) * 128 + kb + lc));
            uint32_t b0[2] = {b4[0], b4[2]}, b1[2] = {b4[1], b4[3]};
            #pragma unroll
            for (int mt = 0; mt < 2; mt++) {
                mma16816h(acc[mt][np * 2],     a[mt], b0);
                mma16816h(acc[mt][np * 2 + 1], a[mt], b1);
            }
        }
    }
}
__device__ __forceinline__ void pipeline1(uint32_t sb, const char* A, const char* B,
                                          long pitchB, int nch,
                                          float (&acc)[2][8][4], int wm, int wn, int lane) {
    cp_rows(sb,         A, pitchB, 128);
    cp_rows(sb + 16384, B, pitchB, 128);
    asm volatile("cp.async.commit_group;" ::: "memory");
    for (int ch = 0; ch < nch; ch++) {
        const uint32_t stb = sb + (ch & 1) * 32768;
        if (ch + 1 < nch) {
            const uint32_t nstb = sb + ((ch + 1) & 1) * 32768;
            const long k0 = (long)(ch + 1) * 128;
            cp_rows(nstb,         A + k0, pitchB, 128);
            cp_rows(nstb + 16384, B + k0, pitchB, 128);
            asm volatile("cp.async.commit_group;" ::: "memory");
            asm volatile("cp.async.wait_group 1;" ::: "memory");
        } else {
            asm volatile("cp.async.wait_group 0;" ::: "memory");
        }
        __syncthreads();
        mma_chunk1(stb, stb + 16384, acc, wm, wn, lane);
        __syncthreads();
    }
}

// ---------- GroupNorm -> fp16 [c][n] ----------
__global__ void __launch_bounds__(256) gn_kernel(const float* __restrict__ x,
                                                 const float* __restrict__ w,
                                                 const float* __restrict__ bias) {
    const int b = blockIdx.x >> 5, g = blockIdx.x & 31;
    const float* xp = x + (b * CH + g * CPG) * NPIX;
    __half*      hp = g_h16c + ((size_t)b * CH + g * CPG) * NPIX;
    const int NE = CPG * NPIX;
    float s = 0.f, ss = 0.f;
    const float4* x4 = (const float4*)xp;
    for (int i = threadIdx.x; i < NE / 4; i += 256) {
        float4 v = x4[i];
        s  += v.x + v.y + v.z + v.w;
        ss += v.x * v.x + v.y * v.y + v.z * v.z + v.w * v.w;
    }
    __shared__ float rs[32], rss[32];
    #pragma unroll
    for (int o = 16; o; o >>= 1) {
        s  += __shfl_xor_sync(~0u, s,  o);
        ss += __shfl_xor_sync(~0u, ss, o);
    }
    const int lane = threadIdx.x & 31, wid = threadIdx.x >> 5;
    if (lane == 0) { rs[wid] = s; rss[wid] = ss; }
    __syncthreads();
    if (wid == 0) {
        s  = (lane < 8) ? rs[lane]  : 0.f;
        ss = (lane < 8) ? rss[lane] : 0.f;
        #pragma unroll
        for (int o = 16; o; o >>= 1) {
            s  += __shfl_xor_sync(~0u, s,  o);
            ss += __shfl_xor_sync(~0u, ss, o);
        }
        if (lane == 0) { rs[0] = s; rss[0] = ss; }
    }
    __syncthreads();
    const float mu   = rs[0] / (float)NE;
    const float rstd = rsqrtf(rss[0] / (float)NE - mu * mu + 1e-5f);
    for (int i = threadIdx.x; i < NE / 4; i += 256) {
        const int c = g * CPG + (i >> 10);
        const float wc = w[c] * rstd, bc = bias[c] - mu * wc;
        float4 v = x4[i];
        __half2 h0, h1;
        h0.x = __float2half_rn(v.x * wc + bc); h0.y = __float2half_rn(v.y * wc + bc);
        h1.x = __float2half_rn(v.z * wc + bc); h1.y = __float2half_rn(v.w * wc + bc);
        *(__half2*)(hp + i * 4)     = h0;
        *(__half2*)(hp + i * 4 + 2) = h1;
    }
}

// ---------- h: [c][n] fp16 -> [n][c] fp16 ----------
__global__ void __launch_bounds__(256) h_convert() {
    __shared__ float t[32][33];
    const int n0 = blockIdx.x * 32, c0 = blockIdx.y * 32, b = blockIdx.z;
    const __half* src = g_h16c + ((size_t)b * CH + c0) * NPIX + n0;
    const int tx = threadIdx.x & 31, ty = threadIdx.x >> 5;
    #pragma unroll
    for (int j = 0; j < 4; j++)
        t[ty + 8 * j][tx] = __half2float(src[(size_t)(ty + 8 * j) * NPIX + tx]);
    __syncthreads();
    const size_t dbase = ((size_t)b * NPIX + n0) * CH + c0;
    #pragma unroll
    for (int j = 0; j < 4; j++)
        g_h16[dbase + (size_t)(ty + 8 * j) * CH + tx] = __float2half_rn(t[tx][ty + 8 * j]);
}

// ---------- weight -> fp16 (also zeroes g_l) ----------
__global__ void __launch_bounds__(256) w_convert(const float* __restrict__ qkv_w,
                                                 const float* __restrict__ proj_w) {
    if (blockIdx.x < 64)
        g_l[blockIdx.x * 256 + threadIdx.x] = 0.f;
    const int f4 = blockIdx.x * 256 + threadIdx.x;
    const float* src;
    __half* d;
    size_t e;
    if (f4 < 49152) { src = qkv_w;  d = g_wq16; e = (size_t)f4 * 4; }
    else            { src = proj_w; d = g_wp16; e = (size_t)(f4 - 49152) * 4; }
    float4 v = *(const float4*)(src + e);
    __half2 h0, h1;
    h0.x = __float2half_rn(v.x); h0.y = __float2half_rn(v.y);
    h1.x = __float2half_rn(v.z); h1.y = __float2half_rn(v.w);
    *(__half2*)(d + e)     = h0;
    *(__half2*)(d + e + 2) = h1;
}

// ---------- QKV = W*H (single fp16; q (scaled by QSC),k -> [n][c], v -> [c][n]) ----------
__global__ void __launch_bounds__(256, 2) qkv_hmma(const float* __restrict__ qkv_b) {
    extern __shared__ char smem[];
    const uint32_t sb = smem_u32(smem);
    const int tid = threadIdx.x, lane = tid & 31, wid = tid >> 5;
    const int wm = wid & 3, wn = wid >> 2;
    const int b = blockIdx.z, n0 = blockIdx.x * 128, o0 = blockIdx.y * 128;

    const char* A = (const char*)(g_wq16 + (size_t)o0 * CH);
    const char* B = (const char*)(g_h16 + ((size_t)b * NPIX + n0) * CH);

    float acc[2][8][4] = {};
    pipeline1(sb, A, B, CH * 2, 4, acc, wm, wn, lane);

    const int r0 = wm * 32 + (lane >> 2), c0 = wn * 64 + (lane & 3) * 2;
    #pragma unroll
    for (int mt = 0; mt < 2; mt++) {
        const float b0 = qkv_b[o0 + r0 + mt * 16];
        const float b1 = qkv_b[o0 + r0 + mt * 16 + 8];
        #pragma unroll
        for (int nt = 0; nt < 8; nt++) {
            acc[mt][nt][0] += b0; acc[mt][nt][1] += b0;
            acc[mt][nt][2] += b1; acc[mt][nt][3] += b1;
        }
    }

    const int sel = blockIdx.y >> 1;   // 0=q, 1=k, 2=v
    if (sel == 2) {
        __half* vh = g_v16h + ((size_t)b * CH + (o0 - 512)) * NPIX + n0;
        #pragma unroll
        for (int mt = 0; mt < 2; mt++)
            #pragma unroll
            for (int nt = 0; nt < 8; nt++) {
                const int rr = r0 + mt * 16, cc = c0 + nt * 8;
                __half2 h0, h1;
                h0.x = __float2half_rn(acc[mt][nt][0]); h0.y = __float2half_rn(acc[mt][nt][1]);
                h1.x = __float2half_rn(acc[mt][nt][2]); h1.y = __float2half_rn(acc[mt][nt][3]);
                *(__half2*)(vh + (size_t)rr * NPIX + cc)       = h0;
                *(__half2*)(vh + (size_t)(rr + 8) * NPIX + cc) = h1;
            }
    } else {
        const float sc = sel ? 1.f : QSC;
        float* st = (float*)smem;   // [c 128][n 132]
        __syncthreads();
        #pragma unroll
        for (int mt = 0; mt < 2; mt++)
            #pragma unroll
            for (int nt = 0; nt < 8; nt++) {
                const int rr = r0 + mt * 16, cc = c0 + nt * 8;
                st[(cc)     * 132 + rr]     = acc[mt][nt][0];
                st[(cc + 1) * 132 + rr]     = acc[mt][nt][1];
                st[(cc)     * 132 + rr + 8] = acc[mt][nt][2];
                st[(cc + 1) * 132 + rr + 8] = acc[mt][nt][3];
            }
        __syncthreads();
        __half* dq = (sel ? g_k16 : g_q16) + ((size_t)b * NPIX + n0) * CH + (o0 - sel * 256);
        const int o4 = lane * 4, nb = tid >> 5;
        #pragma unroll
        for (int j = 0; j < 16; j++) {
            const int n = nb + 8 * j;
            float4 v = *(float4*)(st + n * 132 + o4);
            __half2 h0, h1;
            h0.x = __float2half_rn(v.x * sc); h0.y = __float2half_rn(v.y * sc);
            h1.x = __float2half_rn(v.z * sc); h1.y = __float2half_rn(v.w * sc);
            *(__half2*)(dq + (size_t)n * CH + o4)     = h0;
            *(__half2*)(dq + (size_t)n * CH + o4 + 2) = h1;
        }
    }
}

// ---------- P = 2^(Q K^T) (wide 256B chunks) + row-sum atomics ----------
// stage: A 64K @0 (two 32K halves) | B 32K @65536 (two 16K halves) = 96K; x2 = 192K
__global__ void __launch_bounds__(256, 1) s_gemm_kernel() {
    extern __shared__ char smem[];
    const uint32_t sb = smem_u32(smem);
    const int tid = threadIdx.x, lane = tid & 31, wid = tid >> 5;
    const int wm = wid & 3, wn = wid >> 2;   // 4 x 2 warps
    const int b = blockIdx.z, i0 = blockIdx.y * 256, j0 = blockIdx.x * 128;

    const char* Aq = (const char*)(g_q16 + ((size_t)b * NPIX + i0) * CH);
    const char* Bk = (const char*)(g_k16 + ((size_t)b * NPIX + j0) * CH);
    const long pB = CH * 2;

    float acc[4][8][4] = {};
    const int lr = lane & 15, lc = (lane >> 4) * 16;

    cp_rows2(sb,         Aq, pB, 256);
    cp_rows2(sb + 65536, Bk, pB, 128);
    asm volatile("cp.async.commit_group;" ::: "memory");

    for (int ch = 0; ch < 2; ch++) {
        const uint32_t stb = sb + (ch & 1) * 98304;
        if (ch + 1 < 2) {
            const uint32_t nstb = sb + ((ch + 1) & 1) * 98304;
            cp_rows2(nstb,         Aq + 256, pB, 256);
            cp_rows2(nstb + 65536, Bk + 256, pB, 128);
            asm volatile("cp.async.commit_group;" ::: "memory");
            asm volatile("cp.async.wait_group 1;" ::: "memory");
        } else {
            asm volatile("cp.async.wait_group 0;" ::: "memory");
        }
        __syncthreads();
        #pragma unroll
        for (int kk = 0; kk < 8; kk++) {
            const int kb = (kk & 3) * 32;
            const uint32_t ah = (kk >> 2) * 32768;
            const uint32_t bh = (kk >> 2) * 16384;
            uint32_t a[4][4];
            #pragma unroll
            for (int mt = 0; mt < 4; mt++)
                ldm4(a[mt], stb + ah + SWZ((wm * 64 + mt * 16 + lr) * 128 + kb + lc));
            #pragma unroll
            for (int np = 0; np < 4; np++) {
                uint32_t b4[4];
                ldm4(b4, stb + 65536 + bh + SWZ((wn * 64 + np * 16 + lr) * 128 + kb + lc));
                uint32_t b0[2] = {b4[0], b4[2]}, b1[2] = {b4[1], b4[3]};
                #pragma unroll
                for (int mt = 0; mt < 4; mt++) {
                    mma16816h(acc[mt][np * 2],     a[mt], b0);
                    mma16816h(acc[mt][np * 2 + 1], a[mt], b1);
                }
            }
        }
        __syncthreads();
    }

    // epilogue: P = 2^acc via f16x2 MUFU, row sums via HADD2
    __half* Pb = g_p + ((size_t)b * NPIX + i0) * NPIX + j0;
    float* lrow = g_l + (size_t)b * NPIX + i0;
    const int r0 = wm * 64 + (lane >> 2), c0 = wn * 64 + (lane & 3) * 2;
    #pragma unroll
    for (int mt = 0; mt < 4; mt++) {
        __half2 hs0 = __floats2half2_rn(0.f, 0.f);
        __half2 hs1 = __floats2half2_rn(0.f, 0.f);
        #pragma unroll
        for (int nt = 0; nt < 8; nt++) {
            __half2 x01 = __floats2half2_rn(acc[mt][nt][0], acc[mt][nt][1]);
            __half2 x23 = __floats2half2_rn(acc[mt][nt][2], acc[mt][nt][3]);
            const uint32_t e01 = ex2h2(*(uint32_t*)&x01);
            const uint32_t e23 = ex2h2(*(uint32_t*)&x23);
            hs0 = __hadd2(hs0, *(const __half2*)&e01);
            hs1 = __hadd2(hs1, *(const __half2*)&e23);
            __half* p = Pb + (size_t)(r0 + mt * 16) * NPIX + c0 + nt * 8;
            *(uint32_t*)p = e01;
            *(uint32_t*)(p + (size_t)8 * NPIX) = e23;
        }
        float rs0 = __half2float(hs0.x) + __half2float(hs0.y);
        float rs1 = __half2float(hs1.x) + __half2float(hs1.y);
        rs0 += __shfl_xor_sync(~0u, rs0, 1);
        rs0 += __shfl_xor_sync(~0u, rs0, 2);
        rs1 += __shfl_xor_sync(~0u, rs1, 1);
        rs1 += __shfl_xor_sync(~0u, rs1, 2);
        if ((lane & 3) == 0) {
            atomicAdd(lrow + r0 + mt * 16,     rs0);
            atomicAdd(lrow + r0 + mt * 16 + 8, rs1);
        }
    }
}

// ---------- O = P V (wide 256B chunks) then normalize ----------
// stage: P 32K @0 (two 16K) | V 64K @32768 (two 32K) = 96K; x2 = 192K
__global__ void __launch_bounds__(256, 1) pv_gemm_kernel() {
    extern __shared__ char smem[];
    const uint32_t sb = smem_u32(smem);
    const int tid = threadIdx.x, lane = tid & 31, wid = tid >> 5;
    const int wm = wid & 1, wn = wid >> 1;   // 2 x 4 warps
    const int b = blockIdx.x & 3, i0 = (blockIdx.x >> 2) * 128;

    const char* Ap = (const char*)(g_p + ((size_t)b * NPIX + i0) * NPIX);
    const char* Bh = (const char*)(g_v16h + (size_t)b * CH * NPIX);
    const long pB = NPIX * 2;

    float acc[4][8][4] = {};
    const int lr = lane & 15, lc = (lane >> 4) * 16;

    cp_rows2(sb,         Ap, pB, 128);
    cp_rows2(sb + 32768, Bh, pB, 256);
    asm volatile("cp.async.commit_group;" ::: "memory");

    for (int ch = 0; ch < 32; ch++) {
        const uint32_t stb = sb + (ch & 1) * 98304;
        if (ch + 1 < 32) {
            const uint32_t nstb = sb + ((ch + 1) & 1) * 98304;
            const long k0 = (long)(ch + 1) * 256;
            cp_rows2(nstb,         Ap + k0, pB, 128);
            cp_rows2(nstb + 32768, Bh + k0, pB, 256);
            asm volatile("cp.async.commit_group;" ::: "memory");
            asm volatile("cp.async.wait_group 1;" ::: "memory");
        } else {
            asm volatile("cp.async.wait_group 0;" ::: "memory");
        }
        __syncthreads();
        #pragma unroll
        for (int kk = 0; kk < 8; kk++) {
            const int kb = (kk & 3) * 32;
            const uint32_t ah = (kk >> 2) * 16384;
            const uint32_t bh = (kk >> 2) * 32768;
            uint32_t a[4][4];
            #pragma unroll
            for (int mt = 0; mt < 4; mt++)
                ldm4(a[mt], stb + ah + SWZ((wm * 64 + mt * 16 + lr) * 128 + kb + lc));
            #pragma unroll
            for (int np = 0; np < 4; np++) {
                uint32_t b4[4];
                ldm4(b4, stb + 32768 + bh + SWZ((wn * 64 + np * 16 + lr) * 128 + kb + lc));
                uint32_t b0[2] = {b4[0], b4[2]}, b1[2] = {b4[1], b4[3]};
                #pragma unroll
                for (int mt = 0; mt < 4; mt++) {
                    mma16816h(acc[mt][np * 2],     a[mt], b0);
                    mma16816h(acc[mt][np * 2 + 1], a[mt], b1);
                }
            }
        }
        __syncthreads();
    }

    __half* o16 = g_o16 + ((size_t)b * NPIX + i0) * CH;
    const float* lrow = g_l + (size_t)b * NPIX + i0;
    const int r0 = wm * 64 + (lane >> 2), c0 = wn * 64 + (lane & 3) * 2;
    #pragma unroll
    for (int mt = 0; mt < 4; mt++) {
        const float inv0 = 1.f / lrow[r0 + mt * 16];
        const float inv1 = 1.f / lrow[r0 + mt * 16 + 8];
        #pragma unroll
        for (int nt = 0; nt < 8; nt++) {
            const int rr = r0 + mt * 16, cc = c0 + nt * 8;
            __half2 h0, h1;
            h0.x = __float2half_rn(acc[mt][nt][0] * inv0);
            h0.y = __float2half_rn(acc[mt][nt][1] * inv0);
            h1.x = __float2half_rn(acc[mt][nt][2] * inv1);
            h1.y = __float2half_rn(acc[mt][nt][3] * inv1);
            *(__half2*)(o16 + (size_t)rr * CH + cc)       = h0;
            *(__half2*)(o16 + (size_t)(rr + 8) * CH + cc) = h1;
        }
    }
}

// ---------- out = proj_w * O + proj_b + x ----------
__global__ void __launch_bounds__(256, 2) proj_hmma(const float* __restrict__ proj_b,
                                                    const float* __restrict__ x,
                                                    float* __restrict__ out) {
    extern __shared__ char smem[];
    const uint32_t sb = smem_u32(smem);
    const int tid = threadIdx.x, lane = tid & 31, wid = tid >> 5;
    const int wm = wid & 3, wn = wid >> 2;
    const int b = blockIdx.z, n0 = blockIdx.x * 128, o0 = blockIdx.y * 128;

    const char* A = (const char*)(g_wp16 + (size_t)o0 * CH);
    const char* B = (const char*)(g_o16 + ((size_t)b * NPIX + n0) * CH);

    float acc[2][8][4] = {};
    pipeline1(sb, A, B, CH * 2, 4, acc, wm, wn, lane);

    const int r0 = wm * 32 + (lane >> 2), c0 = wn * 64 + (lane & 3) * 2;
    #pragma unroll
    for (int mt = 0; mt < 2; mt++) {
        const int r  = o0 + r0 + mt * 16;
        const float b0 = proj_b[r], b1 = proj_b[r + 8];
        #pragma unroll
        for (int nt = 0; nt < 8; nt++) {
            const size_t idx0 = ((size_t)b * CH + r) * NPIX + n0 + c0 + nt * 8;
            const size_t idx1 = idx0 + (size_t)8 * NPIX;
            float2 x0 = *(const float2*)(x + idx0);
            float2 x1 = *(const float2*)(x + idx1);
            *(float2*)(out + idx0) = make_float2(acc[mt][nt][0] + b0 + x0.x,
                                                 acc[mt][nt][1] + b0 + x0.y);
            *(float2*)(out + idx1) = make_float2(acc[mt][nt][2] + b1 + x1.x,
                                                 acc[mt][nt][3] + b1 + x1.y);
        }
    }
}

// ---------- launch ----------
extern "C" void kernel_launch(void* const* d_in, const int* in_sizes, int n_in,
                              void* d_out, int out_size) {
    const float* x      = (const float*)d_in[0];
    const float* gn_w   = (const float*)d_in[1];
    const float* gn_b   = (const float*)d_in[2];
    const float* qkv_w  = (const float*)d_in[3];
    const float* qkv_b  = (const float*)d_in[4];
    const float* proj_w = (const float*)d_in[5];
    const float* proj_b = (const float*)d_in[6];
    float* out = (float*)d_out;

    cudaFuncSetAttribute(qkv_hmma,      cudaFuncAttributeMaxDynamicSharedMemorySize, 69632);
    cudaFuncSetAttribute(proj_hmma,     cudaFuncAttributeMaxDynamicSharedMemorySize, 65536);
    cudaFuncSetAttribute(s_gemm_kernel, cudaFuncAttributeMaxDynamicSharedMemorySize, 196608);
    cudaFuncSetAttribute(pv_gemm_kernel,cudaFuncAttributeMaxDynamicSharedMemorySize, 196608);

    w_convert<<<256, 256>>>(qkv_w, proj_w);
    gn_kernel<<<BATCH * 32, 256>>>(x, gn_w, gn_b);
    {
        dim3 g(NPIX / 32, CH / 32, BATCH);
        h_convert<<<g, 256>>>();
    }
    {
        dim3 g(NPIX / 128, 6, BATCH);
        qkv_hmma<<<g, 256, 69632>>>(qkv_b);
    }
    {
        dim3 g(NPIX / 128, NPIX / 256, BATCH);
        s_gemm_kernel<<<g, 256, 196608>>>();
    }
    pv_gemm_kernel<<<(NPIX / 128) * BATCH, 256, 196608>>>();
    {
        dim3 g(NPIX / 128, 2, BATCH);
        proj_hmma<<<g, 256, 65536>>>(proj_b, x, out);
    }
}

// round 15
// speedup vs baseline: 2.2910x; 1.0125x over previous
#include <cuda_runtime.h>
#include <cuda_fp16.h>
#include <math.h>
#include <stdint.h>

#define BATCH 4
#define CH    256
#define NPIX  4096
#define CPG   8
#define QSC   (0.0625f * 1.44269504f)

__device__ __half g_h16c[(size_t)BATCH * CH * NPIX];
__device__ __half g_h16 [(size_t)BATCH * NPIX * CH];
__device__ __half g_wq16[3 * CH * CH];
__device__ __half g_wp16[CH * CH];
__device__ __half g_q16[(size_t)BATCH * NPIX * CH];
__device__ __half g_k16[(size_t)BATCH * NPIX * CH];
__device__ __half g_v16h[(size_t)BATCH * CH * NPIX];
__device__ __half g_p [(size_t)BATCH * NPIX * NPIX];
__device__ float g_l [BATCH * NPIX];

#define SWZ(o) ((o) ^ (((o) >> 3) & 0x70))

__device__ __forceinline__ uint32_t smem_u32(const void* p) {
    uint32_t a;
    asm("{ .reg .u64 t; cvta.to.shared.u64 t, %1; cvt.u32.u64 %0, t; }" : "=r"(a) : "l"(p));
    return a;
}
__device__ __forceinline__ void cp16(uint32_t dst, const void* src) {
    asm volatile("cp.async.cg.shared.global [%0], [%1], 16;" :: "r"(dst), "l"(src) : "memory");
}
__device__ __forceinline__ void ldm4(uint32_t* r, uint32_t addr) {
    asm volatile("ldmatrix.sync.aligned.m8n8.x4.shared.b16 {%0,%1,%2,%3}, [%4];"
                 : "=r"(r[0]), "=r"(r[1]), "=r"(r[2]), "=r"(r[3]) : "r"(addr));
}
__device__ __forceinline__ void mma16816h(float* c, const uint32_t* a, const uint32_t* b) {
    asm volatile("mma.sync.aligned.m16n8k16.row.col.f32.f16.f16.f32 "
                 "{%0,%1,%2,%3}, {%4,%5,%6,%7}, {%8,%9}, {%0,%1,%2,%3};"
                 : "+f"(c[0]), "+f"(c[1]), "+f"(c[2]), "+f"(c[3])
                 : "r"(a[0]), "r"(a[1]), "r"(a[2]), "r"(a[3]), "r"(b[0]), "r"(b[1]));
}
__device__ __forceinline__ uint32_t ex2h2(uint32_t x) {
    uint32_t r;
    asm("ex2.approx.f16x2 %0, %1;" : "=r"(r) : "r"(x));
    return r;
}

__device__ __forceinline__ void cp_rows(uint32_t dst, const char* src, long pitchB, int rows) {
    for (int idx = threadIdx.x; idx < rows * 8; idx += blockDim.x) {
        const int r = idx >> 3, cg = idx & 7;
        cp16(dst + SWZ(r * 128 + cg * 16), src + (long)r * pitchB + cg * 16);
    }
}
__device__ __forceinline__ void cp_rows2(uint32_t dst, const char* src, long pitchB, int rows) {
    for (int idx = threadIdx.x; idx < rows * 16; idx += blockDim.x) {
        const int r = idx >> 4, cg = idx & 15;
        const uint32_t off = ((cg & 8) ? (uint32_t)rows * 128 : 0u) + SWZ(r * 128 + (cg & 7) * 16);
        cp16(dst + off, src + (long)r * pitchB + cg * 16);
    }
}

// ========== single-fp16 core, CTA 128x128, warp 32x64 (8 warps) ==========
__device__ __forceinline__ void mma_chunk1(uint32_t sA, uint32_t sB,
                                           float (&acc)[2][8][4], int wm, int wn, int lane) {
    const int lr = lane & 15, lc = (lane >> 4) * 16;
    #pragma unroll
    for (int kk = 0; kk < 4; kk++) {
        const int kb = kk * 32;
        uint32_t a[2][4];
        #pragma unroll
        for (int mt = 0; mt < 2; mt++)
            ldm4(a[mt], sA + SWZ((wm * 32 + mt * 16 + lr) * 128 + kb + lc));
        #pragma unroll
        for (int np = 0; np < 4; np++) {
            uint32_t b4[4];
            ldm4(b4, sB + SWZ((wn * 64 + np * 16 + lr) * 128 + kb + lc));
            uint32_t b0[2] = {b4[0], b4[2]}, b1[2] = {b4[1], b4[3]};
            #pragma unroll
            for (int mt = 0; mt < 2; mt++) {
                mma16816h(acc[mt][np * 2],     a[mt], b0);
                mma16816h(acc[mt][np * 2 + 1], a[mt], b1);
            }
        }
    }
}

// ---------- GroupNorm -> fp16 [c][n] ----------
__global__ void __launch_bounds__(256) gn_kernel(const float* __restrict__ x,
                                                 const float* __restrict__ w,
                                                 const float* __restrict__ bias) {
    const int b = blockIdx.x >> 5, g = blockIdx.x & 31;
    const float* xp = x + (b * CH + g * CPG) * NPIX;
    __half*      hp = g_h16c + ((size_t)b * CH + g * CPG) * NPIX;
    const int NE = CPG * NPIX;
    float s = 0.f, ss = 0.f;
    const float4* x4 = (const float4*)xp;
    for (int i = threadIdx.x; i < NE / 4; i += 256) {
        float4 v = x4[i];
        s  += v.x + v.y + v.z + v.w;
        ss += v.x * v.x + v.y * v.y + v.z * v.z + v.w * v.w;
    }
    __shared__ float rs[32], rss[32];
    #pragma unroll
    for (int o = 16; o; o >>= 1) {
        s  += __shfl_xor_sync(~0u, s,  o);
        ss += __shfl_xor_sync(~0u, ss, o);
    }
    const int lane = threadIdx.x & 31, wid = threadIdx.x >> 5;
    if (lane == 0) { rs[wid] = s; rss[wid] = ss; }
    __syncthreads();
    if (wid == 0) {
        s  = (lane < 8) ? rs[lane]  : 0.f;
        ss = (lane < 8) ? rss[lane] : 0.f;
        #pragma unroll
        for (int o = 16; o; o >>= 1) {
            s  += __shfl_xor_sync(~0u, s,  o);
            ss += __shfl_xor_sync(~0u, ss, o);
        }
        if (lane == 0) { rs[0] = s; rss[0] = ss; }
    }
    __syncthreads();
    const float mu   = rs[0] / (float)NE;
    const float rstd = rsqrtf(rss[0] / (float)NE - mu * mu + 1e-5f);
    for (int i = threadIdx.x; i < NE / 4; i += 256) {
        const int c = g * CPG + (i >> 10);
        const float wc = w[c] * rstd, bc = bias[c] - mu * wc;
        float4 v = x4[i];
        __half2 h0, h1;
        h0.x = __float2half_rn(v.x * wc + bc); h0.y = __float2half_rn(v.y * wc + bc);
        h1.x = __float2half_rn(v.z * wc + bc); h1.y = __float2half_rn(v.w * wc + bc);
        *(__half2*)(hp + i * 4)     = h0;
        *(__half2*)(hp + i * 4 + 2) = h1;
    }
}

// ---------- h: [c][n] fp16 -> [n][c] fp16 ----------
__global__ void __launch_bounds__(256) h_convert() {
    __shared__ float t[32][33];
    const int n0 = blockIdx.x * 32, c0 = blockIdx.y * 32, b = blockIdx.z;
    const __half* src = g_h16c + ((size_t)b * CH + c0) * NPIX + n0;
    const int tx = threadIdx.x & 31, ty = threadIdx.x >> 5;
    #pragma unroll
    for (int j = 0; j < 4; j++)
        t[ty + 8 * j][tx] = __half2float(src[(size_t)(ty + 8 * j) * NPIX + tx]);
    __syncthreads();
    const size_t dbase = ((size_t)b * NPIX + n0) * CH + c0;
    #pragma unroll
    for (int j = 0; j < 4; j++)
        g_h16[dbase + (size_t)(ty + 8 * j) * CH + tx] = __float2half_rn(t[tx][ty + 8 * j]);
}

// ---------- weight -> fp16 (also zeroes g_l) ----------
__global__ void __launch_bounds__(256) w_convert(const float* __restrict__ qkv_w,
                                                 const float* __restrict__ proj_w) {
    if (blockIdx.x < 64)
        g_l[blockIdx.x * 256 + threadIdx.x] = 0.f;
    const int f4 = blockIdx.x * 256 + threadIdx.x;
    const float* src;
    __half* d;
    size_t e;
    if (f4 < 49152) { src = qkv_w;  d = g_wq16; e = (size_t)f4 * 4; }
    else            { src = proj_w; d = g_wp16; e = (size_t)(f4 - 49152) * 4; }
    float4 v = *(const float4*)(src + e);
    __half2 h0, h1;
    h0.x = __float2half_rn(v.x); h0.y = __float2half_rn(v.y);
    h1.x = __float2half_rn(v.z); h1.y = __float2half_rn(v.w);
    *(__half2*)(d + e)     = h0;
    *(__half2*)(d + e + 2) = h1;
}

// ---------- QKV = W*H (3-stage pipeline, 2 CTAs/SM) ----------
__global__ void __launch_bounds__(256, 2) qkv_hmma(const float* __restrict__ qkv_b) {
    extern __shared__ char smem[];
    const uint32_t sb = smem_u32(smem);
    const int tid = threadIdx.x, lane = tid & 31, wid = tid >> 5;
    const int wm = wid & 3, wn = wid >> 2;
    const int b = blockIdx.z, n0 = blockIdx.x * 128, o0 = blockIdx.y * 128;

    const char* A = (const char*)(g_wq16 + (size_t)o0 * CH);
    const char* B = (const char*)(g_h16 + ((size_t)b * NPIX + n0) * CH);
    const long pB = CH * 2;

    float acc[2][8][4] = {};
    // 3-stage: stages at 0 / 32K / 64K (A 16K + B 16K each)
    cp_rows(sb,         A, pB, 128);
    cp_rows(sb + 16384, B, pB, 128);
    asm volatile("cp.async.commit_group;" ::: "memory");
    cp_rows(sb + 32768,         A + 128, pB, 128);
    cp_rows(sb + 32768 + 16384, B + 128, pB, 128);
    asm volatile("cp.async.commit_group;" ::: "memory");
    for (int ch = 0; ch < 4; ch++) {
        const uint32_t stb = sb + (ch % 3) * 32768;
        if (ch + 2 < 4) {
            const uint32_t nstb = sb + ((ch + 2) % 3) * 32768;
            const long k0 = (long)(ch + 2) * 128;
            cp_rows(nstb,         A + k0, pB, 128);
            cp_rows(nstb + 16384, B + k0, pB, 128);
            asm volatile("cp.async.commit_group;" ::: "memory");
            asm volatile("cp.async.wait_group 2;" ::: "memory");
        } else if (ch + 1 < 4) {
            asm volatile("cp.async.wait_group 1;" ::: "memory");
        } else {
            asm volatile("cp.async.wait_group 0;" ::: "memory");
        }
        __syncthreads();
        mma_chunk1(stb, stb + 16384, acc, wm, wn, lane);
        __syncthreads();
    }

    const int r0 = wm * 32 + (lane >> 2), c0 = wn * 64 + (lane & 3) * 2;
    #pragma unroll
    for (int mt = 0; mt < 2; mt++) {
        const float b0 = qkv_b[o0 + r0 + mt * 16];
        const float b1 = qkv_b[o0 + r0 + mt * 16 + 8];
        #pragma unroll
        for (int nt = 0; nt < 8; nt++) {
            acc[mt][nt][0] += b0; acc[mt][nt][1] += b0;
            acc[mt][nt][2] += b1; acc[mt][nt][3] += b1;
        }
    }

    const int sel = blockIdx.y >> 1;   // 0=q, 1=k, 2=v
    if (sel == 2) {
        __half* vh = g_v16h + ((size_t)b * CH + (o0 - 512)) * NPIX + n0;
        #pragma unroll
        for (int mt = 0; mt < 2; mt++)
            #pragma unroll
            for (int nt = 0; nt < 8; nt++) {
                const int rr = r0 + mt * 16, cc = c0 + nt * 8;
                __half2 h0, h1;
                h0.x = __float2half_rn(acc[mt][nt][0]); h0.y = __float2half_rn(acc[mt][nt][1]);
                h1.x = __float2half_rn(acc[mt][nt][2]); h1.y = __float2half_rn(acc[mt][nt][3]);
                *(__half2*)(vh + (size_t)rr * NPIX + cc)       = h0;
                *(__half2*)(vh + (size_t)(rr + 8) * NPIX + cc) = h1;
            }
    } else {
        const float sc = sel ? 1.f : QSC;
        float* st = (float*)smem;   // [c 128][n 132]
        __syncthreads();
        #pragma unroll
        for (int mt = 0; mt < 2; mt++)
            #pragma unroll
            for (int nt = 0; nt < 8; nt++) {
                const int rr = r0 + mt * 16, cc = c0 + nt * 8;
                st[(cc)     * 132 + rr]     = acc[mt][nt][0];
                st[(cc + 1) * 132 + rr]     = acc[mt][nt][1];
                st[(cc)     * 132 + rr + 8] = acc[mt][nt][2];
                st[(cc + 1) * 132 + rr + 8] = acc[mt][nt][3];
            }
        __syncthreads();
        __half* dq = (sel ? g_k16 : g_q16) + ((size_t)b * NPIX + n0) * CH + (o0 - sel * 256);
        const int o4 = lane * 4, nb = tid >> 5;
        #pragma unroll
        for (int j = 0; j < 16; j++) {
            const int n = nb + 8 * j;
            float4 v = *(float4*)(st + n * 132 + o4);
            __half2 h0, h1;
            h0.x = __float2half_rn(v.x * sc); h0.y = __float2half_rn(v.y * sc);
            h1.x = __float2half_rn(v.z * sc); h1.y = __float2half_rn(v.w * sc);
            *(__half2*)(dq + (size_t)n * CH + o4)     = h0;
            *(__half2*)(dq + (size_t)n * CH + o4 + 2) = h1;
        }
    }
}

// ---------- P = 2^(Q K^T) (wide 256B chunks) + row-sum atomics ----------
__global__ void __launch_bounds__(256, 1) s_gemm_kernel() {
    extern __shared__ char smem[];
    const uint32_t sb = smem_u32(smem);
    const int tid = threadIdx.x, lane = tid & 31, wid = tid >> 5;
    const int wm = wid & 3, wn = wid >> 2;   // 4 x 2 warps
    const int b = blockIdx.z, i0 = blockIdx.y * 256, j0 = blockIdx.x * 128;

    const char* Aq = (const char*)(g_q16 + ((size_t)b * NPIX + i0) * CH);
    const char* Bk = (const char*)(g_k16 + ((size_t)b * NPIX + j0) * CH);
    const long pB = CH * 2;

    float acc[4][8][4] = {};
    const int lr = lane & 15, lc = (lane >> 4) * 16;

    cp_rows2(sb,         Aq, pB, 256);
    cp_rows2(sb + 65536, Bk, pB, 128);
    asm volatile("cp.async.commit_group;" ::: "memory");

    for (int ch = 0; ch < 2; ch++) {
        const uint32_t stb = sb + (ch & 1) * 98304;
        if (ch + 1 < 2) {
            const uint32_t nstb = sb + ((ch + 1) & 1) * 98304;
            cp_rows2(nstb,         Aq + 256, pB, 256);
            cp_rows2(nstb + 65536, Bk + 256, pB, 128);
            asm volatile("cp.async.commit_group;" ::: "memory");
            asm volatile("cp.async.wait_group 1;" ::: "memory");
        } else {
            asm volatile("cp.async.wait_group 0;" ::: "memory");
        }
        __syncthreads();
        #pragma unroll
        for (int kk = 0; kk < 8; kk++) {
            const int kb = (kk & 3) * 32;
            const uint32_t ah = (kk >> 2) * 32768;
            const uint32_t bh = (kk >> 2) * 16384;
            uint32_t a[4][4];
            #pragma unroll
            for (int mt = 0; mt < 4; mt++)
                ldm4(a[mt], stb + ah + SWZ((wm * 64 + mt * 16 + lr) * 128 + kb + lc));
            #pragma unroll
            for (int np = 0; np < 4; np++) {
                uint32_t b4[4];
                ldm4(b4, stb + 65536 + bh + SWZ((wn * 64 + np * 16 + lr) * 128 + kb + lc));
                uint32_t b0[2] = {b4[0], b4[2]}, b1[2] = {b4[1], b4[3]};
                #pragma unroll
                for (int mt = 0; mt < 4; mt++) {
                    mma16816h(acc[mt][np * 2],     a[mt], b0);
                    mma16816h(acc[mt][np * 2 + 1], a[mt], b1);
                }
            }
        }
        __syncthreads();
    }

    __half* Pb = g_p + ((size_t)b * NPIX + i0) * NPIX + j0;
    float* lrow = g_l + (size_t)b * NPIX + i0;
    const int r0 = wm * 64 + (lane >> 2), c0 = wn * 64 + (lane & 3) * 2;
    #pragma unroll
    for (int mt = 0; mt < 4; mt++) {
        __half2 hs0 = __floats2half2_rn(0.f, 0.f);
        __half2 hs1 = __floats2half2_rn(0.f, 0.f);
        #pragma unroll
        for (int nt = 0; nt < 8; nt++) {
            __half2 x01 = __floats2half2_rn(acc[mt][nt][0], acc[mt][nt][1]);
            __half2 x23 = __floats2half2_rn(acc[mt][nt][2], acc[mt][nt][3]);
            const uint32_t e01 = ex2h2(*(uint32_t*)&x01);
            const uint32_t e23 = ex2h2(*(uint32_t*)&x23);
            hs0 = __hadd2(hs0, *(const __half2*)&e01);
            hs1 = __hadd2(hs1, *(const __half2*)&e23);
            __half* p = Pb + (size_t)(r0 + mt * 16) * NPIX + c0 + nt * 8;
            *(uint32_t*)p = e01;
            *(uint32_t*)(p + (size_t)8 * NPIX) = e23;
        }
        float rs0 = __half2float(hs0.x) + __half2float(hs0.y);
        float rs1 = __half2float(hs1.x) + __half2float(hs1.y);
        rs0 += __shfl_xor_sync(~0u, rs0, 1);
        rs0 += __shfl_xor_sync(~0u, rs0, 2);
        rs1 += __shfl_xor_sync(~0u, rs1, 1);
        rs1 += __shfl_xor_sync(~0u, rs1, 2);
        if ((lane & 3) == 0) {
            atomicAdd(lrow + r0 + mt * 16,     rs0);
            atomicAdd(lrow + r0 + mt * 16 + 8, rs1);
        }
    }
}

// ---------- O = P V, normalize, then out = Wp*O^T + b + x (fused) ----------
// phase1 smem: stages at 0 / 98304 (P 32K + V 64K each)
// phase2 smem: O 128K @0 (four 32K c-tiles) | Wp stages @131072, @163840 (32K each)
__global__ void __launch_bounds__(256, 1) pv_proj_kernel(const float* __restrict__ proj_b,
                                                         const float* __restrict__ x,
                                                         float* __restrict__ out) {
    extern __shared__ char smem[];
    const uint32_t sb = smem_u32(smem);
    const int tid = threadIdx.x, lane = tid & 31, wid = tid >> 5;
    const int b = blockIdx.x & 3, i0 = (blockIdx.x >> 2) * 128;
    const int lr = lane & 15, lc = (lane >> 4) * 16;

    // ===== phase 1: O = P V =====
    {
        const int wm = wid & 1, wn = wid >> 1;   // 2 x 4 warps
        const char* Ap = (const char*)(g_p + ((size_t)b * NPIX + i0) * NPIX);
        const char* Bh = (const char*)(g_v16h + (size_t)b * CH * NPIX);
        const long pB = NPIX * 2;

        float acc[4][8][4] = {};

        cp_rows2(sb,         Ap, pB, 128);
        cp_rows2(sb + 32768, Bh, pB, 256);
        asm volatile("cp.async.commit_group;" ::: "memory");

        for (int ch = 0; ch < 32; ch++) {
            const uint32_t stb = sb + (ch & 1) * 98304;
            if (ch + 1 < 32) {
                const uint32_t nstb = sb + ((ch + 1) & 1) * 98304;
                const long k0 = (long)(ch + 1) * 256;
                cp_rows2(nstb,         Ap + k0, pB, 128);
                cp_rows2(nstb + 32768, Bh + k0, pB, 256);
                asm volatile("cp.async.commit_group;" ::: "memory");
                asm volatile("cp.async.wait_group 1;" ::: "memory");
            } else {
                asm volatile("cp.async.wait_group 0;" ::: "memory");
            }
            __syncthreads();
            #pragma unroll
            for (int kk = 0; kk < 8; kk++) {
                const int kb = (kk & 3) * 32;
                const uint32_t ah = (kk >> 2) * 16384;
                const uint32_t bh = (kk >> 2) * 32768;
                uint32_t a[4][4];
                #pragma unroll
                for (int mt = 0; mt < 4; mt++)
                    ldm4(a[mt], stb + ah + SWZ((wm * 64 + mt * 16 + lr) * 128 + kb + lc));
                #pragma unroll
                for (int np = 0; np < 4; np++) {
                    uint32_t b4[4];
                    ldm4(b4, stb + 32768 + bh + SWZ((wn * 64 + np * 16 + lr) * 128 + kb + lc));
                    uint32_t b0[2] = {b4[0], b4[2]}, b1[2] = {b4[1], b4[3]};
                    #pragma unroll
                    for (int mt = 0; mt < 4; mt++) {
                        mma16816h(acc[mt][np * 2],     a[mt], b0);
                        mma16816h(acc[mt][np * 2 + 1], a[mt], b1);
                    }
                }
            }
            __syncthreads();
        }

        // normalize and deposit O into smem: tile wn (64 channels) @ wn*32768, row n, SW128
        const float* lrow = g_l + (size_t)b * NPIX + i0;
        const int r0 = wm * 64 + (lane >> 2), c0l = (lane & 3) * 2;
        __syncthreads();   // all reads of stage smem done; safe to overwrite with O
        #pragma unroll
        for (int mt = 0; mt < 4; mt++) {
            const float inv0 = 1.f / lrow[r0 + mt * 16];
            const float inv1 = 1.f / lrow[r0 + mt * 16 + 8];
            #pragma unroll
            for (int nt = 0; nt < 8; nt++) {
                const int rr = r0 + mt * 16;
                const int ccl = nt * 8 + c0l;    // col within 64-wide tile
                __half2 h0, h1;
                h0.x = __float2half_rn(acc[mt][nt][0] * inv0);
                h0.y = __float2half_rn(acc[mt][nt][1] * inv0);
                h1.x = __float2half_rn(acc[mt][nt][2] * inv1);
                h1.y = __float2half_rn(acc[mt][nt][3] * inv1);
                *(__half2*)(smem + wn * 32768 + SWZ(rr * 128 + ccl * 2))       = h0;
                *(__half2*)(smem + wn * 32768 + SWZ((rr + 8) * 128 + ccl * 2)) = h1;
            }
        }
    }
    __syncthreads();

    // ===== phase 2: out = Wp * O^T + b + x =====
    {
        const int wm = wid & 3, wn = wid >> 2;   // 4 x 2 warps (M=256 o, N=128 n)
        float acc[4][4][4] = {};                 // warp 64x32? no: warp 64(o) x 64(n) -> [4][8][4]
        float acc2[4][8][4] = {};

        // Wp chunks over c: 4 chunks of 64 (256 rows x 128B), double-buffered
        cp_rows(sb + 131072, (const char*)g_wp16, CH * 2, 256);
        asm volatile("cp.async.commit_group;" ::: "memory");
        for (int ck = 0; ck < 4; ck++) {
            const uint32_t wst = sb + 131072 + (ck & 1) * 32768;
            if (ck + 1 < 4) {
                const uint32_t nwst = sb + 131072 + ((ck + 1) & 1) * 32768;
                cp_rows(nwst, (const char*)g_wp16 + (ck + 1) * 128, CH * 2, 256);
                asm volatile("cp.async.commit_group;" ::: "memory");
                asm volatile("cp.async.wait_group 1;" ::: "memory");
            } else {
                asm volatile("cp.async.wait_group 0;" ::: "memory");
            }
            __syncthreads();
            #pragma unroll
            for (int kk = 0; kk < 4; kk++) {
                const int kb = kk * 32;
                uint32_t a[4][4];
                #pragma unroll
                for (int mt = 0; mt < 4; mt++)
                    ldm4(a[mt], wst + SWZ((wm * 64 + mt * 16 + lr) * 128 + kb + lc));
                #pragma unroll
                for (int np = 0; np < 4; np++) {
                    uint32_t b4[4];
                    ldm4(b4, sb + ck * 32768 + SWZ((wn * 64 + np * 16 + lr) * 128 + kb + lc));
                    uint32_t b0[2] = {b4[0], b4[2]}, b1[2] = {b4[1], b4[3]};
                    #pragma unroll
                    for (int mt = 0; mt < 4; mt++) {
                        mma16816h(acc2[mt][np * 2],     a[mt], b0);
                        mma16816h(acc2[mt][np * 2 + 1], a[mt], b1);
                    }
                }
            }
            __syncthreads();
        }
        (void)acc;

        const int r0 = wm * 64 + (lane >> 2), c0 = wn * 64 + (lane & 3) * 2;
        #pragma unroll
        for (int mt = 0; mt < 4; mt++) {
            const int o  = r0 + mt * 16;
            const float b0 = proj_b[o], b1 = proj_b[o + 8];
            #pragma unroll
            for (int nt = 0; nt < 8; nt++) {
                const size_t idx0 = ((size_t)b * CH + o) * NPIX + i0 + c0 + nt * 8;
                const size_t idx1 = idx0 + (size_t)8 * NPIX;
                float2 x0 = *(const float2*)(x + idx0);
                float2 x1 = *(const float2*)(x + idx1);
                *(float2*)(out + idx0) = make_float2(acc2[mt][nt][0] + b0 + x0.x,
                                                     acc2[mt][nt][1] + b0 + x0.y);
                *(float2*)(out + idx1) = make_float2(acc2[mt][nt][2] + b1 + x1.x,
                                                     acc2[mt][nt][3] + b1 + x1.y);
            }
        }
    }
}

// ---------- launch ----------
extern "C" void kernel_launch(void* const* d_in, const int* in_sizes, int n_in,
                              void* d_out, int out_size) {
    const float* x      = (const float*)d_in[0];
    const float* gn_w   = (const float*)d_in[1];
    const float* gn_b   = (const float*)d_in[2];
    const float* qkv_w  = (const float*)d_in[3];
    const float* qkv_b  = (const float*)d_in[4];
    const float* proj_w = (const float*)d_in[5];
    const float* proj_b = (const float*)d_in[6];
    float* out = (float*)d_out;

    cudaFuncSetAttribute(qkv_hmma,       cudaFuncAttributeMaxDynamicSharedMemorySize, 98304);
    cudaFuncSetAttribute(s_gemm_kernel,  cudaFuncAttributeMaxDynamicSharedMemorySize, 196608);
    cudaFuncSetAttribute(pv_proj_kernel, cudaFuncAttributeMaxDynamicSharedMemorySize, 196608);

    w_convert<<<256, 256>>>(qkv_w, proj_w);
    gn_kernel<<<BATCH * 32, 256>>>(x, gn_w, gn_b);
    {
        dim3 g(NPIX / 32, CH / 32, BATCH);
        h_convert<<<g, 256>>>();
    }
    {
        dim3 g(NPIX / 128, 6, BATCH);
        qkv_hmma<<<g, 256, 98304>>>(qkv_b);
    }
    {
        dim3 g(NPIX / 128, NPIX / 256, BATCH);
        s_gemm_kernel<<<g, 256, 196608>>>();
    }
    pv_proj_kernel<<<(NPIX / 128) * BATCH, 256, 196608>>>(proj_b, x, out);
}

// round 16
// speedup vs baseline: 2.3347x; 1.0191x over previous
#include <cuda_runtime.h>
#include <cuda_fp16.h>
#include <math.h>
#include <stdint.h>

#define BATCH 4
#define CH    256
#define NPIX  4096
#define CPG   8
#define QSC   (0.0625f * 1.44269504f)

__device__ __half g_h16c[(size_t)BATCH * CH * NPIX];
__device__ __half g_h16 [(size_t)BATCH * NPIX * CH];
__device__ __half g_wq16[3 * CH * CH];
__device__ __half g_wp16[CH * CH];
__device__ __half g_q16[(size_t)BATCH * NPIX * CH];
__device__ __half g_k16[(size_t)BATCH * NPIX * CH];
__device__ __half g_v16h[(size_t)BATCH * CH * NPIX];
__device__ __half g_p [(size_t)BATCH * NPIX * NPIX];
__device__ float g_l [BATCH * NPIX];

#define SWZ(o) ((o) ^ (((o) >> 3) & 0x70))

__device__ __forceinline__ uint32_t smem_u32(const void* p) {
    uint32_t a;
    asm("{ .reg .u64 t; cvta.to.shared.u64 t, %1; cvt.u32.u64 %0, t; }" : "=r"(a) : "l"(p));
    return a;
}
__device__ __forceinline__ void cp16(uint32_t dst, const void* src) {
    asm volatile("cp.async.cg.shared.global [%0], [%1], 16;" :: "r"(dst), "l"(src) : "memory");
}
__device__ __forceinline__ void ldm4(uint32_t* r, uint32_t addr) {
    asm volatile("ldmatrix.sync.aligned.m8n8.x4.shared.b16 {%0,%1,%2,%3}, [%4];"
                 : "=r"(r[0]), "=r"(r[1]), "=r"(r[2]), "=r"(r[3]) : "r"(addr));
}
__device__ __forceinline__ void mma16816h(float* c, const uint32_t* a, const uint32_t* b) {
    asm volatile("mma.sync.aligned.m16n8k16.row.col.f32.f16.f16.f32 "
                 "{%0,%1,%2,%3}, {%4,%5,%6,%7}, {%8,%9}, {%0,%1,%2,%3};"
                 : "+f"(c[0]), "+f"(c[1]), "+f"(c[2]), "+f"(c[3])
                 : "r"(a[0]), "r"(a[1]), "r"(a[2]), "r"(a[3]), "r"(b[0]), "r"(b[1]));
}
__device__ __forceinline__ uint32_t ex2h2(uint32_t x) {
    uint32_t r;
    asm("ex2.approx.f16x2 %0, %1;" : "=r"(r) : "r"(x));
    return r;
}

__device__ __forceinline__ void cp_rows(uint32_t dst, const char* src, long pitchB, int rows) {
    for (int idx = threadIdx.x; idx < rows * 8; idx += blockDim.x) {
        const int r = idx >> 3, cg = idx & 7;
        cp16(dst + SWZ(r * 128 + cg * 16), src + (long)r * pitchB + cg * 16);
    }
}
__device__ __forceinline__ void cp_rows2(uint32_t dst, const char* src, long pitchB, int rows) {
    for (int idx = threadIdx.x; idx < rows * 16; idx += blockDim.x) {
        const int r = idx >> 4, cg = idx & 15;
        const uint32_t off = ((cg & 8) ? (uint32_t)rows * 128 : 0u) + SWZ(r * 128 + (cg & 7) * 16);
        cp16(dst + off, src + (long)r * pitchB + cg * 16);
    }
}

// ========== single-fp16 core, CTA 128x128, warp 32x64 (8 warps) ==========
__device__ __forceinline__ void mma_chunk1(uint32_t sA, uint32_t sB,
                                           float (&acc)[2][8][4], int wm, int wn, int lane) {
    const int lr = lane & 15, lc = (lane >> 4) * 16;
    #pragma unroll
    for (int kk = 0; kk < 4; kk++) {
        const int kb = kk * 32;
        uint32_t a[2][4];
        #pragma unroll
        for (int mt = 0; mt < 2; mt++)
            ldm4(a[mt], sA + SWZ((wm * 32 + mt * 16 + lr) * 128 + kb + lc));
        #pragma unroll
        for (int np = 0; np < 4; np++) {
            uint32_t b4[4];
            ldm4(b4, sB + SWZ((wn * 64 + np * 16 + lr) * 128 + kb + lc));
            uint32_t b0[2] = {b4[0], b4[2]}, b1[2] = {b4[1], b4[3]};
            #pragma unroll
            for (int mt = 0; mt < 2; mt++) {
                mma16816h(acc[mt][np * 2],     a[mt], b0);
                mma16816h(acc[mt][np * 2 + 1], a[mt], b1);
            }
        }
    }
}

// ---------- GroupNorm -> fp16 [c][n] (512 threads) ----------
__global__ void __launch_bounds__(512) gn_kernel(const float* __restrict__ x,
                                                 const float* __restrict__ w,
                                                 const float* __restrict__ bias) {
    const int b = blockIdx.x >> 5, g = blockIdx.x & 31;
    const float* xp = x + (b * CH + g * CPG) * NPIX;
    __half*      hp = g_h16c + ((size_t)b * CH + g * CPG) * NPIX;
    const int NE = CPG * NPIX;
    float s = 0.f, ss = 0.f;
    const float4* x4 = (const float4*)xp;
    for (int i = threadIdx.x; i < NE / 4; i += 512) {
        float4 v = x4[i];
        s  += v.x + v.y + v.z + v.w;
        ss += v.x * v.x + v.y * v.y + v.z * v.z + v.w * v.w;
    }
    __shared__ float rs[16], rss[16];
    #pragma unroll
    for (int o = 16; o; o >>= 1) {
        s  += __shfl_xor_sync(~0u, s,  o);
        ss += __shfl_xor_sync(~0u, ss, o);
    }
    const int lane = threadIdx.x & 31, wid = threadIdx.x >> 5;
    if (lane == 0) { rs[wid] = s; rss[wid] = ss; }
    __syncthreads();
    if (wid == 0) {
        s  = (lane < 16) ? rs[lane]  : 0.f;
        ss = (lane < 16) ? rss[lane] : 0.f;
        #pragma unroll
        for (int o = 16; o; o >>= 1) {
            s  += __shfl_xor_sync(~0u, s,  o);
            ss += __shfl_xor_sync(~0u, ss, o);
        }
        if (lane == 0) { rs[0] = s; rss[0] = ss; }
    }
    __syncthreads();
    const float mu   = rs[0] / (float)NE;
    const float rstd = rsqrtf(rss[0] / (float)NE - mu * mu + 1e-5f);
    for (int i = threadIdx.x; i < NE / 4; i += 512) {
        const int c = g * CPG + (i >> 10);
        const float wc = w[c] * rstd, bc = bias[c] - mu * wc;
        float4 v = x4[i];
        __half2 h0, h1;
        h0.x = __float2half_rn(v.x * wc + bc); h0.y = __float2half_rn(v.y * wc + bc);
        h1.x = __float2half_rn(v.z * wc + bc); h1.y = __float2half_rn(v.w * wc + bc);
        *(__half2*)(hp + i * 4)     = h0;
        *(__half2*)(hp + i * 4 + 2) = h1;
    }
}

// ---------- h: [c][n] fp16 -> [n][c] fp16 ----------
__global__ void __launch_bounds__(256) h_convert() {
    __shared__ float t[32][33];
    const int n0 = blockIdx.x * 32, c0 = blockIdx.y * 32, b = blockIdx.z;
    const __half* src = g_h16c + ((size_t)b * CH + c0) * NPIX + n0;
    const int tx = threadIdx.x & 31, ty = threadIdx.x >> 5;
    #pragma unroll
    for (int j = 0; j < 4; j++)
        t[ty + 8 * j][tx] = __half2float(src[(size_t)(ty + 8 * j) * NPIX + tx]);
    __syncthreads();
    const size_t dbase = ((size_t)b * NPIX + n0) * CH + c0;
    #pragma unroll
    for (int j = 0; j < 4; j++)
        g_h16[dbase + (size_t)(ty + 8 * j) * CH + tx] = __float2half_rn(t[tx][ty + 8 * j]);
}

// ---------- weight -> fp16 (also zeroes g_l) ----------
__global__ void __launch_bounds__(256) w_convert(const float* __restrict__ qkv_w,
                                                 const float* __restrict__ proj_w) {
    if (blockIdx.x < 64)
        g_l[blockIdx.x * 256 + threadIdx.x] = 0.f;
    const int f4 = blockIdx.x * 256 + threadIdx.x;
    const float* src;
    __half* d;
    size_t e;
    if (f4 < 49152) { src = qkv_w;  d = g_wq16; e = (size_t)f4 * 4; }
    else            { src = proj_w; d = g_wp16; e = (size_t)(f4 - 49152) * 4; }
    float4 v = *(const float4*)(src + e);
    __half2 h0, h1;
    h0.x = __float2half_rn(v.x); h0.y = __float2half_rn(v.y);
    h1.x = __float2half_rn(v.z); h1.y = __float2half_rn(v.w);
    *(__half2*)(d + e)     = h0;
    *(__half2*)(d + e + 2) = h1;
}

// ---------- QKV = W*H (3-stage pipeline, 2 CTAs/SM) ----------
__global__ void __launch_bounds__(256, 2) qkv_hmma(const float* __restrict__ qkv_b) {
    extern __shared__ char smem[];
    const uint32_t sb = smem_u32(smem);
    const int tid = threadIdx.x, lane = tid & 31, wid = tid >> 5;
    const int wm = wid & 3, wn = wid >> 2;
    const int b = blockIdx.z, n0 = blockIdx.x * 128, o0 = blockIdx.y * 128;

    const char* A = (const char*)(g_wq16 + (size_t)o0 * CH);
    const char* B = (const char*)(g_h16 + ((size_t)b * NPIX + n0) * CH);
    const long pB = CH * 2;

    float acc[2][8][4] = {};
    cp_rows(sb,         A, pB, 128);
    cp_rows(sb + 16384, B, pB, 128);
    asm volatile("cp.async.commit_group;" ::: "memory");
    cp_rows(sb + 32768,         A + 128, pB, 128);
    cp_rows(sb + 32768 + 16384, B + 128, pB, 128);
    asm volatile("cp.async.commit_group;" ::: "memory");
    for (int ch = 0; ch < 4; ch++) {
        const uint32_t stb = sb + (ch % 3) * 32768;
        if (ch + 2 < 4) {
            const uint32_t nstb = sb + ((ch + 2) % 3) * 32768;
            const long k0 = (long)(ch + 2) * 128;
            cp_rows(nstb,         A + k0, pB, 128);
            cp_rows(nstb + 16384, B + k0, pB, 128);
            asm volatile("cp.async.commit_group;" ::: "memory");
            asm volatile("cp.async.wait_group 2;" ::: "memory");
        } else if (ch + 1 < 4) {
            asm volatile("cp.async.wait_group 1;" ::: "memory");
        } else {
            asm volatile("cp.async.wait_group 0;" ::: "memory");
        }
        __syncthreads();
        mma_chunk1(stb, stb + 16384, acc, wm, wn, lane);
        __syncthreads();
    }

    const int r0 = wm * 32 + (lane >> 2), c0 = wn * 64 + (lane & 3) * 2;
    #pragma unroll
    for (int mt = 0; mt < 2; mt++) {
        const float b0 = qkv_b[o0 + r0 + mt * 16];
        const float b1 = qkv_b[o0 + r0 + mt * 16 + 8];
        #pragma unroll
        for (int nt = 0; nt < 8; nt++) {
            acc[mt][nt][0] += b0; acc[mt][nt][1] += b0;
            acc[mt][nt][2] += b1; acc[mt][nt][3] += b1;
        }
    }

    const int sel = blockIdx.y >> 1;   // 0=q, 1=k, 2=v
    if (sel == 2) {
        __half* vh = g_v16h + ((size_t)b * CH + (o0 - 512)) * NPIX + n0;
        #pragma unroll
        for (int mt = 0; mt < 2; mt++)
            #pragma unroll
            for (int nt = 0; nt < 8; nt++) {
                const int rr = r0 + mt * 16, cc = c0 + nt * 8;
                __half2 h0, h1;
                h0.x = __float2half_rn(acc[mt][nt][0]); h0.y = __float2half_rn(acc[mt][nt][1]);
                h1.x = __float2half_rn(acc[mt][nt][2]); h1.y = __float2half_rn(acc[mt][nt][3]);
                *(__half2*)(vh + (size_t)rr * NPIX + cc)       = h0;
                *(__half2*)(vh + (size_t)(rr + 8) * NPIX + cc) = h1;
            }
    } else {
        const float sc = sel ? 1.f : QSC;
        float* st = (float*)smem;   // [c 128][n 132]
        __syncthreads();
        #pragma unroll
        for (int mt = 0; mt < 2; mt++)
            #pragma unroll
            for (int nt = 0; nt < 8; nt++) {
                const int rr = r0 + mt * 16, cc = c0 + nt * 8;
                st[(cc)     * 132 + rr]     = acc[mt][nt][0];
                st[(cc + 1) * 132 + rr]     = acc[mt][nt][1];
                st[(cc)     * 132 + rr + 8] = acc[mt][nt][2];
                st[(cc + 1) * 132 + rr + 8] = acc[mt][nt][3];
            }
        __syncthreads();
        __half* dq = (sel ? g_k16 : g_q16) + ((size_t)b * NPIX + n0) * CH + (o0 - sel * 256);
        const int o4 = lane * 4, nb = tid >> 5;
        #pragma unroll
        for (int j = 0; j < 16; j++) {
            const int n = nb + 8 * j;
            float4 v = *(float4*)(st + n * 132 + o4);
            __half2 h0, h1;
            h0.x = __float2half_rn(v.x * sc); h0.y = __float2half_rn(v.y * sc);
            h1.x = __float2half_rn(v.z * sc); h1.y = __float2half_rn(v.w * sc);
            *(__half2*)(dq + (size_t)n * CH + o4)     = h0;
            *(__half2*)(dq + (size_t)n * CH + o4 + 2) = h1;
        }
    }
}

// ---------- P = 2^(Q K^T) + row-sum atomics; smem-staged coalesced P store ----------
__global__ void __launch_bounds__(256, 1) s_gemm_kernel() {
    extern __shared__ char smem[];
    const uint32_t sb = smem_u32(smem);
    const int tid = threadIdx.x, lane = tid & 31, wid = tid >> 5;
    const int wm = wid & 3, wn = wid >> 2;   // 4 x 2 warps
    const int b = blockIdx.z, i0 = blockIdx.y * 256, j0 = blockIdx.x * 128;

    const char* Aq = (const char*)(g_q16 + ((size_t)b * NPIX + i0) * CH);
    const char* Bk = (const char*)(g_k16 + ((size_t)b * NPIX + j0) * CH);
    const long pB = CH * 2;

    float acc[4][8][4] = {};
    const int lr = lane & 15, lc = (lane >> 4) * 16;

    cp_rows2(sb,         Aq, pB, 256);
    cp_rows2(sb + 65536, Bk, pB, 128);
    asm volatile("cp.async.commit_group;" ::: "memory");

    for (int ch = 0; ch < 2; ch++) {
        const uint32_t stb = sb + (ch & 1) * 98304;
        if (ch + 1 < 2) {
            const uint32_t nstb = sb + ((ch + 1) & 1) * 98304;
            cp_rows2(nstb,         Aq + 256, pB, 256);
            cp_rows2(nstb + 65536, Bk + 256, pB, 128);
            asm volatile("cp.async.commit_group;" ::: "memory");
            asm volatile("cp.async.wait_group 1;" ::: "memory");
        } else {
            asm volatile("cp.async.wait_group 0;" ::: "memory");
        }
        __syncthreads();
        #pragma unroll
        for (int kk = 0; kk < 8; kk++) {
            const int kb = (kk & 3) * 32;
            const uint32_t ah = (kk >> 2) * 32768;
            const uint32_t bh = (kk >> 2) * 16384;
            uint32_t a[4][4];
            #pragma unroll
            for (int mt = 0; mt < 4; mt++)
                ldm4(a[mt], stb + ah + SWZ((wm * 64 + mt * 16 + lr) * 128 + kb + lc));
            #pragma unroll
            for (int np = 0; np < 4; np++) {
                uint32_t b4[4];
                ldm4(b4, stb + 65536 + bh + SWZ((wn * 64 + np * 16 + lr) * 128 + kb + lc));
                uint32_t b0[2] = {b4[0], b4[2]}, b1[2] = {b4[1], b4[3]};
                #pragma unroll
                for (int mt = 0; mt < 4; mt++) {
                    mma16816h(acc[mt][np * 2],     a[mt], b0);
                    mma16816h(acc[mt][np * 2 + 1], a[mt], b1);
                }
            }
        }
        __syncthreads();
    }

    // epilogue: exp into smem tile (pitch 272B), row sums, then coalesced copy-out
    float* lrow = g_l + (size_t)b * NPIX + i0;
    const int r0 = wm * 64 + (lane >> 2), c0 = wn * 64 + (lane & 3) * 2;
    #pragma unroll
    for (int mt = 0; mt < 4; mt++) {
        __half2 hs0 = __floats2half2_rn(0.f, 0.f);
        __half2 hs1 = __floats2half2_rn(0.f, 0.f);
        #pragma unroll
        for (int nt = 0; nt < 8; nt++) {
            __half2 x01 = __floats2half2_rn(acc[mt][nt][0], acc[mt][nt][1]);
            __half2 x23 = __floats2half2_rn(acc[mt][nt][2], acc[mt][nt][3]);
            const uint32_t e01 = ex2h2(*(uint32_t*)&x01);
            const uint32_t e23 = ex2h2(*(uint32_t*)&x23);
            hs0 = __hadd2(hs0, *(const __half2*)&e01);
            hs1 = __hadd2(hs1, *(const __half2*)&e23);
            const int row = r0 + mt * 16;
            const int cb  = (c0 + nt * 8) * 2;
            *(uint32_t*)(smem + row * 272 + cb)       = e01;
            *(uint32_t*)(smem + (row + 8) * 272 + cb) = e23;
        }
        float rs0 = __half2float(hs0.x) + __half2float(hs0.y);
        float rs1 = __half2float(hs1.x) + __half2float(hs1.y);
        rs0 += __shfl_xor_sync(~0u, rs0, 1);
        rs0 += __shfl_xor_sync(~0u, rs0, 2);
        rs1 += __shfl_xor_sync(~0u, rs1, 1);
        rs1 += __shfl_xor_sync(~0u, rs1, 2);
        if ((lane & 3) == 0) {
            atomicAdd(lrow + r0 + mt * 16,     rs0);
            atomicAdd(lrow + r0 + mt * 16 + 8, rs1);
        }
    }
    __syncthreads();
    // coalesced copy-out: 256 rows x 256B
    __half* Pb = g_p + ((size_t)b * NPIX + i0) * NPIX + j0;
    for (int idx = tid; idx < 4096; idx += 256) {
        const int r = idx >> 4, sg = idx & 15;
        uint4 v = *(uint4*)(smem + r * 272 + sg * 16);
        *(uint4*)(Pb + (size_t)r * NPIX + sg * 8) = v;
    }
}

// ---------- O = P V, normalize, then out = Wp*O^T + b + x (fused) ----------
__global__ void __launch_bounds__(256, 1) pv_proj_kernel(const float* __restrict__ proj_b,
                                                         const float* __restrict__ x,
                                                         float* __restrict__ out) {
    extern __shared__ char smem[];
    const uint32_t sb = smem_u32(smem);
    const int tid = threadIdx.x, lane = tid & 31, wid = tid >> 5;
    const int b = blockIdx.x & 3, i0 = (blockIdx.x >> 2) * 128;
    const int lr = lane & 15, lc = (lane >> 4) * 16;

    // ===== phase 1: O = P V =====
    {
        const int wm = wid & 1, wn = wid >> 1;   // 2 x 4 warps
        const char* Ap = (const char*)(g_p + ((size_t)b * NPIX + i0) * NPIX);
        const char* Bh = (const char*)(g_v16h + (size_t)b * CH * NPIX);
        const long pB = NPIX * 2;

        float acc[4][8][4] = {};

        cp_rows2(sb,         Ap, pB, 128);
        cp_rows2(sb + 32768, Bh, pB, 256);
        asm volatile("cp.async.commit_group;" ::: "memory");

        for (int ch = 0; ch < 32; ch++) {
            const uint32_t stb = sb + (ch & 1) * 98304;
            if (ch + 1 < 32) {
                const uint32_t nstb = sb + ((ch + 1) & 1) * 98304;
                const long k0 = (long)(ch + 1) * 256;
                cp_rows2(nstb,         Ap + k0, pB, 128);
                cp_rows2(nstb + 32768, Bh + k0, pB, 256);
                asm volatile("cp.async.commit_group;" ::: "memory");
                asm volatile("cp.async.wait_group 1;" ::: "memory");
            } else {
                asm volatile("cp.async.wait_group 0;" ::: "memory");
            }
            __syncthreads();
            #pragma unroll
            for (int kk = 0; kk < 8; kk++) {
                const int kb = (kk & 3) * 32;
                const uint32_t ah = (kk >> 2) * 16384;
                const uint32_t bh = (kk >> 2) * 32768;
                uint32_t a[4][4];
                #pragma unroll
                for (int mt = 0; mt < 4; mt++)
                    ldm4(a[mt], stb + ah + SWZ((wm * 64 + mt * 16 + lr) * 128 + kb + lc));
                #pragma unroll
                for (int np = 0; np < 4; np++) {
                    uint32_t b4[4];
                    ldm4(b4, stb + 32768 + bh + SWZ((wn * 64 + np * 16 + lr) * 128 + kb + lc));
                    uint32_t b0[2] = {b4[0], b4[2]}, b1[2] = {b4[1], b4[3]};
                    #pragma unroll
                    for (int mt = 0; mt < 4; mt++) {
                        mma16816h(acc[mt][np * 2],     a[mt], b0);
                        mma16816h(acc[mt][np * 2 + 1], a[mt], b1);
                    }
                }
            }
            __syncthreads();
        }

        const float* lrow = g_l + (size_t)b * NPIX + i0;
        const int r0 = wm * 64 + (lane >> 2), c0l = (lane & 3) * 2;
        __syncthreads();
        #pragma unroll
        for (int mt = 0; mt < 4; mt++) {
            const float inv0 = 1.f / lrow[r0 + mt * 16];
            const float inv1 = 1.f / lrow[r0 + mt * 16 + 8];
            #pragma unroll
            for (int nt = 0; nt < 8; nt++) {
                const int rr = r0 + mt * 16;
                const int ccl = nt * 8 + c0l;
                __half2 h0, h1;
                h0.x = __float2half_rn(acc[mt][nt][0] * inv0);
                h0.y = __float2half_rn(acc[mt][nt][1] * inv0);
                h1.x = __float2half_rn(acc[mt][nt][2] * inv1);
                h1.y = __float2half_rn(acc[mt][nt][3] * inv1);
                *(__half2*)(smem + wn * 32768 + SWZ(rr * 128 + ccl * 2))       = h0;
                *(__half2*)(smem + wn * 32768 + SWZ((rr + 8) * 128 + ccl * 2)) = h1;
            }
        }
    }
    __syncthreads();

    // ===== phase 2: out = Wp * O^T + b + x =====
    {
        const int wm = wid & 3, wn = wid >> 2;   // 4 x 2 warps
        float acc2[4][8][4] = {};

        cp_rows(sb + 131072, (const char*)g_wp16, CH * 2, 256);
        asm volatile("cp.async.commit_group;" ::: "memory");
        for (int ck = 0; ck < 4; ck++) {
            const uint32_t wst = sb + 131072 + (ck & 1) * 32768;
            if (ck + 1 < 4) {
                const uint32_t nwst = sb + 131072 + ((ck + 1) & 1) * 32768;
                cp_rows(nwst, (const char*)g_wp16 + (ck + 1) * 128, CH * 2, 256);
                asm volatile("cp.async.commit_group;" ::: "memory");
                asm volatile("cp.async.wait_group 1;" ::: "memory");
            } else {
                asm volatile("cp.async.wait_group 0;" ::: "memory");
            }
            __syncthreads();
            #pragma unroll
            for (int kk = 0; kk < 4; kk++) {
                const int kb = kk * 32;
                uint32_t a[4][4];
                #pragma unroll
                for (int mt = 0; mt < 4; mt++)
                    ldm4(a[mt], wst + SWZ((wm * 64 + mt * 16 + lr) * 128 + kb + lc));
                #pragma unroll
                for (int np = 0; np < 4; np++) {
                    uint32_t b4[4];
                    ldm4(b4, sb + ck * 32768 + SWZ((wn * 64 + np * 16 + lr) * 128 + kb + lc));
                    uint32_t b0[2] = {b4[0], b4[2]}, b1[2] = {b4[1], b4[3]};
                    #pragma unroll
                    for (int mt = 0; mt < 4; mt++) {
                        mma16816h(acc2[mt][np * 2],     a[mt], b0);
                        mma16816h(acc2[mt][np * 2 + 1], a[mt], b1);
                    }
                }
            }
            __syncthreads();
        }

        const int r0 = wm * 64 + (lane >> 2), c0 = wn * 64 + (lane & 3) * 2;
        #pragma unroll
        for (int mt = 0; mt < 4; mt++) {
            const int o  = r0 + mt * 16;
            const float b0 = proj_b[o], b1 = proj_b[o + 8];
            #pragma unroll
            for (int nt = 0; nt < 8; nt++) {
                const size_t idx0 = ((size_t)b * CH + o) * NPIX + i0 + c0 + nt * 8;
                const size_t idx1 = idx0 + (size_t)8 * NPIX;
                float2 x0 = *(const float2*)(x + idx0);
                float2 x1 = *(const float2*)(x + idx1);
                *(float2*)(out + idx0) = make_float2(acc2[mt][nt][0] + b0 + x0.x,
                                                     acc2[mt][nt][1] + b0 + x0.y);
                *(float2*)(out + idx1) = make_float2(acc2[mt][nt][2] + b1 + x1.x,
                                                     acc2[mt][nt][3] + b1 + x1.y);
            }
        }
    }
}

// ---------- launch ----------
extern "C" void kernel_launch(void* const* d_in, const int* in_sizes, int n_in,
                              void* d_out, int out_size) {
    const float* x      = (const float*)d_in[0];
    const float* gn_w   = (const float*)d_in[1];
    const float* gn_b   = (const float*)d_in[2];
    const float* qkv_w  = (const float*)d_in[3];
    const float* qkv_b  = (const float*)d_in[4];
    const float* proj_w = (const float*)d_in[5];
    const float* proj_b = (const float*)d_in[6];
    float* out = (float*)d_out;

    cudaFuncSetAttribute(qkv_hmma,       cudaFuncAttributeMaxDynamicSharedMemorySize, 98304);
    cudaFuncSetAttribute(s_gemm_kernel,  cudaFuncAttributeMaxDynamicSharedMemorySize, 196608);
    cudaFuncSetAttribute(pv_proj_kernel, cudaFuncAttributeMaxDynamicSharedMemorySize, 196608);

    w_convert<<<256, 256>>>(qkv_w, proj_w);
    gn_kernel<<<BATCH * 32, 512>>>(x, gn_w, gn_b);
    {
        dim3 g(NPIX / 32, CH / 32, BATCH);
        h_convert<<<g, 256>>>();
    }
    {
        dim3 g(NPIX / 128, 6, BATCH);
        qkv_hmma<<<g, 256, 98304>>>(qkv_b);
    }
    {
        dim3 g(NPIX / 128, NPIX / 256, BATCH);
        s_gemm_kernel<<<g, 256, 196608>>>();
    }
    pv_proj_kernel<<<(NPIX / 128) * BATCH, 256, 196608>>>(proj_b, x, out);
}

// round 17
// speedup vs baseline: 2.3395x; 1.0020x over previous
#include <cuda_runtime.h>
#include <cuda_fp16.h>
#include <math.h>
#include <stdint.h>

#define BATCH 4
#define CH    256
#define NPIX  4096
#define CPG   8
#define QSC   (0.0625f * 1.44269504f)

__device__ __half g_h16c[(size_t)BATCH * CH * NPIX];
__device__ __half g_h16 [(size_t)BATCH * NPIX * CH];
__device__ __half g_wq16[3 * CH * CH];
__device__ __half g_wp16[CH * CH];
__device__ __half g_q16[(size_t)BATCH * NPIX * CH];
__device__ __half g_k16[(size_t)BATCH * NPIX * CH];
__device__ __half g_v16h[(size_t)BATCH * CH * NPIX];
__device__ __half g_p [(size_t)BATCH * NPIX * NPIX];
__device__ float g_l [BATCH * NPIX];

#define SWZ(o) ((o) ^ (((o) >> 3) & 0x70))

__device__ __forceinline__ uint32_t smem_u32(const void* p) {
    uint32_t a;
    asm("{ .reg .u64 t; cvta.to.shared.u64 t, %1; cvt.u32.u64 %0, t; }" : "=r"(a) : "l"(p));
    return a;
}
__device__ __forceinline__ void cp16(uint32_t dst, const void* src) {
    asm volatile("cp.async.cg.shared.global [%0], [%1], 16;" :: "r"(dst), "l"(src) : "memory");
}
__device__ __forceinline__ void ldm4(uint32_t* r, uint32_t addr) {
    asm volatile("ldmatrix.sync.aligned.m8n8.x4.shared.b16 {%0,%1,%2,%3}, [%4];"
                 : "=r"(r[0]), "=r"(r[1]), "=r"(r[2]), "=r"(r[3]) : "r"(addr));
}
__device__ __forceinline__ void mma16816h(float* c, const uint32_t* a, const uint32_t* b) {
    asm volatile("mma.sync.aligned.m16n8k16.row.col.f32.f16.f16.f32 "
                 "{%0,%1,%2,%3}, {%4,%5,%6,%7}, {%8,%9}, {%0,%1,%2,%3};"
                 : "+f"(c[0]), "+f"(c[1]), "+f"(c[2]), "+f"(c[3])
                 : "r"(a[0]), "r"(a[1]), "r"(a[2]), "r"(a[3]), "r"(b[0]), "r"(b[1]));
}
__device__ __forceinline__ uint32_t ex2h2(uint32_t x) {
    uint32_t r;
    asm("ex2.approx.f16x2 %0, %1;" : "=r"(r) : "r"(x));
    return r;
}

__device__ __forceinline__ void cp_rows(uint32_t dst, const char* src, long pitchB, int rows) {
    for (int idx = threadIdx.x; idx < rows * 8; idx += blockDim.x) {
        const int r = idx >> 3, cg = idx & 7;
        cp16(dst + SWZ(r * 128 + cg * 16), src + (long)r * pitchB + cg * 16);
    }
}
__device__ __forceinline__ void cp_rows2(uint32_t dst, const char* src, long pitchB, int rows) {
    for (int idx = threadIdx.x; idx < rows * 16; idx += blockDim.x) {
        const int r = idx >> 4, cg = idx & 15;
        const uint32_t off = ((cg & 8) ? (uint32_t)rows * 128 : 0u) + SWZ(r * 128 + (cg & 7) * 16);
        cp16(dst + off, src + (long)r * pitchB + cg * 16);
    }
}

// ========== single-fp16 core, CTA 128x128, warp 32x64 (8 warps) ==========
__device__ __forceinline__ void mma_chunk1(uint32_t sA, uint32_t sB,
                                           float (&acc)[2][8][4], int wm, int wn, int lane) {
    const int lr = lane & 15, lc = (lane >> 4) * 16;
    #pragma unroll
    for (int kk = 0; kk < 4; kk++) {
        const int kb = kk * 32;
        uint32_t a[2][4];
        #pragma unroll
        for (int mt = 0; mt < 2; mt++)
            ldm4(a[mt], sA + SWZ((wm * 32 + mt * 16 + lr) * 128 + kb + lc));
        #pragma unroll
        for (int np = 0; np < 4; np++) {
            uint32_t b4[4];
            ldm4(b4, sB + SWZ((wn * 64 + np * 16 + lr) * 128 + kb + lc));
            uint32_t b0[2] = {b4[0], b4[2]}, b1[2] = {b4[1], b4[3]};
            #pragma unroll
            for (int mt = 0; mt < 2; mt++) {
                mma16816h(acc[mt][np * 2],     a[mt], b0);
                mma16816h(acc[mt][np * 2 + 1], a[mt], b1);
            }
        }
    }
}

// ---------- GroupNorm -> fp16 [c][n]; x cached fp16 in smem for 2nd pass ----------
__global__ void __launch_bounds__(512) gn_kernel(const float* __restrict__ x,
                                                 const float* __restrict__ w,
                                                 const float* __restrict__ bias) {
    extern __shared__ __half xs[];   // 8 * 4096 halves = 64 KB
    const int b = blockIdx.x >> 5, g = blockIdx.x & 31;
    const float* xp = x + (b * CH + g * CPG) * NPIX;
    __half*      hp = g_h16c + ((size_t)b * CH + g * CPG) * NPIX;
    const int NE = CPG * NPIX;
    float s = 0.f, ss = 0.f;
    const float4* x4 = (const float4*)xp;
    for (int i = threadIdx.x; i < NE / 4; i += 512) {
        float4 v = x4[i];
        s  += v.x + v.y + v.z + v.w;
        ss += v.x * v.x + v.y * v.y + v.z * v.z + v.w * v.w;
        __half2 c0, c1;
        c0.x = __float2half_rn(v.x); c0.y = __float2half_rn(v.y);
        c1.x = __float2half_rn(v.z); c1.y = __float2half_rn(v.w);
        *(__half2*)(xs + i * 4)     = c0;
        *(__half2*)(xs + i * 4 + 2) = c1;
    }
    __shared__ float rs[16], rss[16];
    #pragma unroll
    for (int o = 16; o; o >>= 1) {
        s  += __shfl_xor_sync(~0u, s,  o);
        ss += __shfl_xor_sync(~0u, ss, o);
    }
    const int lane = threadIdx.x & 31, wid = threadIdx.x >> 5;
    if (lane == 0) { rs[wid] = s; rss[wid] = ss; }
    __syncthreads();
    if (wid == 0) {
        s  = (lane < 16) ? rs[lane]  : 0.f;
        ss = (lane < 16) ? rss[lane] : 0.f;
        #pragma unroll
        for (int o = 16; o; o >>= 1) {
            s  += __shfl_xor_sync(~0u, s,  o);
            ss += __shfl_xor_sync(~0u, ss, o);
        }
        if (lane == 0) { rs[0] = s; rss[0] = ss; }
    }
    __syncthreads();
    const float mu   = rs[0] / (float)NE;
    const float rstd = rsqrtf(rss[0] / (float)NE - mu * mu + 1e-5f);
    for (int i = threadIdx.x; i < NE / 4; i += 512) {
        const int c = g * CPG + (i >> 10);
        const float wc = w[c] * rstd, bc = bias[c] - mu * wc;
        __half2 c0 = *(__half2*)(xs + i * 4);
        __half2 c1 = *(__half2*)(xs + i * 4 + 2);
        __half2 h0, h1;
        h0.x = __float2half_rn(__half2float(c0.x) * wc + bc);
        h0.y = __float2half_rn(__half2float(c0.y) * wc + bc);
        h1.x = __float2half_rn(__half2float(c1.x) * wc + bc);
        h1.y = __float2half_rn(__half2float(c1.y) * wc + bc);
        *(__half2*)(hp + i * 4)     = h0;
        *(__half2*)(hp + i * 4 + 2) = h1;
    }
}

// ---------- h: [c][n] fp16 -> [n][c] fp16 ----------
__global__ void __launch_bounds__(256) h_convert() {
    __shared__ float t[32][33];
    const int n0 = blockIdx.x * 32, c0 = blockIdx.y * 32, b = blockIdx.z;
    const __half* src = g_h16c + ((size_t)b * CH + c0) * NPIX + n0;
    const int tx = threadIdx.x & 31, ty = threadIdx.x >> 5;
    #pragma unroll
    for (int j = 0; j < 4; j++)
        t[ty + 8 * j][tx] = __half2float(src[(size_t)(ty + 8 * j) * NPIX + tx]);
    __syncthreads();
    const size_t dbase = ((size_t)b * NPIX + n0) * CH + c0;
    #pragma unroll
    for (int j = 0; j < 4; j++)
        g_h16[dbase + (size_t)(ty + 8 * j) * CH + tx] = __float2half_rn(t[tx][ty + 8 * j]);
}

// ---------- weight -> fp16 (also zeroes g_l) ----------
__global__ void __launch_bounds__(256) w_convert(const float* __restrict__ qkv_w,
                                                 const float* __restrict__ proj_w) {
    if (blockIdx.x < 64)
        g_l[blockIdx.x * 256 + threadIdx.x] = 0.f;
    const int f4 = blockIdx.x * 256 + threadIdx.x;
    const float* src;
    __half* d;
    size_t e;
    if (f4 < 49152) { src = qkv_w;  d = g_wq16; e = (size_t)f4 * 4; }
    else            { src = proj_w; d = g_wp16; e = (size_t)(f4 - 49152) * 4; }
    float4 v = *(const float4*)(src + e);
    __half2 h0, h1;
    h0.x = __float2half_rn(v.x); h0.y = __float2half_rn(v.y);
    h1.x = __float2half_rn(v.z); h1.y = __float2half_rn(v.w);
    *(__half2*)(d + e)     = h0;
    *(__half2*)(d + e + 2) = h1;
}

// ---------- QKV = W*H (3-stage pipeline, 2 CTAs/SM) ----------
__global__ void __launch_bounds__(256, 2) qkv_hmma(const float* __restrict__ qkv_b) {
    extern __shared__ char smem[];
    const uint32_t sb = smem_u32(smem);
    const int tid = threadIdx.x, lane = tid & 31, wid = tid >> 5;
    const int wm = wid & 3, wn = wid >> 2;
    const int b = blockIdx.z, n0 = blockIdx.x * 128, o0 = blockIdx.y * 128;

    const char* A = (const char*)(g_wq16 + (size_t)o0 * CH);
    const char* B = (const char*)(g_h16 + ((size_t)b * NPIX + n0) * CH);
    const long pB = CH * 2;

    float acc[2][8][4] = {};
    cp_rows(sb,         A, pB, 128);
    cp_rows(sb + 16384, B, pB, 128);
    asm volatile("cp.async.commit_group;" ::: "memory");
    cp_rows(sb + 32768,         A + 128, pB, 128);
    cp_rows(sb + 32768 + 16384, B + 128, pB, 128);
    asm volatile("cp.async.commit_group;" ::: "memory");
    for (int ch = 0; ch < 4; ch++) {
        const uint32_t stb = sb + (ch % 3) * 32768;
        if (ch + 2 < 4) {
            const uint32_t nstb = sb + ((ch + 2) % 3) * 32768;
            const long k0 = (long)(ch + 2) * 128;
            cp_rows(nstb,         A + k0, pB, 128);
            cp_rows(nstb + 16384, B + k0, pB, 128);
            asm volatile("cp.async.commit_group;" ::: "memory");
            asm volatile("cp.async.wait_group 2;" ::: "memory");
        } else if (ch + 1 < 4) {
            asm volatile("cp.async.wait_group 1;" ::: "memory");
        } else {
            asm volatile("cp.async.wait_group 0;" ::: "memory");
        }
        __syncthreads();
        mma_chunk1(stb, stb + 16384, acc, wm, wn, lane);
        __syncthreads();
    }

    const int r0 = wm * 32 + (lane >> 2), c0 = wn * 64 + (lane & 3) * 2;
    #pragma unroll
    for (int mt = 0; mt < 2; mt++) {
        const float b0 = qkv_b[o0 + r0 + mt * 16];
        const float b1 = qkv_b[o0 + r0 + mt * 16 + 8];
        #pragma unroll
        for (int nt = 0; nt < 8; nt++) {
            acc[mt][nt][0] += b0; acc[mt][nt][1] += b0;
            acc[mt][nt][2] += b1; acc[mt][nt][3] += b1;
        }
    }

    const int sel = blockIdx.y >> 1;   // 0=q, 1=k, 2=v
    if (sel == 2) {
        __half* vh = g_v16h + ((size_t)b * CH + (o0 - 512)) * NPIX + n0;
        #pragma unroll
        for (int mt = 0; mt < 2; mt++)
            #pragma unroll
            for (int nt = 0; nt < 8; nt++) {
                const int rr = r0 + mt * 16, cc = c0 + nt * 8;
                __half2 h0, h1;
                h0.x = __float2half_rn(acc[mt][nt][0]); h0.y = __float2half_rn(acc[mt][nt][1]);
                h1.x = __float2half_rn(acc[mt][nt][2]); h1.y = __float2half_rn(acc[mt][nt][3]);
                *(__half2*)(vh + (size_t)rr * NPIX + cc)       = h0;
                *(__half2*)(vh + (size_t)(rr + 8) * NPIX + cc) = h1;
            }
    } else {
        const float sc = sel ? 1.f : QSC;
        float* st = (float*)smem;   // [c 128][n 132]
        __syncthreads();
        #pragma unroll
        for (int mt = 0; mt < 2; mt++)
            #pragma unroll
            for (int nt = 0; nt < 8; nt++) {
                const int rr = r0 + mt * 16, cc = c0 + nt * 8;
                st[(cc)     * 132 + rr]     = acc[mt][nt][0];
                st[(cc + 1) * 132 + rr]     = acc[mt][nt][1];
                st[(cc)     * 132 + rr + 8] = acc[mt][nt][2];
                st[(cc + 1) * 132 + rr + 8] = acc[mt][nt][3];
            }
        __syncthreads();
        __half* dq = (sel ? g_k16 : g_q16) + ((size_t)b * NPIX + n0) * CH + (o0 - sel * 256);
        const int o4 = lane * 4, nb = tid >> 5;
        #pragma unroll
        for (int j = 0; j < 16; j++) {
            const int n = nb + 8 * j;
            float4 v = *(float4*)(st + n * 132 + o4);
            __half2 h0, h1;
            h0.x = __float2half_rn(v.x * sc); h0.y = __float2half_rn(v.y * sc);
            h1.x = __float2half_rn(v.z * sc); h1.y = __float2half_rn(v.w * sc);
            *(__half2*)(dq + (size_t)n * CH + o4)     = h0;
            *(__half2*)(dq + (size_t)n * CH + o4 + 2) = h1;
        }
    }
}

// ---------- P = 2^(Q K^T): single-phase (all K resident) + smem-staged P store ----------
// layout: A0 64K @0 | B0 32K @65536 | A1 64K @98304 | B1 32K @163840 = 192K
__global__ void __launch_bounds__(256, 1) s_gemm_kernel() {
    extern __shared__ char smem[];
    const uint32_t sb = smem_u32(smem);
    const int tid = threadIdx.x, lane = tid & 31, wid = tid >> 5;
    const int wm = wid & 3, wn = wid >> 2;   // 4 x 2 warps
    const int b = blockIdx.z, i0 = blockIdx.y * 256, j0 = blockIdx.x * 128;

    const char* Aq = (const char*)(g_q16 + ((size_t)b * NPIX + i0) * CH);
    const char* Bk = (const char*)(g_k16 + ((size_t)b * NPIX + j0) * CH);
    const long pB = CH * 2;

    float acc[4][8][4] = {};
    const int lr = lane & 15, lc = (lane >> 4) * 16;

    // load the entire K=256 (two 256B chunks) at once
    cp_rows2(sb,          Aq,       pB, 256);
    cp_rows2(sb + 65536,  Bk,       pB, 128);
    cp_rows2(sb + 98304,  Aq + 256, pB, 256);
    cp_rows2(sb + 163840, Bk + 256, pB, 128);
    asm volatile("cp.async.commit_group;" ::: "memory");
    asm volatile("cp.async.wait_group 0;" ::: "memory");
    __syncthreads();

    #pragma unroll
    for (int ch = 0; ch < 2; ch++) {
        const uint32_t stb = sb + ch * 98304;
        #pragma unroll
        for (int kk = 0; kk < 8; kk++) {
            const int kb = (kk & 3) * 32;
            const uint32_t ah = (kk >> 2) * 32768;
            const uint32_t bh = (kk >> 2) * 16384;
            uint32_t a[4][4];
            #pragma unroll
            for (int mt = 0; mt < 4; mt++)
                ldm4(a[mt], stb + ah + SWZ((wm * 64 + mt * 16 + lr) * 128 + kb + lc));
            #pragma unroll
            for (int np = 0; np < 4; np++) {
                uint32_t b4[4];
                ldm4(b4, stb + 65536 + bh + SWZ((wn * 64 + np * 16 + lr) * 128 + kb + lc));
                uint32_t b0[2] = {b4[0], b4[2]}, b1[2] = {b4[1], b4[3]};
                #pragma unroll
                for (int mt = 0; mt < 4; mt++) {
                    mma16816h(acc[mt][np * 2],     a[mt], b0);
                    mma16816h(acc[mt][np * 2 + 1], a[mt], b1);
                }
            }
        }
    }
    __syncthreads();

    // epilogue: exp into smem tile (pitch 272B), row sums, coalesced copy-out
    float* lrow = g_l + (size_t)b * NPIX + i0;
    const int r0 = wm * 64 + (lane >> 2), c0 = wn * 64 + (lane & 3) * 2;
    #pragma unroll
    for (int mt = 0; mt < 4; mt++) {
        __half2 hs0 = __floats2half2_rn(0.f, 0.f);
        __half2 hs1 = __floats2half2_rn(0.f, 0.f);
        #pragma unroll
        for (int nt = 0; nt < 8; nt++) {
            __half2 x01 = __floats2half2_rn(acc[mt][nt][0], acc[mt][nt][1]);
            __half2 x23 = __floats2half2_rn(acc[mt][nt][2], acc[mt][nt][3]);
            const uint32_t e01 = ex2h2(*(uint32_t*)&x01);
            const uint32_t e23 = ex2h2(*(uint32_t*)&x23);
            hs0 = __hadd2(hs0, *(const __half2*)&e01);
            hs1 = __hadd2(hs1, *(const __half2*)&e23);
            const int row = r0 + mt * 16;
            const int cb  = (c0 + nt * 8) * 2;
            *(uint32_t*)(smem + row * 272 + cb)       = e01;
            *(uint32_t*)(smem + (row + 8) * 272 + cb) = e23;
        }
        float rs0 = __half2float(hs0.x) + __half2float(hs0.y);
        float rs1 = __half2float(hs1.x) + __half2float(hs1.y);
        rs0 += __shfl_xor_sync(~0u, rs0, 1);
        rs0 += __shfl_xor_sync(~0u, rs0, 2);
        rs1 += __shfl_xor_sync(~0u, rs1, 1);
        rs1 += __shfl_xor_sync(~0u, rs1, 2);
        if ((lane & 3) == 0) {
            atomicAdd(lrow + r0 + mt * 16,     rs0);
            atomicAdd(lrow + r0 + mt * 16 + 8, rs1);
        }
    }
    __syncthreads();
    __half* Pb = g_p + ((size_t)b * NPIX + i0) * NPIX + j0;
    for (int idx = tid; idx < 4096; idx += 256) {
        const int r = idx >> 4, sg = idx & 15;
        uint4 v = *(uint4*)(smem + r * 272 + sg * 16);
        *(uint4*)(Pb + (size_t)r * NPIX + sg * 8) = v;
    }
}

// ---------- O = P V, normalize, then out = Wp*O^T + b + x (fused) ----------
__global__ void __launch_bounds__(256, 1) pv_proj_kernel(const float* __restrict__ proj_b,
                                                         const float* __restrict__ x,
                                                         float* __restrict__ out) {
    extern __shared__ char smem[];
    const uint32_t sb = smem_u32(smem);
    const int tid = threadIdx.x, lane = tid & 31, wid = tid >> 5;
    const int b = blockIdx.x & 3, i0 = (blockIdx.x >> 2) * 128;
    const int lr = lane & 15, lc = (lane >> 4) * 16;

    // ===== phase 1: O = P V =====
    {
        const int wm = wid & 1, wn = wid >> 1;   // 2 x 4 warps
        const char* Ap = (const char*)(g_p + ((size_t)b * NPIX + i0) * NPIX);
        const char* Bh = (const char*)(g_v16h + (size_t)b * CH * NPIX);
        const long pB = NPIX * 2;

        float acc[4][8][4] = {};

        cp_rows2(sb,         Ap, pB, 128);
        cp_rows2(sb + 32768, Bh, pB, 256);
        asm volatile("cp.async.commit_group;" ::: "memory");

        for (int ch = 0; ch < 32; ch++) {
            const uint32_t stb = sb + (ch & 1) * 98304;
            if (ch + 1 < 32) {
                const uint32_t nstb = sb + ((ch + 1) & 1) * 98304;
                const long k0 = (long)(ch + 1) * 256;
                cp_rows2(nstb,         Ap + k0, pB, 128);
                cp_rows2(nstb + 32768, Bh + k0, pB, 256);
                asm volatile("cp.async.commit_group;" ::: "memory");
                asm volatile("cp.async.wait_group 1;" ::: "memory");
            } else {
                asm volatile("cp.async.wait_group 0;" ::: "memory");
            }
            __syncthreads();
            #pragma unroll
            for (int kk = 0; kk < 8; kk++) {
                const int kb = (kk & 3) * 32;
                const uint32_t ah = (kk >> 2) * 16384;
                const uint32_t bh = (kk >> 2) * 32768;
                uint32_t a[4][4];
                #pragma unroll
                for (int mt = 0; mt < 4; mt++)
                    ldm4(a[mt], stb + ah + SWZ((wm * 64 + mt * 16 + lr) * 128 + kb + lc));
                #pragma unroll
                for (int np = 0; np < 4; np++) {
                    uint32_t b4[4];
                    ldm4(b4, stb + 32768 + bh + SWZ((wn * 64 + np * 16 + lr) * 128 + kb + lc));
                    uint32_t b0[2] = {b4[0], b4[2]}, b1[2] = {b4[1], b4[3]};
                    #pragma unroll
                    for (int mt = 0; mt < 4; mt++) {
                        mma16816h(acc[mt][np * 2],     a[mt], b0);
                        mma16816h(acc[mt][np * 2 + 1], a[mt], b1);
                    }
                }
            }
            __syncthreads();
        }

        const float* lrow = g_l + (size_t)b * NPIX + i0;
        const int r0 = wm * 64 + (lane >> 2), c0l = (lane & 3) * 2;
        __syncthreads();
        #pragma unroll
        for (int mt = 0; mt < 4; mt++) {
            const float inv0 = 1.f / lrow[r0 + mt * 16];
            const float inv1 = 1.f / lrow[r0 + mt * 16 + 8];
            #pragma unroll
            for (int nt = 0; nt < 8; nt++) {
                const int rr = r0 + mt * 16;
                const int ccl = nt * 8 + c0l;
                __half2 h0, h1;
                h0.x = __float2half_rn(acc[mt][nt][0] * inv0);
                h0.y = __float2half_rn(acc[mt][nt][1] * inv0);
                h1.x = __float2half_rn(acc[mt][nt][2] * inv1);
                h1.y = __float2half_rn(acc[mt][nt][3] * inv1);
                *(__half2*)(smem + wn * 32768 + SWZ(rr * 128 + ccl * 2))       = h0;
                *(__half2*)(smem + wn * 32768 + SWZ((rr + 8) * 128 + ccl * 2)) = h1;
            }
        }
    }
    __syncthreads();

    // ===== phase 2: out = Wp * O^T + b + x =====
    {
        const int wm = wid & 3, wn = wid >> 2;   // 4 x 2 warps
        float acc2[4][8][4] = {};

        cp_rows(sb + 131072, (const char*)g_wp16, CH * 2, 256);
        asm volatile("cp.async.commit_group;" ::: "memory");
        for (int ck = 0; ck < 4; ck++) {
            const uint32_t wst = sb + 131072 + (ck & 1) * 32768;
            if (ck + 1 < 4) {
                const uint32_t nwst = sb + 131072 + ((ck + 1) & 1) * 32768;
                cp_rows(nwst, (const char*)g_wp16 + (ck + 1) * 128, CH * 2, 256);
                asm volatile("cp.async.commit_group;" ::: "memory");
                asm volatile("cp.async.wait_group 1;" ::: "memory");
            } else {
                asm volatile("cp.async.wait_group 0;" ::: "memory");
            }
            __syncthreads();
            #pragma unroll
            for (int kk = 0; kk < 4; kk++) {
                const int kb = kk * 32;
                uint32_t a[4][4];
                #pragma unroll
                for (int mt = 0; mt < 4; mt++)
                    ldm4(a[mt], wst + SWZ((wm * 64 + mt * 16 + lr) * 128 + kb + lc));
                #pragma unroll
                for (int np = 0; np < 4; np++) {
                    uint32_t b4[4];
                    ldm4(b4, sb + ck * 32768 + SWZ((wn * 64 + np * 16 + lr) * 128 + kb + lc));
                    uint32_t b0[2] = {b4[0], b4[2]}, b1[2] = {b4[1], b4[3]};
                    #pragma unroll
                    for (int mt = 0; mt < 4; mt++) {
                        mma16816h(acc2[mt][np * 2],     a[mt], b0);
                        mma16816h(acc2[mt][np * 2 + 1], a[mt], b1);
                    }
                }
            }
            __syncthreads();
        }

        const int r0 = wm * 64 + (lane >> 2), c0 = wn * 64 + (lane & 3) * 2;
        #pragma unroll
        for (int mt = 0; mt < 4; mt++) {
            const int o  = r0 + mt * 16;
            const float b0 = proj_b[o], b1 = proj_b[o + 8];
            #pragma unroll
            for (int nt = 0; nt < 8; nt++) {
                const size_t idx0 = ((size_t)b * CH + o) * NPIX + i0 + c0 + nt * 8;
                const size_t idx1 = idx0 + (size_t)8 * NPIX;
                float2 x0 = *(const float2*)(x + idx0);
                float2 x1 = *(const float2*)(x + idx1);
                *(float2*)(out + idx0) = make_float2(acc2[mt][nt][0] + b0 + x0.x,
                                                     acc2[mt][nt][1] + b0 + x0.y);
                *(float2*)(out + idx1) = make_float2(acc2[mt][nt][2] + b1 + x1.x,
                                                     acc2[mt][nt][3] + b1 + x1.y);
            }
        }
    }
}

// ---------- launch ----------
extern "C" void kernel_launch(void* const* d_in, const int* in_sizes, int n_in,
                              void* d_out, int out_size) {
    const float* x      = (const float*)d_in[0];
    const float* gn_w   = (const float*)d_in[1];
    const float* gn_b   = (const float*)d_in[2];
    const float* qkv_w  = (const float*)d_in[3];
    const float* qkv_b  = (const float*)d_in[4];
    const float* proj_w = (const float*)d_in[5];
    const float* proj_b = (const float*)d_in[6];
    float* out = (float*)d_out;

    cudaFuncSetAttribute(gn_kernel,      cudaFuncAttributeMaxDynamicSharedMemorySize, 65536);
    cudaFuncSetAttribute(qkv_hmma,       cudaFuncAttributeMaxDynamicSharedMemorySize, 98304);
    cudaFuncSetAttribute(s_gemm_kernel,  cudaFuncAttributeMaxDynamicSharedMemorySize, 196608);
    cudaFuncSetAttribute(pv_proj_kernel, cudaFuncAttributeMaxDynamicSharedMemorySize, 196608);

    w_convert<<<256, 256>>>(qkv_w, proj_w);
    gn_kernel<<<BATCH * 32, 512, 65536>>>(x, gn_w, gn_b);
    {
        dim3 g(NPIX / 32, CH / 32, BATCH);
        h_convert<<<g, 256>>>();
    }
    {
        dim3 g(NPIX / 128, 6, BATCH);
        qkv_hmma<<<g, 256, 98304>>>(qkv_b);
    }
    {
        dim3 g(NPIX / 128, NPIX / 256, BATCH);
        s_gemm_kernel<<<g, 256, 196608>>>();
    }
    pv_proj_kernel<<<(NPIX / 128) * BATCH, 256, 196608>>>(proj_b, x, out);
}